// round 1
// baseline (speedup 1.0000x reference)
#include <cuda_runtime.h>
#include <math.h>

#define BB 4
#define LL 1024
#define DIMM 1024
#define NHEADS 16
#define HD 64
#define NTOK (BB*LL)
#define HID 512
#define NE 16
#define NSHARED 2048
#define NSLOTS (NTOK*2)

// ---------------- scratch (static device globals: allowed) ----------------
__device__ float g_hn[NTOK*DIMM];
__device__ float g_q[NTOK*DIMM];
__device__ float g_k[NTOK*DIMM];
__device__ float g_v[NTOK*DIMM];
__device__ float g_scores[(long long)BB*NHEADS*LL*LL];   // 256 MB
__device__ float g_attn[NTOK*DIMM];
__device__ float g_h[NTOK*DIMM];
__device__ float g_xf[NTOK*DIMM];
__device__ float g_ta[NTOK*NSHARED];
__device__ float g_tb[NTOK*NSHARED];
__device__ float g_moe[NTOK*DIMM];
__device__ float g_hexp[NSLOTS*HID];
__device__ float g_yexp[NSLOTS*DIMM];
__device__ int   g_topi[NSLOTS];
__device__ float g_topw[NSLOTS];
__device__ int   g_counts[NE];
__device__ int   g_cursor[NE];
__device__ int   g_offs[NE];
__device__ int   g_order[NSLOTS];
__device__ int   g_tokslot[NSLOTS];

// ---------------- reductions ----------------
__device__ __forceinline__ float warpReduceSum(float v){
    #pragma unroll
    for (int o=16;o;o>>=1) v += __shfl_xor_sync(0xffffffffu, v, o);
    return v;
}
__device__ __forceinline__ float warpReduceMax(float v){
    #pragma unroll
    for (int o=16;o;o>>=1) v = fmaxf(v, __shfl_xor_sync(0xffffffffu, v, o));
    return v;
}
__device__ float blockReduceSum(float v){
    __shared__ float sh[33];
    int lane = threadIdx.x & 31, wid = threadIdx.x >> 5;
    __syncthreads();
    v = warpReduceSum(v);
    if (lane==0) sh[wid] = v;
    __syncthreads();
    int nw = blockDim.x >> 5;
    float r = (threadIdx.x < nw) ? sh[threadIdx.x] : 0.f;
    if (wid==0){ r = warpReduceSum(r); if (lane==0) sh[32] = r; }
    __syncthreads();
    return sh[32];
}
__device__ float blockReduceMax(float v){
    __shared__ float sh[33];
    int lane = threadIdx.x & 31, wid = threadIdx.x >> 5;
    __syncthreads();
    v = warpReduceMax(v);
    if (lane==0) sh[wid] = v;
    __syncthreads();
    int nw = blockDim.x >> 5;
    float r = (threadIdx.x < nw) ? sh[threadIdx.x] : -3.0e38f;
    if (wid==0){ r = warpReduceMax(r); if (lane==0) sh[32] = r; }
    __syncthreads();
    return sh[32];
}

// ---------------- rmsnorm ----------------
__global__ void __launch_bounds__(256) rmsnorm_kernel(const float* __restrict__ x,
                                                      const float* __restrict__ w,
                                                      float* __restrict__ out){
    long long row = blockIdx.x;
    const float4* xr = (const float4*)(x + row*DIMM);
    float4 xv = xr[threadIdx.x];
    float ss = xv.x*xv.x + xv.y*xv.y + xv.z*xv.z + xv.w*xv.w;
    float tot = blockReduceSum(ss);
    float scale = rsqrtf(tot * (1.0f/DIMM) + 1e-5f);
    float4 wv = ((const float4*)w)[threadIdx.x];
    float4 o;
    o.x = xv.x*scale*wv.x; o.y = xv.y*scale*wv.y;
    o.z = xv.z*scale*wv.z; o.w = xv.w*scale*wv.w;
    ((float4*)(out + row*DIMM))[threadIdx.x] = o;
}

// ---------------- generic batched NT GEMM: C = alpha*A*B^T (+res) ----------------
// A[M,K] row-major lda, B[N,K] row-major ldb. Batch offset = (z/bdiv)*Outer + (z%bdiv)*Inner.
__global__ void __launch_bounds__(256) gemm_nt(
    const float* __restrict__ A, const float* __restrict__ B, float* __restrict__ C,
    const float* __restrict__ res,
    int M, int N, int K, int lda, int ldb, int ldc, float alpha,
    int bdiv, long long aO, long long aI, long long bO, long long bI,
    long long cO, long long cI)
{
    int z = blockIdx.z;
    long long aOff = (long long)(z/bdiv)*aO + (long long)(z%bdiv)*aI;
    long long bOff = (long long)(z/bdiv)*bO + (long long)(z%bdiv)*bI;
    long long cOff = (long long)(z/bdiv)*cO + (long long)(z%bdiv)*cI;
    const float* Ab = A + aOff;
    const float* Bb = B + bOff;
    __shared__ float As[8][132];
    __shared__ float Bs[8][132];
    int row0 = blockIdx.y * 128, col0 = blockIdx.x * 128;
    int tid = threadIdx.x, tx = tid & 15, ty = tid >> 4;
    float acc[8][8] = {};
    for (int k0 = 0; k0 < K; k0 += 8){
        #pragma unroll
        for (int i = tid; i < 1024; i += 256){
            int r = i >> 3, c = i & 7; int gr = row0 + r;
            As[c][r] = (gr < M) ? Ab[(long long)gr*lda + k0 + c] : 0.f;
        }
        #pragma unroll
        for (int i = tid; i < 1024; i += 256){
            int r = i >> 3, c = i & 7; int gc = col0 + r;
            Bs[c][r] = (gc < N) ? Bb[(long long)gc*ldb + k0 + c] : 0.f;
        }
        __syncthreads();
        #pragma unroll
        for (int kk = 0; kk < 8; kk++){
            float a[8], b[8];
            #pragma unroll
            for (int i = 0; i < 8; i++) a[i] = As[kk][ty*8+i];
            #pragma unroll
            for (int j = 0; j < 8; j++) b[j] = Bs[kk][tx*8+j];
            #pragma unroll
            for (int i = 0; i < 8; i++)
                #pragma unroll
                for (int j = 0; j < 8; j++) acc[i][j] = fmaf(a[i], b[j], acc[i][j]);
        }
        __syncthreads();
    }
    #pragma unroll
    for (int i = 0; i < 8; i++){
        int gm = row0 + ty*8 + i; if (gm >= M) continue;
        #pragma unroll
        for (int j = 0; j < 8; j++){
            int gn = col0 + tx*8 + j; if (gn >= N) continue;
            long long ci = cOff + (long long)gm*ldc + gn;
            float v = acc[i][j] * alpha;
            if (res) v += res[ci];
            C[ci] = v;
        }
    }
}

// ---------------- grouped (per-expert) NT GEMM with row gather ----------------
__global__ void __launch_bounds__(256) gemm_nt_grouped(
    const float* __restrict__ A, const float* __restrict__ Bw, float* __restrict__ C,
    const int* __restrict__ counts, const int* __restrict__ offs, const int* __restrict__ rows,
    int N, int K, int lda, int ldc, long long bStrideE, int doSilu)
{
    int e = blockIdx.z;
    int M = counts[e]; int off = offs[e];
    int row0 = blockIdx.y * 128; if (row0 >= M) return;
    int col0 = blockIdx.x * 128;
    const float* Bb = Bw + (long long)e * bStrideE;
    __shared__ float As[8][132];
    __shared__ float Bs[8][132];
    __shared__ int rsrc[128];
    int tid = threadIdx.x, tx = tid & 15, ty = tid >> 4;
    for (int i = tid; i < 128; i += 256){
        int lr = row0 + i;
        rsrc[i] = (lr < M) ? (rows ? rows[off + lr] : (off + lr)) : -1;
    }
    __syncthreads();
    float acc[8][8] = {};
    for (int k0 = 0; k0 < K; k0 += 8){
        #pragma unroll
        for (int i = tid; i < 1024; i += 256){
            int r = i >> 3, c = i & 7; int s = rsrc[r];
            As[c][r] = (s >= 0) ? A[(long long)s*lda + k0 + c] : 0.f;
        }
        #pragma unroll
        for (int i = tid; i < 1024; i += 256){
            int r = i >> 3, c = i & 7; int gc = col0 + r;
            Bs[c][r] = (gc < N) ? Bb[(long long)gc*K + k0 + c] : 0.f;
        }
        __syncthreads();
        #pragma unroll
        for (int kk = 0; kk < 8; kk++){
            float a[8], b[8];
            #pragma unroll
            for (int i = 0; i < 8; i++) a[i] = As[kk][ty*8+i];
            #pragma unroll
            for (int j = 0; j < 8; j++) b[j] = Bs[kk][tx*8+j];
            #pragma unroll
            for (int i = 0; i < 8; i++)
                #pragma unroll
                for (int j = 0; j < 8; j++) acc[i][j] = fmaf(a[i], b[j], acc[i][j]);
        }
        __syncthreads();
    }
    #pragma unroll
    for (int i = 0; i < 8; i++){
        int gm = row0 + ty*8 + i; if (gm >= M) continue;
        #pragma unroll
        for (int j = 0; j < 8; j++){
            int gn = col0 + tx*8 + j; if (gn >= N) continue;
            float v = acc[i][j];
            if (doSilu) v = v / (1.f + expf(-v));
            C[(long long)(off+gm)*ldc + gn] = v;
        }
    }
}

// ---------------- RoPE (in-place on q,k in [tok, h*64+d] layout) ----------------
__global__ void rope_kernel(float* __restrict__ q, float* __restrict__ k){
    int idx = blockIdx.x*blockDim.x + threadIdx.x;
    if (idx >= NTOK*NHEADS*(HD/2)) return;
    int j = idx & 31;
    int h = (idx >> 5) & 15;
    int t = idx >> 9;
    int l = t & (LL-1);
    long long base = (long long)t*DIMM + h*HD;
    float inv = powf(10000.f, -(float)j * (1.f/32.f));
    float ang = (float)l * inv;
    float sn, cs; sincosf(ang, &sn, &cs);
    float a = q[base+j], b = q[base+32+j];
    q[base+j]    = a*cs - b*sn;
    q[base+32+j] = a*sn + b*cs;
    a = k[base+j]; b = k[base+32+j];
    k[base+j]    = a*cs - b*sn;
    k[base+32+j] = a*sn + b*cs;
}

// ---------------- softmax over key dim, +mask ----------------
__global__ void __launch_bounds__(256) softmax_kernel(float* __restrict__ s,
                                                      const float* __restrict__ mask){
    long long row = blockIdx.x;
    int q = (int)(row & (LL-1));
    float* p = s + row*LL;
    const float* mr = mask + (long long)q*LL;
    float4 v = ((float4*)p)[threadIdx.x];
    float4 m = ((const float4*)mr)[threadIdx.x];
    v.x += m.x; v.y += m.y; v.z += m.z; v.w += m.w;
    float mx = fmaxf(fmaxf(v.x,v.y), fmaxf(v.z,v.w));
    mx = blockReduceMax(mx);
    float4 e;
    e.x = expf(v.x-mx); e.y = expf(v.y-mx); e.z = expf(v.z-mx); e.w = expf(v.w-mx);
    float sum = blockReduceSum(e.x+e.y+e.z+e.w);
    float invs = 1.f / sum;
    e.x *= invs; e.y *= invs; e.z *= invs; e.w *= invs;
    ((float4*)p)[threadIdx.x] = e;
}

// ---------------- P(probs) @ V, writes attn in [tok, h*64+d] layout ----------------
__global__ void __launch_bounds__(256) attn_pv(const float* __restrict__ P,
                                               const float* __restrict__ V,
                                               float* __restrict__ O){
    int zb = blockIdx.z;
    int b = zb >> 4, h = zb & 15;
    int m0 = blockIdx.y * 64;
    const float* Pb = P + (long long)zb*LL*LL;
    __shared__ float Ps[64][33];
    __shared__ float Vs[32][65];
    int tid = threadIdx.x, tx = tid & 15, ty = tid >> 4;
    float acc[4][4] = {};
    for (int k0 = 0; k0 < LL; k0 += 32){
        #pragma unroll
        for (int i = tid; i < 2048; i += 256){
            int r = i >> 5, c = i & 31;
            Ps[r][c] = Pb[(long long)(m0+r)*LL + k0 + c];
        }
        #pragma unroll
        for (int i = tid; i < 2048; i += 256){
            int r = i >> 6, c = i & 63;
            Vs[r][c] = V[(long long)(b*LL + k0 + r)*DIMM + h*HD + c];
        }
        __syncthreads();
        #pragma unroll
        for (int kk = 0; kk < 32; kk++){
            float a[4], bv[4];
            #pragma unroll
            for (int i = 0; i < 4; i++) a[i] = Ps[ty*4+i][kk];
            #pragma unroll
            for (int j = 0; j < 4; j++) bv[j] = Vs[kk][tx*4+j];
            #pragma unroll
            for (int i = 0; i < 4; i++)
                #pragma unroll
                for (int j = 0; j < 4; j++) acc[i][j] = fmaf(a[i], bv[j], acc[i][j]);
        }
        __syncthreads();
    }
    #pragma unroll
    for (int i = 0; i < 4; i++)
        #pragma unroll
        for (int j = 0; j < 4; j++)
            O[(long long)(b*LL + m0 + ty*4 + i)*DIMM + h*HD + tx*4 + j] = acc[i][j];
}

// ---------------- silu(a)*b ----------------
__global__ void silumul_kernel(float* __restrict__ ta, const float* __restrict__ tb, long long n){
    long long i = (long long)blockIdx.x*blockDim.x + threadIdx.x;
    if (i >= n) return;
    float a = ta[i], b = tb[i];
    ta[i] = a / (1.f + expf(-a)) * b;
}

// ---------------- gate logits + top2 + softmax + count ----------------
__global__ void __launch_bounds__(256) gate_topk(const float* __restrict__ xf,
                                                 const float* __restrict__ gw,
                                                 int* __restrict__ topi, float* __restrict__ topw,
                                                 int* __restrict__ counts){
    int t = blockIdx.x;
    int tid = threadIdx.x;
    float4 xv = ((const float4*)(xf + (long long)t*DIMM))[tid];
    float acc[16];
    #pragma unroll
    for (int e = 0; e < 16; e++){
        float4 g = ((const float4*)(gw + (long long)e*DIMM))[tid];
        acc[e] = xv.x*g.x + xv.y*g.y + xv.z*g.z + xv.w*g.w;
    }
    #pragma unroll
    for (int e = 0; e < 16; e++) acc[e] = warpReduceSum(acc[e]);
    __shared__ float wr[8][16];
    __shared__ float lg[16];
    int lane = tid & 31, wid = tid >> 5;
    if (lane == 0){
        #pragma unroll
        for (int e = 0; e < 16; e++) wr[wid][e] = acc[e];
    }
    __syncthreads();
    if (tid < 16){
        float s = 0.f;
        #pragma unroll
        for (int w = 0; w < 8; w++) s += wr[w][tid];
        lg[tid] = s;
    }
    __syncthreads();
    if (tid == 0){
        float l0 = -3.0e38f; int i0 = 0;
        for (int e = 0; e < 16; e++) if (lg[e] > l0){ l0 = lg[e]; i0 = e; }
        float l1 = -3.0e38f; int i1 = 0;
        for (int e = 0; e < 16; e++) if (e != i0 && lg[e] > l1){ l1 = lg[e]; i1 = e; }
        float w1 = expf(l1 - l0);
        float s = 1.f + w1;
        topi[2*t] = i0; topi[2*t+1] = i1;
        topw[2*t] = 1.f / s; topw[2*t+1] = w1 / s;
        atomicAdd(&counts[i0], 1);
        atomicAdd(&counts[i1], 1);
    }
}

__global__ void zero_counts(int* counts){
    if (threadIdx.x < NE) counts[threadIdx.x] = 0;
}

__global__ void scan_kernel(const int* __restrict__ counts, int* __restrict__ offs,
                            int* __restrict__ cursor){
    if (threadIdx.x == 0){
        int s = 0;
        for (int e = 0; e < NE; e++){ offs[e] = s; s += counts[e]; cursor[e] = 0; }
    }
}

__global__ void scatter_kernel(const int* __restrict__ topi, int* __restrict__ cursor,
                               const int* __restrict__ offs, int* __restrict__ order,
                               int* __restrict__ tokslot){
    int t = blockIdx.x*blockDim.x + threadIdx.x;
    if (t >= NTOK) return;
    #pragma unroll
    for (int k = 0; k < 2; k++){
        int e = topi[2*t+k];
        int pos = atomicAdd(&cursor[e], 1);
        int slot = offs[e] + pos;
        order[slot] = t;
        tokslot[2*t+k] = slot;
    }
}

// ---------------- final: out = h + shared_moe + sum_k w_k * y[slot_k] ----------------
__global__ void final_kernel(const float* __restrict__ h, const float* __restrict__ moe,
                             const float* __restrict__ y, const int* __restrict__ tokslot,
                             const float* __restrict__ topw, float* __restrict__ out){
    long long idx = (long long)blockIdx.x*blockDim.x + threadIdx.x;
    if (idx >= (long long)NTOK*DIMM) return;
    int t = (int)(idx >> 10);
    int i = (int)(idx & 1023);
    int s0 = tokslot[2*t], s1 = tokslot[2*t+1];
    float w0 = topw[2*t], w1 = topw[2*t+1];
    out[idx] = h[idx] + moe[idx] + w0*y[(long long)s0*DIMM + i] + w1*y[(long long)s1*DIMM + i];
}

// ---------------- host launcher ----------------
extern "C" void kernel_launch(void* const* d_in, const int* in_sizes, int n_in,
                              void* d_out, int out_size){
    const float* x    = (const float*)d_in[0];
    const float* mask = (const float*)d_in[1];
    const float* wq   = (const float*)d_in[2];
    const float* wk   = (const float*)d_in[3];
    const float* wv   = (const float*)d_in[4];
    const float* wo   = (const float*)d_in[5];
    const float* n1   = (const float*)d_in[6];
    const float* n2   = (const float*)d_in[7];
    const float* gw   = (const float*)d_in[8];
    const float* fc1  = (const float*)d_in[9];
    const float* fc2  = (const float*)d_in[10];
    const float* s1   = (const float*)d_in[11];
    const float* s2   = (const float*)d_in[12];
    const float* s3   = (const float*)d_in[13];
    float* out = (float*)d_out;

    void *p;
    cudaGetSymbolAddress(&p, g_hn);     float* hn     = (float*)p;
    cudaGetSymbolAddress(&p, g_q);      float* q      = (float*)p;
    cudaGetSymbolAddress(&p, g_k);      float* k      = (float*)p;
    cudaGetSymbolAddress(&p, g_v);      float* v      = (float*)p;
    cudaGetSymbolAddress(&p, g_scores); float* scores = (float*)p;
    cudaGetSymbolAddress(&p, g_attn);   float* attn   = (float*)p;
    cudaGetSymbolAddress(&p, g_h);      float* hbuf   = (float*)p;
    cudaGetSymbolAddress(&p, g_xf);     float* xf     = (float*)p;
    cudaGetSymbolAddress(&p, g_ta);     float* ta     = (float*)p;
    cudaGetSymbolAddress(&p, g_tb);     float* tb     = (float*)p;
    cudaGetSymbolAddress(&p, g_moe);    float* moe    = (float*)p;
    cudaGetSymbolAddress(&p, g_hexp);   float* hexp   = (float*)p;
    cudaGetSymbolAddress(&p, g_yexp);   float* yexp   = (float*)p;
    cudaGetSymbolAddress(&p, g_topi);   int*   topi   = (int*)p;
    cudaGetSymbolAddress(&p, g_topw);   float* topw   = (float*)p;
    cudaGetSymbolAddress(&p, g_counts); int*   counts = (int*)p;
    cudaGetSymbolAddress(&p, g_cursor); int*   cursor = (int*)p;
    cudaGetSymbolAddress(&p, g_offs);   int*   offs   = (int*)p;
    cudaGetSymbolAddress(&p, g_order);  int*   order  = (int*)p;
    cudaGetSymbolAddress(&p, g_tokslot);int*   tokslot= (int*)p;

    // 1. rmsnorm1
    rmsnorm_kernel<<<NTOK, 256>>>(x, n1, hn);
    // 2. QKV projections (NT)
    gemm_nt<<<dim3(8,32,1),256>>>(hn, wq, q, nullptr, NTOK, DIMM, DIMM, DIMM, DIMM, DIMM,
                                  1.f, 1, 0,0,0,0,0,0);
    gemm_nt<<<dim3(8,32,1),256>>>(hn, wk, k, nullptr, NTOK, DIMM, DIMM, DIMM, DIMM, DIMM,
                                  1.f, 1, 0,0,0,0,0,0);
    gemm_nt<<<dim3(8,32,1),256>>>(hn, wv, v, nullptr, NTOK, DIMM, DIMM, DIMM, DIMM, DIMM,
                                  1.f, 1, 0,0,0,0,0,0);
    // 3. RoPE on q,k in place
    rope_kernel<<<(NTOK*NHEADS*32)/256, 256>>>(q, k);
    // 4. scores = 1/8 * Q K^T  (batched over b,h)
    gemm_nt<<<dim3(8,8,BB*NHEADS),256>>>(q, k, scores, nullptr, LL, LL, HD, DIMM, DIMM, LL,
                                         0.125f, NHEADS,
                                         (long long)LL*DIMM, HD,
                                         (long long)LL*DIMM, HD,
                                         (long long)NHEADS*LL*LL, (long long)LL*LL);
    // 5. softmax(+mask)
    softmax_kernel<<<BB*NHEADS*LL, 256>>>(scores, mask);
    // 6. attn = P @ V, written to [tok, h*64+d]
    attn_pv<<<dim3(1,16,BB*NHEADS),256>>>(scores, v, attn);
    // 7. h = x + attn @ wo^T
    gemm_nt<<<dim3(8,32,1),256>>>(attn, wo, hbuf, x, NTOK, DIMM, DIMM, DIMM, DIMM, DIMM,
                                  1.f, 1, 0,0,0,0,0,0);
    // 8. rmsnorm2
    rmsnorm_kernel<<<NTOK, 256>>>(hbuf, n2, xf);
    // 9-11. shared expert: silu(xf@s1^T)*(xf@s2^T) @ s3^T
    gemm_nt<<<dim3(16,32,1),256>>>(xf, s1, ta, nullptr, NTOK, NSHARED, DIMM, DIMM, DIMM, NSHARED,
                                   1.f, 1, 0,0,0,0,0,0);
    gemm_nt<<<dim3(16,32,1),256>>>(xf, s2, tb, nullptr, NTOK, NSHARED, DIMM, DIMM, DIMM, NSHARED,
                                   1.f, 1, 0,0,0,0,0,0);
    silumul_kernel<<<(NTOK*NSHARED)/256, 256>>>(ta, tb, (long long)NTOK*NSHARED);
    gemm_nt<<<dim3(8,32,1),256>>>(ta, s3, moe, nullptr, NTOK, DIMM, NSHARED, NSHARED, NSHARED, DIMM,
                                  1.f, 1, 0,0,0,0,0,0);
    // 12-15. routing
    zero_counts<<<1,32>>>(counts);
    gate_topk<<<NTOK,256>>>(xf, gw, topi, topw, counts);
    scan_kernel<<<1,1>>>(counts, offs, cursor);
    scatter_kernel<<<NTOK/256,256>>>(topi, cursor, offs, order, tokslot);
    // 16. expert fc1 (gathered, silu epilogue): hexp[slot, 0..512)
    gemm_nt_grouped<<<dim3(4,32,NE),256>>>(xf, fc1, hexp, counts, offs, order,
                                           HID, DIMM, DIMM, HID, (long long)HID*DIMM, 1);
    // 17. expert fc2: yexp[slot, 0..1024)
    gemm_nt_grouped<<<dim3(8,32,NE),256>>>(hexp, fc2, yexp, counts, offs, nullptr,
                                           DIMM, HID, HID, DIMM, (long long)DIMM*HID, 0);
    // 18. final combine
    final_kernel<<<(NTOK*DIMM)/256, 256>>>(hbuf, moe, yexp, tokslot, topw, out);
}

// round 3
// speedup vs baseline: 1.8854x; 1.8854x over previous
#include <cuda_runtime.h>
#include <cuda_bf16.h>
#include <math.h>
#include <stdint.h>

#define BB 4
#define LL 1024
#define DIMM 1024
#define NHEADS 16
#define HD 64
#define NTOK (BB*LL)
#define HID 512
#define NE 16
#define NSHARED 2048
#define NSLOTS (NTOK*2)

// ---------------- scratch (static device globals: allowed) ----------------
__device__ float g_hn[NTOK*DIMM];
__device__ float g_q[NTOK*DIMM];
__device__ float g_k[NTOK*DIMM];
__device__ float g_v[NTOK*DIMM];
__device__ float g_scores[(long long)BB*NHEADS*LL*LL];   // 256 MB
__device__ float g_attn[NTOK*DIMM];
__device__ float g_h[NTOK*DIMM];
__device__ float g_xf[NTOK*DIMM];
__device__ float g_ta[NTOK*NSHARED];
__device__ float g_tb[NTOK*NSHARED];
__device__ float g_moe[NTOK*DIMM];
__device__ float g_hexp[NSLOTS*HID];
__device__ float g_yexp[NSLOTS*DIMM];
__device__ int   g_topi[NSLOTS];
__device__ float g_topw[NSLOTS];
__device__ int   g_counts[NE];
__device__ int   g_cursor[NE];
__device__ int   g_offs[NE];
__device__ int   g_order[NSLOTS];
__device__ int   g_tokslot[NSLOTS];

__device__ __forceinline__ uint32_t smem_u32(const void* p){
    uint32_t a;
    asm("{ .reg .u64 t; cvta.to.shared.u64 t, %1; cvt.u32.u64 %0, t; }" : "=r"(a) : "l"(p));
    return a;
}

#define LDMX4(r0,r1,r2,r3,addr) \
    asm volatile("ldmatrix.sync.aligned.m8n8.x4.shared.b16 {%0,%1,%2,%3}, [%4];" \
        : "=r"(r0),"=r"(r1),"=r"(r2),"=r"(r3) : "r"(addr))

#define MMA16816(c0,c1,c2,c3,a0,a1,a2,a3,b0,b1) \
    asm volatile("mma.sync.aligned.m16n8k16.row.col.f32.bf16.bf16.f32 " \
        "{%0,%1,%2,%3}, {%4,%5,%6,%7}, {%8,%9}, {%0,%1,%2,%3};" \
        : "+f"(c0),"+f"(c1),"+f"(c2),"+f"(c3) \
        : "r"(a0),"r"(a1),"r"(a2),"r"(a3), "r"(b0),"r"(b1))

// ==================  split-bf16 mma.sync NT GEMM  ==================
// C[M,N] = A[M,K] * B[N,K]^T ; fp32 in/out; bf16 hi/lo 3-term split (HH+HL+LH).
// mode: 0 plain, 1 += res, 2 silu. Grouped (experts) via counts/offs/rows.
// N must be a multiple of 128, K a multiple of 32.
#define SSTR 40   // bf16 elems per smem row (32 data + 8 pad)

__global__ void __launch_bounds__(256) mm_mma(
    const float* __restrict__ A, const float* __restrict__ B, float* __restrict__ C,
    const float* __restrict__ res,
    int M, int N, int K, int lda, int ldb, int ldc, int mode,
    const int* __restrict__ counts, const int* __restrict__ offs,
    const int* __restrict__ rows, long long bStrideE)
{
    __shared__ __align__(16) __nv_bfloat16 sAh[128*SSTR];
    __shared__ __align__(16) __nv_bfloat16 sAl[128*SSTR];
    __shared__ __align__(16) __nv_bfloat16 sBh[128*SSTR];
    __shared__ __align__(16) __nv_bfloat16 sBl[128*SSTR];
    __shared__ int rsrc[128];

    int tid = threadIdx.x, wid = tid >> 5, lane = tid & 31;
    int e = blockIdx.z;

    int Mloc = M, rowOff = 0;
    const float* Bp = B;
    if (counts){ Mloc = counts[e]; rowOff = offs[e]; Bp = B + (long long)e * bStrideE; }
    int m0 = blockIdx.y * 128;
    if (m0 >= Mloc) return;
    int n0 = blockIdx.x * 128;

    for (int i = tid; i < 128; i += 256){
        int gr = m0 + i;
        rsrc[i] = (gr < Mloc) ? (rows ? rows[rowOff + gr] : (counts ? rowOff + gr : gr)) : -1;
    }
    __syncthreads();

    float acc[4][4][4];   // [mt][nt8][frag]
    #pragma unroll
    for (int i = 0; i < 4; i++)
        #pragma unroll
        for (int j = 0; j < 4; j++)
            #pragma unroll
            for (int f = 0; f < 4; f++) acc[i][j][f] = 0.f;

    int lr = tid >> 1;          // smem row this thread loads (0..127)
    int lk = (tid & 1) * 16;    // k-half within 32-chunk
    int src = rsrc[lr];
    const float* bRow = Bp + (long long)(n0 + lr) * ldb + lk;
    const float* aRow = (src >= 0) ? (A + (long long)src * lda + lk) : nullptr;

    int wm = (wid >> 2) * 64;   // warp m offset in tile
    int wn = (wid & 3) * 32;    // warp n offset in tile

    uint32_t uAh = smem_u32(sAh), uAl = smem_u32(sAl);
    uint32_t uBh = smem_u32(sBh), uBl = smem_u32(sBl);
    // ldmatrix lane address components
    int lrow = lane & 15, lsel = (lane >> 4) * 8;

    for (int kc = 0; kc < K; kc += 32){
        // ---- load + convert A,B 128x32 fp32 -> bf16 hi/lo smem ----
        #pragma unroll
        for (int j = 0; j < 4; j++){
            float4 av = aRow ? *(const float4*)(aRow + kc + 4*j)
                             : make_float4(0.f,0.f,0.f,0.f);
            __nv_bfloat162 h01 = __floats2bfloat162_rn(av.x, av.y);
            __nv_bfloat162 h23 = __floats2bfloat162_rn(av.z, av.w);
            __nv_bfloat162 l01 = __floats2bfloat162_rn(av.x - __low2float(h01), av.y - __high2float(h01));
            __nv_bfloat162 l23 = __floats2bfloat162_rn(av.z - __low2float(h23), av.w - __high2float(h23));
            int o = lr*SSTR + lk + 4*j;
            *(uint2*)&sAh[o] = make_uint2(*(uint32_t*)&h01, *(uint32_t*)&h23);
            *(uint2*)&sAl[o] = make_uint2(*(uint32_t*)&l01, *(uint32_t*)&l23);
            float4 bv = *(const float4*)(bRow + kc + 4*j);
            __nv_bfloat162 bh01 = __floats2bfloat162_rn(bv.x, bv.y);
            __nv_bfloat162 bh23 = __floats2bfloat162_rn(bv.z, bv.w);
            __nv_bfloat162 bl01 = __floats2bfloat162_rn(bv.x - __low2float(bh01), bv.y - __high2float(bh01));
            __nv_bfloat162 bl23 = __floats2bfloat162_rn(bv.z - __low2float(bh23), bv.w - __high2float(bh23));
            *(uint2*)&sBh[o] = make_uint2(*(uint32_t*)&bh01, *(uint32_t*)&bh23);
            *(uint2*)&sBl[o] = make_uint2(*(uint32_t*)&bl01, *(uint32_t*)&bl23);
        }
        __syncthreads();

        #pragma unroll
        for (int ks = 0; ks < 2; ks++){
            int kofs = ks*16 + lsel;
            uint32_t ah[4][4], al[4][4], bh[2][4], bl[2][4];
            #pragma unroll
            for (int mt = 0; mt < 4; mt++){
                uint32_t ad = 2u*((wm + mt*16 + lrow)*SSTR + kofs);
                LDMX4(ah[mt][0],ah[mt][1],ah[mt][2],ah[mt][3], uAh + ad);
                LDMX4(al[mt][0],al[mt][1],al[mt][2],al[mt][3], uAl + ad);
            }
            #pragma unroll
            for (int j = 0; j < 2; j++){
                uint32_t bd = 2u*((wn + j*16 + lrow)*SSTR + kofs);
                LDMX4(bh[j][0],bh[j][1],bh[j][2],bh[j][3], uBh + bd);
                LDMX4(bl[j][0],bl[j][1],bl[j][2],bl[j][3], uBl + bd);
            }
            #pragma unroll
            for (int mt = 0; mt < 4; mt++){
                #pragma unroll
                for (int j = 0; j < 2; j++){
                    float* c0 = acc[mt][2*j];
                    float* c1 = acc[mt][2*j+1];
                    // HH
                    MMA16816(c0[0],c0[1],c0[2],c0[3], ah[mt][0],ah[mt][1],ah[mt][2],ah[mt][3], bh[j][0],bh[j][2]);
                    MMA16816(c1[0],c1[1],c1[2],c1[3], ah[mt][0],ah[mt][1],ah[mt][2],ah[mt][3], bh[j][1],bh[j][3]);
                    // HL
                    MMA16816(c0[0],c0[1],c0[2],c0[3], ah[mt][0],ah[mt][1],ah[mt][2],ah[mt][3], bl[j][0],bl[j][2]);
                    MMA16816(c1[0],c1[1],c1[2],c1[3], ah[mt][0],ah[mt][1],ah[mt][2],ah[mt][3], bl[j][1],bl[j][3]);
                    // LH
                    MMA16816(c0[0],c0[1],c0[2],c0[3], al[mt][0],al[mt][1],al[mt][2],al[mt][3], bh[j][0],bh[j][2]);
                    MMA16816(c1[0],c1[1],c1[2],c1[3], al[mt][0],al[mt][1],al[mt][2],al[mt][3], bh[j][1],bh[j][3]);
                }
            }
        }
        __syncthreads();
    }

    // ---- epilogue ----
    int rbase = lane >> 2;
    int cbase = (lane & 3) * 2;
    #pragma unroll
    for (int mt = 0; mt < 4; mt++){
        #pragma unroll
        for (int nt = 0; nt < 4; nt++){
            int gn = n0 + wn + nt*8 + cbase;
            #pragma unroll
            for (int half = 0; half < 2; half++){
                int gm = m0 + wm + mt*16 + rbase + half*8;
                if (gm >= Mloc) continue;
                float v0 = acc[mt][nt][2*half];
                float v1 = acc[mt][nt][2*half+1];
                long long ci = (long long)(rowOff + gm) * ldc + gn;
                if (mode == 1){
                    v0 += res[ci]; v1 += res[ci+1];
                } else if (mode == 2){
                    v0 = v0 / (1.f + expf(-v0));
                    v1 = v1 / (1.f + expf(-v1));
                }
                float2 o = make_float2(v0, v1);
                *(float2*)(C + ci) = o;
            }
        }
    }
}

// ---------------- reductions ----------------
__device__ __forceinline__ float warpReduceSum(float v){
    #pragma unroll
    for (int o=16;o;o>>=1) v += __shfl_xor_sync(0xffffffffu, v, o);
    return v;
}
__device__ __forceinline__ float warpReduceMax(float v){
    #pragma unroll
    for (int o=16;o;o>>=1) v = fmaxf(v, __shfl_xor_sync(0xffffffffu, v, o));
    return v;
}
__device__ float blockReduceSum(float v){
    __shared__ float sh[33];
    int lane = threadIdx.x & 31, wid = threadIdx.x >> 5;
    __syncthreads();
    v = warpReduceSum(v);
    if (lane==0) sh[wid] = v;
    __syncthreads();
    int nw = blockDim.x >> 5;
    float r = (threadIdx.x < nw) ? sh[threadIdx.x] : 0.f;
    if (wid==0){ r = warpReduceSum(r); if (lane==0) sh[32] = r; }
    __syncthreads();
    return sh[32];
}
__device__ float blockReduceMax(float v){
    __shared__ float sh[33];
    int lane = threadIdx.x & 31, wid = threadIdx.x >> 5;
    __syncthreads();
    v = warpReduceMax(v);
    if (lane==0) sh[wid] = v;
    __syncthreads();
    int nw = blockDim.x >> 5;
    float r = (threadIdx.x < nw) ? sh[threadIdx.x] : -3.0e38f;
    if (wid==0){ r = warpReduceMax(r); if (lane==0) sh[32] = r; }
    __syncthreads();
    return sh[32];
}

// ---------------- rmsnorm ----------------
__global__ void __launch_bounds__(256) rmsnorm_kernel(const float* __restrict__ x,
                                                      const float* __restrict__ w,
                                                      float* __restrict__ out){
    long long row = blockIdx.x;
    const float4* xr = (const float4*)(x + row*DIMM);
    float4 xv = xr[threadIdx.x];
    float ss = xv.x*xv.x + xv.y*xv.y + xv.z*xv.z + xv.w*xv.w;
    float tot = blockReduceSum(ss);
    float scale = rsqrtf(tot * (1.0f/DIMM) + 1e-5f);
    float4 wv = ((const float4*)w)[threadIdx.x];
    float4 o;
    o.x = xv.x*scale*wv.x; o.y = xv.y*scale*wv.y;
    o.z = xv.z*scale*wv.z; o.w = xv.w*scale*wv.w;
    ((float4*)(out + row*DIMM))[threadIdx.x] = o;
}

// ---------------- fp32 batched NT GEMM (attention scores only) --------
__global__ void __launch_bounds__(256) gemm_nt(
    const float* __restrict__ A, const float* __restrict__ B, float* __restrict__ C,
    const float* __restrict__ res,
    int M, int N, int K, int lda, int ldb, int ldc, float alpha,
    int bdiv, long long aO, long long aI, long long bO, long long bI,
    long long cO, long long cI)
{
    int z = blockIdx.z;
    long long aOff = (long long)(z/bdiv)*aO + (long long)(z%bdiv)*aI;
    long long bOff = (long long)(z/bdiv)*bO + (long long)(z%bdiv)*bI;
    long long cOff = (long long)(z/bdiv)*cO + (long long)(z%bdiv)*cI;
    const float* Ab = A + aOff;
    const float* Bb = B + bOff;
    __shared__ float As[8][132];
    __shared__ float Bs[8][132];
    int row0 = blockIdx.y * 128, col0 = blockIdx.x * 128;
    int tid = threadIdx.x, tx = tid & 15, ty = tid >> 4;
    float acc[8][8] = {};
    for (int k0 = 0; k0 < K; k0 += 8){
        #pragma unroll
        for (int i = tid; i < 1024; i += 256){
            int r = i >> 3, c = i & 7; int gr = row0 + r;
            As[c][r] = (gr < M) ? Ab[(long long)gr*lda + k0 + c] : 0.f;
        }
        #pragma unroll
        for (int i = tid; i < 1024; i += 256){
            int r = i >> 3, c = i & 7; int gc = col0 + r;
            Bs[c][r] = (gc < N) ? Bb[(long long)gc*ldb + k0 + c] : 0.f;
        }
        __syncthreads();
        #pragma unroll
        for (int kk = 0; kk < 8; kk++){
            float a[8], b[8];
            #pragma unroll
            for (int i = 0; i < 8; i++) a[i] = As[kk][ty*8+i];
            #pragma unroll
            for (int j = 0; j < 8; j++) b[j] = Bs[kk][tx*8+j];
            #pragma unroll
            for (int i = 0; i < 8; i++)
                #pragma unroll
                for (int j = 0; j < 8; j++) acc[i][j] = fmaf(a[i], b[j], acc[i][j]);
        }
        __syncthreads();
    }
    #pragma unroll
    for (int i = 0; i < 8; i++){
        int gm = row0 + ty*8 + i; if (gm >= M) continue;
        #pragma unroll
        for (int j = 0; j < 8; j++){
            int gn = col0 + tx*8 + j; if (gn >= N) continue;
            long long ci = cOff + (long long)gm*ldc + gn;
            float v = acc[i][j] * alpha;
            if (res) v += res[ci];
            C[ci] = v;
        }
    }
}

// ---------------- RoPE (in-place on q,k in [tok, h*64+d] layout) ----------------
__global__ void rope_kernel(float* __restrict__ q, float* __restrict__ k){
    int idx = blockIdx.x*blockDim.x + threadIdx.x;
    if (idx >= NTOK*NHEADS*(HD/2)) return;
    int j = idx & 31;
    int h = (idx >> 5) & 15;
    int t = idx >> 9;
    int l = t & (LL-1);
    long long base = (long long)t*DIMM + h*HD;
    float inv = powf(10000.f, -(float)j * (1.f/32.f));
    float ang = (float)l * inv;
    float sn, cs; sincosf(ang, &sn, &cs);
    float a = q[base+j], b = q[base+32+j];
    q[base+j]    = a*cs - b*sn;
    q[base+32+j] = a*sn + b*cs;
    a = k[base+j]; b = k[base+32+j];
    k[base+j]    = a*cs - b*sn;
    k[base+32+j] = a*sn + b*cs;
}

// ---------------- softmax over key dim, +mask ----------------
__global__ void __launch_bounds__(256) softmax_kernel(float* __restrict__ s,
                                                      const float* __restrict__ mask){
    long long row = blockIdx.x;
    int q = (int)(row & (LL-1));
    float* p = s + row*LL;
    const float* mr = mask + (long long)q*LL;
    float4 v = ((float4*)p)[threadIdx.x];
    float4 m = ((const float4*)mr)[threadIdx.x];
    v.x += m.x; v.y += m.y; v.z += m.z; v.w += m.w;
    float mx = fmaxf(fmaxf(v.x,v.y), fmaxf(v.z,v.w));
    mx = blockReduceMax(mx);
    float4 e;
    e.x = expf(v.x-mx); e.y = expf(v.y-mx); e.z = expf(v.z-mx); e.w = expf(v.w-mx);
    float sum = blockReduceSum(e.x+e.y+e.z+e.w);
    float invs = 1.f / sum;
    e.x *= invs; e.y *= invs; e.z *= invs; e.w *= invs;
    ((float4*)p)[threadIdx.x] = e;
}

// ---------------- P(probs) @ V ----------------
__global__ void __launch_bounds__(256) attn_pv(const float* __restrict__ P,
                                               const float* __restrict__ V,
                                               float* __restrict__ O){
    int zb = blockIdx.z;
    int b = zb >> 4, h = zb & 15;
    int m0 = blockIdx.y * 64;
    const float* Pb = P + (long long)zb*LL*LL;
    __shared__ float Ps[64][33];
    __shared__ float Vs[32][65];
    int tid = threadIdx.x, tx = tid & 15, ty = tid >> 4;
    float acc[4][4] = {};
    for (int k0 = 0; k0 < LL; k0 += 32){
        #pragma unroll
        for (int i = tid; i < 2048; i += 256){
            int r = i >> 5, c = i & 31;
            Ps[r][c] = Pb[(long long)(m0+r)*LL + k0 + c];
        }
        #pragma unroll
        for (int i = tid; i < 2048; i += 256){
            int r = i >> 6, c = i & 63;
            Vs[r][c] = V[(long long)(b*LL + k0 + r)*DIMM + h*HD + c];
        }
        __syncthreads();
        #pragma unroll
        for (int kk = 0; kk < 32; kk++){
            float a[4], bv[4];
            #pragma unroll
            for (int i = 0; i < 4; i++) a[i] = Ps[ty*4+i][kk];
            #pragma unroll
            for (int j = 0; j < 4; j++) bv[j] = Vs[kk][tx*4+j];
            #pragma unroll
            for (int i = 0; i < 4; i++)
                #pragma unroll
                for (int j = 0; j < 4; j++) acc[i][j] = fmaf(a[i], bv[j], acc[i][j]);
        }
        __syncthreads();
    }
    #pragma unroll
    for (int i = 0; i < 4; i++)
        #pragma unroll
        for (int j = 0; j < 4; j++)
            O[(long long)(b*LL + m0 + ty*4 + i)*DIMM + h*HD + tx*4 + j] = acc[i][j];
}

// ---------------- silu(a)*b ----------------
__global__ void silumul_kernel(float* __restrict__ ta, const float* __restrict__ tb, long long n){
    long long i = (long long)blockIdx.x*blockDim.x + threadIdx.x;
    if (i >= n) return;
    float a = ta[i], b = tb[i];
    ta[i] = a / (1.f + expf(-a)) * b;
}

// ---------------- gate logits + top2 + softmax + count ----------------
__global__ void __launch_bounds__(256) gate_topk(const float* __restrict__ xf,
                                                 const float* __restrict__ gw,
                                                 int* __restrict__ topi, float* __restrict__ topw,
                                                 int* __restrict__ counts){
    int t = blockIdx.x;
    int tid = threadIdx.x;
    float4 xv = ((const float4*)(xf + (long long)t*DIMM))[tid];
    float acc[16];
    #pragma unroll
    for (int e = 0; e < 16; e++){
        float4 g = ((const float4*)(gw + (long long)e*DIMM))[tid];
        acc[e] = xv.x*g.x + xv.y*g.y + xv.z*g.z + xv.w*g.w;
    }
    #pragma unroll
    for (int e = 0; e < 16; e++) acc[e] = warpReduceSum(acc[e]);
    __shared__ float wr[8][16];
    __shared__ float lg[16];
    int lane = tid & 31, wid = tid >> 5;
    if (lane == 0){
        #pragma unroll
        for (int e = 0; e < 16; e++) wr[wid][e] = acc[e];
    }
    __syncthreads();
    if (tid < 16){
        float s = 0.f;
        #pragma unroll
        for (int w = 0; w < 8; w++) s += wr[w][tid];
        lg[tid] = s;
    }
    __syncthreads();
    if (tid == 0){
        float l0 = -3.0e38f; int i0 = 0;
        for (int e = 0; e < 16; e++) if (lg[e] > l0){ l0 = lg[e]; i0 = e; }
        float l1 = -3.0e38f; int i1 = 0;
        for (int e = 0; e < 16; e++) if (e != i0 && lg[e] > l1){ l1 = lg[e]; i1 = e; }
        float w1 = expf(l1 - l0);
        float s = 1.f + w1;
        topi[2*t] = i0; topi[2*t+1] = i1;
        topw[2*t] = 1.f / s; topw[2*t+1] = w1 / s;
        atomicAdd(&counts[i0], 1);
        atomicAdd(&counts[i1], 1);
    }
}

__global__ void zero_counts(int* counts){
    if (threadIdx.x < NE) counts[threadIdx.x] = 0;
}

__global__ void scan_kernel(const int* __restrict__ counts, int* __restrict__ offs,
                            int* __restrict__ cursor){
    if (threadIdx.x == 0){
        int s = 0;
        for (int e = 0; e < NE; e++){ offs[e] = s; s += counts[e]; cursor[e] = 0; }
    }
}

__global__ void scatter_kernel(const int* __restrict__ topi, int* __restrict__ cursor,
                               const int* __restrict__ offs, int* __restrict__ order,
                               int* __restrict__ tokslot){
    int t = blockIdx.x*blockDim.x + threadIdx.x;
    if (t >= NTOK) return;
    #pragma unroll
    for (int k = 0; k < 2; k++){
        int e = topi[2*t+k];
        int pos = atomicAdd(&cursor[e], 1);
        int slot = offs[e] + pos;
        order[slot] = t;
        tokslot[2*t+k] = slot;
    }
}

// ---------------- final: out = h + shared_moe + sum_k w_k * y[slot_k] ----------------
__global__ void final_kernel(const float* __restrict__ h, const float* __restrict__ moe,
                             const float* __restrict__ y, const int* __restrict__ tokslot,
                             const float* __restrict__ topw, float* __restrict__ out){
    long long idx = (long long)blockIdx.x*blockDim.x + threadIdx.x;
    if (idx >= (long long)NTOK*DIMM) return;
    int t = (int)(idx >> 10);
    int i = (int)(idx & 1023);
    int s0 = tokslot[2*t], s1 = tokslot[2*t+1];
    float w0 = topw[2*t], w1 = topw[2*t+1];
    out[idx] = h[idx] + moe[idx] + w0*y[(long long)s0*DIMM + i] + w1*y[(long long)s1*DIMM + i];
}

// ---------------- host launcher ----------------
extern "C" void kernel_launch(void* const* d_in, const int* in_sizes, int n_in,
                              void* d_out, int out_size){
    const float* x    = (const float*)d_in[0];
    const float* mask = (const float*)d_in[1];
    const float* wq   = (const float*)d_in[2];
    const float* wk   = (const float*)d_in[3];
    const float* wv   = (const float*)d_in[4];
    const float* wo   = (const float*)d_in[5];
    const float* n1   = (const float*)d_in[6];
    const float* n2   = (const float*)d_in[7];
    const float* gw   = (const float*)d_in[8];
    const float* fc1  = (const float*)d_in[9];
    const float* fc2  = (const float*)d_in[10];
    const float* s1   = (const float*)d_in[11];
    const float* s2   = (const float*)d_in[12];
    const float* s3   = (const float*)d_in[13];
    float* out = (float*)d_out;

    void *p;
    cudaGetSymbolAddress(&p, g_hn);     float* hn     = (float*)p;
    cudaGetSymbolAddress(&p, g_q);      float* q      = (float*)p;
    cudaGetSymbolAddress(&p, g_k);      float* k      = (float*)p;
    cudaGetSymbolAddress(&p, g_v);      float* v      = (float*)p;
    cudaGetSymbolAddress(&p, g_scores); float* scores = (float*)p;
    cudaGetSymbolAddress(&p, g_attn);   float* attn   = (float*)p;
    cudaGetSymbolAddress(&p, g_h);      float* hbuf   = (float*)p;
    cudaGetSymbolAddress(&p, g_xf);     float* xf     = (float*)p;
    cudaGetSymbolAddress(&p, g_ta);     float* ta     = (float*)p;
    cudaGetSymbolAddress(&p, g_tb);     float* tb     = (float*)p;
    cudaGetSymbolAddress(&p, g_moe);    float* moe    = (float*)p;
    cudaGetSymbolAddress(&p, g_hexp);   float* hexp   = (float*)p;
    cudaGetSymbolAddress(&p, g_yexp);   float* yexp   = (float*)p;
    cudaGetSymbolAddress(&p, g_topi);   int*   topi   = (int*)p;
    cudaGetSymbolAddress(&p, g_topw);   float* topw   = (float*)p;
    cudaGetSymbolAddress(&p, g_counts); int*   counts = (int*)p;
    cudaGetSymbolAddress(&p, g_cursor); int*   cursor = (int*)p;
    cudaGetSymbolAddress(&p, g_offs);   int*   offs   = (int*)p;
    cudaGetSymbolAddress(&p, g_order);  int*   order  = (int*)p;
    cudaGetSymbolAddress(&p, g_tokslot);int*   tokslot= (int*)p;

    // 1. rmsnorm1
    rmsnorm_kernel<<<NTOK, 256>>>(x, n1, hn);
    // 2. QKV projections on tensor cores (split-bf16)
    mm_mma<<<dim3(8,32,1),256>>>(hn, wq, q, nullptr, NTOK, DIMM, DIMM, DIMM, DIMM, DIMM, 0, nullptr, nullptr, nullptr, 0);
    mm_mma<<<dim3(8,32,1),256>>>(hn, wk, k, nullptr, NTOK, DIMM, DIMM, DIMM, DIMM, DIMM, 0, nullptr, nullptr, nullptr, 0);
    mm_mma<<<dim3(8,32,1),256>>>(hn, wv, v, nullptr, NTOK, DIMM, DIMM, DIMM, DIMM, DIMM, 0, nullptr, nullptr, nullptr, 0);
    // 3. RoPE on q,k in place
    rope_kernel<<<(NTOK*NHEADS*32)/256, 256>>>(q, k);
    // 4. scores = 1/8 * Q K^T  (batched over b,h) — fp32
    gemm_nt<<<dim3(8,8,BB*NHEADS),256>>>(q, k, scores, nullptr, LL, LL, HD, DIMM, DIMM, LL,
                                         0.125f, NHEADS,
                                         (long long)LL*DIMM, HD,
                                         (long long)LL*DIMM, HD,
                                         (long long)NHEADS*LL*LL, (long long)LL*LL);
    // 5. softmax(+mask)
    softmax_kernel<<<BB*NHEADS*LL, 256>>>(scores, mask);
    // 6. attn = P @ V
    attn_pv<<<dim3(1,16,BB*NHEADS),256>>>(scores, v, attn);
    // 7. h = x + attn @ wo^T
    mm_mma<<<dim3(8,32,1),256>>>(attn, wo, hbuf, x, NTOK, DIMM, DIMM, DIMM, DIMM, DIMM, 1, nullptr, nullptr, nullptr, 0);
    // 8. rmsnorm2
    rmsnorm_kernel<<<NTOK, 256>>>(hbuf, n2, xf);
    // 9-11. shared expert
    mm_mma<<<dim3(16,32,1),256>>>(xf, s1, ta, nullptr, NTOK, NSHARED, DIMM, DIMM, DIMM, NSHARED, 0, nullptr, nullptr, nullptr, 0);
    mm_mma<<<dim3(16,32,1),256>>>(xf, s2, tb, nullptr, NTOK, NSHARED, DIMM, DIMM, DIMM, NSHARED, 0, nullptr, nullptr, nullptr, 0);
    silumul_kernel<<<(NTOK*NSHARED)/256, 256>>>(ta, tb, (long long)NTOK*NSHARED);
    mm_mma<<<dim3(8,32,1),256>>>(ta, s3, moe, nullptr, NTOK, DIMM, NSHARED, NSHARED, NSHARED, DIMM, 0, nullptr, nullptr, nullptr, 0);
    // 12-15. routing
    zero_counts<<<1,32>>>(counts);
    gate_topk<<<NTOK,256>>>(xf, gw, topi, topw, counts);
    scan_kernel<<<1,1>>>(counts, offs, cursor);
    scatter_kernel<<<NTOK/256,256>>>(topi, cursor, offs, order, tokslot);
    // 16. expert fc1 (gathered rows, silu epilogue)
    mm_mma<<<dim3(4,64,NE),256>>>(xf, fc1, hexp, nullptr, 0, HID, DIMM, DIMM, DIMM, HID, 2, counts, offs, order, (long long)HID*DIMM);
    // 17. expert fc2
    mm_mma<<<dim3(8,64,NE),256>>>(hexp, fc2, yexp, nullptr, 0, DIMM, HID, HID, HID, DIMM, 0, counts, offs, nullptr, (long long)DIMM*HID);
    // 18. final combine
    final_kernel<<<(NTOK*DIMM)/256, 256>>>(hbuf, moe, yexp, tokslot, topw, out);
}

// round 4
// speedup vs baseline: 2.4490x; 1.2989x over previous
#include <cuda_runtime.h>
#include <cuda_bf16.h>
#include <math.h>
#include <stdint.h>

#define BB 4
#define LL 1024
#define DIMM 1024
#define NHEADS 16
#define HD 64
#define NTOK (BB*LL)
#define HID 512
#define NE 16
#define NSHARED 2048
#define NSLOTS (NTOK*2)

typedef __nv_bfloat16 bf16;
typedef __nv_bfloat162 bf162;

// ---------------- scratch ----------------
__device__ float g_q[NTOK*DIMM];
__device__ float g_k[NTOK*DIMM];
__device__ float g_v[NTOK*DIMM];
__device__ float g_h[NTOK*DIMM];
__device__ float g_xf[NTOK*DIMM];
__device__ float g_ta[NTOK*NSHARED];
__device__ float g_tb[NTOK*NSHARED];
__device__ float g_moe[NTOK*DIMM];
__device__ float g_hexp[NSLOTS*HID];
__device__ float g_yexp[NSLOTS*DIMM];
// bf16 hi/lo buffers
__device__ bf16 g_hnh[NTOK*DIMM], g_hnl[NTOK*DIMM];
__device__ bf16 g_wh[NE*HID*DIMM], g_wl[NE*HID*DIMM];        // 8M weight scratch
__device__ bf16 g_qh[NTOK*DIMM], g_ql[NTOK*DIMM];
__device__ bf16 g_kh[NTOK*DIMM], g_kl[NTOK*DIMM];
__device__ bf16 g_vh[NTOK*DIMM], g_vl[NTOK*DIMM];
__device__ bf16 g_ah[NTOK*DIMM], g_al[NTOK*DIMM];            // attn out
__device__ bf16 g_xh[NTOK*DIMM], g_xl[NTOK*DIMM];            // xf
__device__ bf16 g_tah[NTOK*NSHARED], g_tal[NTOK*NSHARED];
__device__ bf16 g_eh[NSLOTS*HID], g_el[NSLOTS*HID];
// routing
__device__ int   g_topi[NSLOTS];
__device__ float g_topw[NSLOTS];
__device__ int   g_counts[NE];
__device__ int   g_cursor[NE];
__device__ int   g_offs[NE];
__device__ int   g_order[NSLOTS];
__device__ int   g_tokslot[NSLOTS];

__device__ __forceinline__ uint32_t smem_u32(const void* p){
    uint32_t a;
    asm("{ .reg .u64 t; cvta.to.shared.u64 t, %1; cvt.u32.u64 %0, t; }" : "=r"(a) : "l"(p));
    return a;
}

#define LDMX4(r0,r1,r2,r3,addr) \
    asm volatile("ldmatrix.sync.aligned.m8n8.x4.shared.b16 {%0,%1,%2,%3}, [%4];" \
        : "=r"(r0),"=r"(r1),"=r"(r2),"=r"(r3) : "r"(addr))
#define LDMX4T(r0,r1,r2,r3,addr) \
    asm volatile("ldmatrix.sync.aligned.m8n8.x4.trans.shared.b16 {%0,%1,%2,%3}, [%4];" \
        : "=r"(r0),"=r"(r1),"=r"(r2),"=r"(r3) : "r"(addr))

#define MMA16816(c0,c1,c2,c3,a0,a1,a2,a3,b0,b1) \
    asm volatile("mma.sync.aligned.m16n8k16.row.col.f32.bf16.bf16.f32 " \
        "{%0,%1,%2,%3}, {%4,%5,%6,%7}, {%8,%9}, {%0,%1,%2,%3};" \
        : "+f"(c0),"+f"(c1),"+f"(c2),"+f"(c3) \
        : "r"(a0),"r"(a1),"r"(a2),"r"(a3), "r"(b0),"r"(b1))

#define CPASYNC(dst,src,sz) \
    asm volatile("cp.async.cg.shared.global [%0], [%1], 16, %2;" :: "r"(dst), "l"(src), "r"(sz))
#define CPCOMMIT() asm volatile("cp.async.commit_group;")
#define CPWAIT(n)  asm volatile("cp.async.wait_group %0;" :: "n"(n))

// =============== split-bf16 GEMM, preconverted operands, cp.async 2-stage ===============
// C[M,N] = A[M,K]*B[N,K]^T. A/B as bf16 hi/lo pairs. mode: 0 plain, 1 +=res, 2 silu.
#define SSTR 40
#define STGB 10240           // bytes per operand-array per stage (128*40*2)
#define STAGE_BYTES 40960    // 4 arrays
#define MMBF_SMEM 81920

__global__ void __launch_bounds__(256) mm_bf(
    const bf16* __restrict__ Ah, const bf16* __restrict__ Al,
    const bf16* __restrict__ Bh, const bf16* __restrict__ Bl,
    float* __restrict__ C, const float* __restrict__ res,
    int M, int N, int K, int lda, int ldb, int ldc, int mode,
    const int* __restrict__ counts, const int* __restrict__ offs,
    const int* __restrict__ rows, long long bStrideE)
{
    extern __shared__ __align__(16) char dsm[];
    __shared__ int rsrc[128];
    uint32_t ub = smem_u32(dsm);
    int tid = threadIdx.x, wid = tid >> 5, lane = tid & 31;
    int e = blockIdx.z;

    int Mloc = M, rowOff = 0;
    const bf16* Bhp = Bh; const bf16* Blp = Bl;
    if (counts){ Mloc = counts[e]; rowOff = offs[e];
                 Bhp = Bh + (long long)e*bStrideE; Blp = Bl + (long long)e*bStrideE; }
    int m0 = blockIdx.y * 128;
    if (m0 >= Mloc) return;
    int n0 = blockIdx.x * 128;

    for (int i = tid; i < 128; i += 256){
        int gr = m0 + i;
        rsrc[i] = (gr < Mloc) ? (rows ? rows[rowOff + gr] : (counts ? rowOff + gr : gr)) : -1;
    }
    __syncthreads();

    int lrow2 = tid >> 1, lhalf = (tid & 1) * 16;   // copy row / 16-elem half
    int asrc = rsrc[lrow2];
    int szA = (asrc >= 0) ? 16 : 0;
    const bf16* agh = Ah + (long long)asrc*lda + lhalf;
    const bf16* agl = Al + (long long)asrc*lda + lhalf;
    const bf16* bgh = Bhp + (long long)(n0 + lrow2)*ldb + lhalf;
    const bf16* bgl = Blp + (long long)(n0 + lrow2)*ldb + lhalf;
    uint32_t dstoff = (uint32_t)(lrow2*SSTR + lhalf)*2;

#define MMBF_ISSUE(stg, kc) do { \
    uint32_t d = ub + (stg)*STAGE_BYTES + dstoff; \
    int ko = (kc)*32; \
    CPASYNC(d,             agh + ko,     szA); CPASYNC(d+16,           agh + ko + 8, szA); \
    CPASYNC(d+STGB,        agl + ko,     szA); CPASYNC(d+STGB+16,      agl + ko + 8, szA); \
    CPASYNC(d+2*STGB,      bgh + ko,     16 ); CPASYNC(d+2*STGB+16,    bgh + ko + 8, 16 ); \
    CPASYNC(d+3*STGB,      bgl + ko,     16 ); CPASYNC(d+3*STGB+16,    bgl + ko + 8, 16 ); \
    CPCOMMIT(); } while(0)

    float acc[4][4][4];
    #pragma unroll
    for (int i=0;i<4;i++) for (int j=0;j<4;j++) for (int f=0;f<4;f++) acc[i][j][f]=0.f;

    int wm = (wid >> 2) * 64, wn = (wid & 3) * 32;
    int lrow = lane & 15, lsel = (lane >> 4) * 8;
    int nk = K >> 5;

    MMBF_ISSUE(0, 0);
    for (int kc = 0; kc < nk; kc++){
        int cur = kc & 1;
        if (kc + 1 < nk){ MMBF_ISSUE((kc+1)&1, kc+1); CPWAIT(1); }
        else            { CPWAIT(0); }
        __syncthreads();
        uint32_t uAh = ub + cur*STAGE_BYTES, uAl = uAh + STGB;
        uint32_t uBh = uAh + 2*STGB,         uBl = uAh + 3*STGB;
        #pragma unroll
        for (int ks = 0; ks < 2; ks++){
            int kofs = ks*16 + lsel;
            uint32_t ah[4][4], al[4][4], bh[2][4], bl[2][4];
            #pragma unroll
            for (int mt = 0; mt < 4; mt++){
                uint32_t ad = 2u*((wm + mt*16 + lrow)*SSTR + kofs);
                LDMX4(ah[mt][0],ah[mt][1],ah[mt][2],ah[mt][3], uAh + ad);
                LDMX4(al[mt][0],al[mt][1],al[mt][2],al[mt][3], uAl + ad);
            }
            #pragma unroll
            for (int j = 0; j < 2; j++){
                uint32_t bd = 2u*((wn + j*16 + lrow)*SSTR + kofs);
                LDMX4(bh[j][0],bh[j][1],bh[j][2],bh[j][3], uBh + bd);
                LDMX4(bl[j][0],bl[j][1],bl[j][2],bl[j][3], uBl + bd);
            }
            #pragma unroll
            for (int mt = 0; mt < 4; mt++){
                #pragma unroll
                for (int j = 0; j < 2; j++){
                    float* c0 = acc[mt][2*j];
                    float* c1 = acc[mt][2*j+1];
                    MMA16816(c0[0],c0[1],c0[2],c0[3], ah[mt][0],ah[mt][1],ah[mt][2],ah[mt][3], bh[j][0],bh[j][2]);
                    MMA16816(c1[0],c1[1],c1[2],c1[3], ah[mt][0],ah[mt][1],ah[mt][2],ah[mt][3], bh[j][1],bh[j][3]);
                    MMA16816(c0[0],c0[1],c0[2],c0[3], ah[mt][0],ah[mt][1],ah[mt][2],ah[mt][3], bl[j][0],bl[j][2]);
                    MMA16816(c1[0],c1[1],c1[2],c1[3], ah[mt][0],ah[mt][1],ah[mt][2],ah[mt][3], bl[j][1],bl[j][3]);
                    MMA16816(c0[0],c0[1],c0[2],c0[3], al[mt][0],al[mt][1],al[mt][2],al[mt][3], bh[j][0],bh[j][2]);
                    MMA16816(c1[0],c1[1],c1[2],c1[3], al[mt][0],al[mt][1],al[mt][2],al[mt][3], bh[j][1],bh[j][3]);
                }
            }
        }
        __syncthreads();
    }

    int rbase = lane >> 2, cbase = (lane & 3) * 2;
    #pragma unroll
    for (int mt = 0; mt < 4; mt++){
        #pragma unroll
        for (int nt = 0; nt < 4; nt++){
            int gn = n0 + wn + nt*8 + cbase;
            #pragma unroll
            for (int half = 0; half < 2; half++){
                int gm = m0 + wm + mt*16 + rbase + half*8;
                if (gm >= Mloc) continue;
                float v0 = acc[mt][nt][2*half];
                float v1 = acc[mt][nt][2*half+1];
                long long ci = (long long)(rowOff + gm)*ldc + gn;
                if (mode == 1){ v0 += res[ci]; v1 += res[ci+1]; }
                else if (mode == 2){
                    v0 = v0 / (1.f + expf(-v0));
                    v1 = v1 / (1.f + expf(-v1));
                }
                *(float2*)(C + ci) = make_float2(v0, v1);
            }
        }
    }
}

// ===================== fused flash attention (split bf16) =====================
#define FSTR 72
#define FLASH_SMEM (6*128*FSTR*2)

__global__ void __launch_bounds__(256,1) flash_attn(
    const bf16* __restrict__ qh, const bf16* __restrict__ ql,
    const bf16* __restrict__ kh, const bf16* __restrict__ kl,
    const bf16* __restrict__ vh, const bf16* __restrict__ vl,
    const float* __restrict__ mask,
    bf16* __restrict__ oh, bf16* __restrict__ ol)
{
    extern __shared__ __align__(16) char fsm[];
    bf16* sQh = (bf16*)fsm;
    bf16* sQl = sQh + 128*FSTR;
    bf16* sKh = sQl + 128*FSTR;
    bf16* sKl = sKh + 128*FSTR;
    bf16* sVh = sKl + 128*FSTR;
    bf16* sVl = sVh + 128*FSTR;

    int tid = threadIdx.x, wid = tid >> 5, lane = tid & 31;
    int bh = blockIdx.y, b = bh >> 4, h = bh & 15;
    int q0 = blockIdx.x * 128;
    long long tb = (long long)b * LL;
    int crow = tid >> 1, chalf = (tid & 1) * 32;

    { // load Q tile once
        long long g = (tb + q0 + crow)*DIMM + h*HD + chalf;
        uint4* d0 = (uint4*)&sQh[crow*FSTR + chalf];
        uint4* d1 = (uint4*)&sQl[crow*FSTR + chalf];
        const uint4* s0 = (const uint4*)(qh + g);
        const uint4* s1 = (const uint4*)(ql + g);
        #pragma unroll
        for (int i = 0; i < 4; i++){ d0[i] = s0[i]; d1[i] = s1[i]; }
    }
    __syncthreads();

    uint32_t uQh = smem_u32(sQh), uQl = smem_u32(sQl);
    uint32_t uKh = smem_u32(sKh), uKl = smem_u32(sKl);
    uint32_t uVh = smem_u32(sVh), uVl = smem_u32(sVl);
    int lr = lane & 15, ls = (lane >> 4) * 8;

    uint32_t aqh[4][4], aql[4][4];
    #pragma unroll
    for (int kc = 0; kc < 4; kc++){
        uint32_t ad = 2u*((wid*16 + lr)*FSTR + kc*16 + ls);
        LDMX4(aqh[kc][0],aqh[kc][1],aqh[kc][2],aqh[kc][3], uQh + ad);
        LDMX4(aql[kc][0],aql[kc][1],aql[kc][2],aql[kc][3], uQl + ad);
    }

    float oacc[8][4];
    #pragma unroll
    for (int i=0;i<8;i++) for (int j=0;j<4;j++) oacc[i][j]=0.f;
    float m0r = -1e30f, m1r = -1e30f, l0r = 0.f, l1r = 0.f;

    const float* mp0 = mask + (long long)(q0 + wid*16 + (lane>>2))*LL;
    const float* mp1 = mp0 + 8*LL;
    const float SC  = 0.125f * 1.44269504f;
    const float L2E = 1.44269504f;

    for (int jt = 0; jt < 8; jt++){
        __syncthreads();
        { // load K,V tile
            long long g = (tb + jt*128 + crow)*DIMM + h*HD + chalf;
            int so = crow*FSTR + chalf;
            const uint4 *k0 = (const uint4*)(kh+g), *k1 = (const uint4*)(kl+g);
            const uint4 *v0 = (const uint4*)(vh+g), *v1 = (const uint4*)(vl+g);
            uint4 *dk0 = (uint4*)&sKh[so], *dk1 = (uint4*)&sKl[so];
            uint4 *dv0 = (uint4*)&sVh[so], *dv1 = (uint4*)&sVl[so];
            #pragma unroll
            for (int i = 0; i < 4; i++){ dk0[i]=k0[i]; dk1[i]=k1[i]; dv0[i]=v0[i]; dv1[i]=v1[i]; }
        }
        __syncthreads();

        float s[16][4];
        #pragma unroll
        for (int i=0;i<16;i++) for (int j=0;j<4;j++) s[i][j]=0.f;

        #pragma unroll
        for (int kc = 0; kc < 4; kc++){
            #pragma unroll
            for (int np = 0; np < 8; np++){
                uint32_t bh_[4], bl_[4];
                uint32_t ad = 2u*((np*16 + lr)*FSTR + kc*16 + ls);
                LDMX4(bh_[0],bh_[1],bh_[2],bh_[3], uKh + ad);
                LDMX4(bl_[0],bl_[1],bl_[2],bl_[3], uKl + ad);
                float* c0 = s[2*np]; float* c1 = s[2*np+1];
                MMA16816(c0[0],c0[1],c0[2],c0[3], aqh[kc][0],aqh[kc][1],aqh[kc][2],aqh[kc][3], bh_[0],bh_[2]);
                MMA16816(c1[0],c1[1],c1[2],c1[3], aqh[kc][0],aqh[kc][1],aqh[kc][2],aqh[kc][3], bh_[1],bh_[3]);
                MMA16816(c0[0],c0[1],c0[2],c0[3], aqh[kc][0],aqh[kc][1],aqh[kc][2],aqh[kc][3], bl_[0],bl_[2]);
                MMA16816(c1[0],c1[1],c1[2],c1[3], aqh[kc][0],aqh[kc][1],aqh[kc][2],aqh[kc][3], bl_[1],bl_[3]);
                MMA16816(c0[0],c0[1],c0[2],c0[3], aql[kc][0],aql[kc][1],aql[kc][2],aql[kc][3], bh_[0],bh_[2]);
                MMA16816(c1[0],c1[1],c1[2],c1[3], aql[kc][0],aql[kc][1],aql[kc][2],aql[kc][3], bh_[1],bh_[3]);
            }
        }

        // scale + mask (base-2 domain), row max
        float mx0 = -1e30f, mx1 = -1e30f;
        #pragma unroll
        for (int nt = 0; nt < 16; nt++){
            int colb = jt*128 + nt*8 + (lane&3)*2;
            float2 mm0 = *(const float2*)(mp0 + colb);
            float2 mm1 = *(const float2*)(mp1 + colb);
            s[nt][0] = fmaf(s[nt][0], SC, mm0.x*L2E);
            s[nt][1] = fmaf(s[nt][1], SC, mm0.y*L2E);
            s[nt][2] = fmaf(s[nt][2], SC, mm1.x*L2E);
            s[nt][3] = fmaf(s[nt][3], SC, mm1.y*L2E);
            mx0 = fmaxf(mx0, fmaxf(s[nt][0], s[nt][1]));
            mx1 = fmaxf(mx1, fmaxf(s[nt][2], s[nt][3]));
        }
        mx0 = fmaxf(mx0, __shfl_xor_sync(0xffffffffu, mx0, 1));
        mx0 = fmaxf(mx0, __shfl_xor_sync(0xffffffffu, mx0, 2));
        mx1 = fmaxf(mx1, __shfl_xor_sync(0xffffffffu, mx1, 1));
        mx1 = fmaxf(mx1, __shfl_xor_sync(0xffffffffu, mx1, 2));

        float nm0 = fmaxf(m0r, mx0), nm1 = fmaxf(m1r, mx1);
        float al0 = exp2f(m0r - nm0), al1 = exp2f(m1r - nm1);
        m0r = nm0; m1r = nm1;

        float rs0 = 0.f, rs1 = 0.f;
        #pragma unroll
        for (int nt = 0; nt < 16; nt++){
            s[nt][0] = exp2f(s[nt][0] - nm0);
            s[nt][1] = exp2f(s[nt][1] - nm0);
            s[nt][2] = exp2f(s[nt][2] - nm1);
            s[nt][3] = exp2f(s[nt][3] - nm1);
            rs0 += s[nt][0] + s[nt][1];
            rs1 += s[nt][2] + s[nt][3];
        }
        rs0 += __shfl_xor_sync(0xffffffffu, rs0, 1);
        rs0 += __shfl_xor_sync(0xffffffffu, rs0, 2);
        rs1 += __shfl_xor_sync(0xffffffffu, rs1, 1);
        rs1 += __shfl_xor_sync(0xffffffffu, rs1, 2);
        l0r = l0r*al0 + rs0;
        l1r = l1r*al1 + rs1;
        #pragma unroll
        for (int dt = 0; dt < 8; dt++){
            oacc[dt][0] *= al0; oacc[dt][1] *= al0;
            oacc[dt][2] *= al1; oacc[dt][3] *= al1;
        }

        // PV: P frags from s, V B-frags via ldmatrix.trans
        #pragma unroll
        for (int kc2 = 0; kc2 < 8; kc2++){
            uint32_t pah[4], pal[4];
            {
                float c0 = s[2*kc2][0],  c1 = s[2*kc2][1];
                float c2 = s[2*kc2][2],  c3 = s[2*kc2][3];
                float d0 = s[2*kc2+1][0],d1 = s[2*kc2+1][1];
                float d2 = s[2*kc2+1][2],d3 = s[2*kc2+1][3];
                bf162 h0 = __floats2bfloat162_rn(c0, c1);
                bf162 h1 = __floats2bfloat162_rn(c2, c3);
                bf162 h2 = __floats2bfloat162_rn(d0, d1);
                bf162 h3 = __floats2bfloat162_rn(d2, d3);
                bf162 e0 = __floats2bfloat162_rn(c0-__low2float(h0), c1-__high2float(h0));
                bf162 e1 = __floats2bfloat162_rn(c2-__low2float(h1), c3-__high2float(h1));
                bf162 e2 = __floats2bfloat162_rn(d0-__low2float(h2), d1-__high2float(h2));
                bf162 e3 = __floats2bfloat162_rn(d2-__low2float(h3), d3-__high2float(h3));
                pah[0]=*(uint32_t*)&h0; pah[1]=*(uint32_t*)&h1; pah[2]=*(uint32_t*)&h2; pah[3]=*(uint32_t*)&h3;
                pal[0]=*(uint32_t*)&e0; pal[1]=*(uint32_t*)&e1; pal[2]=*(uint32_t*)&e2; pal[3]=*(uint32_t*)&e3;
            }
            #pragma unroll
            for (int dt = 0; dt < 4; dt++){
                uint32_t bvh[4], bvl[4];
                uint32_t ad = 2u*((kc2*16 + lr)*FSTR + dt*16 + ls);
                LDMX4T(bvh[0],bvh[1],bvh[2],bvh[3], uVh + ad);
                LDMX4T(bvl[0],bvl[1],bvl[2],bvl[3], uVl + ad);
                float* o0 = oacc[2*dt]; float* o1 = oacc[2*dt+1];
                MMA16816(o0[0],o0[1],o0[2],o0[3], pah[0],pah[1],pah[2],pah[3], bvh[0],bvh[1]);
                MMA16816(o0[0],o0[1],o0[2],o0[3], pah[0],pah[1],pah[2],pah[3], bvl[0],bvl[1]);
                MMA16816(o0[0],o0[1],o0[2],o0[3], pal[0],pal[1],pal[2],pal[3], bvh[0],bvh[1]);
                MMA16816(o1[0],o1[1],o1[2],o1[3], pah[0],pah[1],pah[2],pah[3], bvh[2],bvh[3]);
                MMA16816(o1[0],o1[1],o1[2],o1[3], pah[0],pah[1],pah[2],pah[3], bvl[2],bvl[3]);
                MMA16816(o1[0],o1[1],o1[2],o1[3], pal[0],pal[1],pal[2],pal[3], bvh[2],bvh[3]);
            }
        }
    }

    // finalize + write bf16 hi/lo
    float i0 = 1.f / l0r, i1 = 1.f / l1r;
    long long r0 = tb + q0 + wid*16 + (lane>>2);
    #pragma unroll
    for (int dt = 0; dt < 8; dt++){
        long long g0 = r0*DIMM + h*HD + dt*8 + (lane&3)*2;
        long long g1 = g0 + 8*DIMM;
        float v0 = oacc[dt][0]*i0, v1 = oacc[dt][1]*i0;
        float v2 = oacc[dt][2]*i1, v3 = oacc[dt][3]*i1;
        bf162 h0 = __floats2bfloat162_rn(v0, v1);
        bf162 h1 = __floats2bfloat162_rn(v2, v3);
        bf162 e0 = __floats2bfloat162_rn(v0-__low2float(h0), v1-__high2float(h0));
        bf162 e1 = __floats2bfloat162_rn(v2-__low2float(h1), v3-__high2float(h1));
        *(bf162*)(oh + g0) = h0;  *(bf162*)(ol + g0) = e0;
        *(bf162*)(oh + g1) = h1;  *(bf162*)(ol + g1) = e1;
    }
}

// ---------------- misc kernels ----------------
__device__ __forceinline__ float warpReduceSum(float v){
    #pragma unroll
    for (int o=16;o;o>>=1) v += __shfl_xor_sync(0xffffffffu, v, o);
    return v;
}
__device__ float blockReduceSum(float v){
    __shared__ float sh[33];
    int lane = threadIdx.x & 31, wid = threadIdx.x >> 5;
    __syncthreads();
    v = warpReduceSum(v);
    if (lane==0) sh[wid] = v;
    __syncthreads();
    int nw = blockDim.x >> 5;
    float r = (threadIdx.x < nw) ? sh[threadIdx.x] : 0.f;
    if (wid==0){ r = warpReduceSum(r); if (lane==0) sh[32] = r; }
    __syncthreads();
    return sh[32];
}

// convert fp32 -> bf16 hi/lo
__global__ void conv_hl(const float* __restrict__ in, bf16* __restrict__ ohh,
                        bf16* __restrict__ oll, long long n){
    long long i = ((long long)blockIdx.x*256 + threadIdx.x)*4;
    if (i >= n) return;
    float4 v = *(const float4*)(in + i);
    bf162 h01 = __floats2bfloat162_rn(v.x, v.y);
    bf162 h23 = __floats2bfloat162_rn(v.z, v.w);
    bf162 l01 = __floats2bfloat162_rn(v.x-__low2float(h01), v.y-__high2float(h01));
    bf162 l23 = __floats2bfloat162_rn(v.z-__low2float(h23), v.w-__high2float(h23));
    *(uint2*)(ohh + i) = make_uint2(*(uint32_t*)&h01, *(uint32_t*)&h23);
    *(uint2*)(oll + i) = make_uint2(*(uint32_t*)&l01, *(uint32_t*)&l23);
}

// rmsnorm writing fp32 + bf16 hi/lo
__global__ void __launch_bounds__(256) rmsnorm_hl(const float* __restrict__ x,
        const float* __restrict__ w, float* __restrict__ outf,
        bf16* __restrict__ ohh, bf16* __restrict__ oll){
    long long row = blockIdx.x;
    float4 xv = ((const float4*)(x + row*DIMM))[threadIdx.x];
    float ss = xv.x*xv.x + xv.y*xv.y + xv.z*xv.z + xv.w*xv.w;
    float tot = blockReduceSum(ss);
    float scale = rsqrtf(tot * (1.0f/DIMM) + 1e-5f);
    float4 wv = ((const float4*)w)[threadIdx.x];
    float4 o;
    o.x = xv.x*scale*wv.x; o.y = xv.y*scale*wv.y;
    o.z = xv.z*scale*wv.z; o.w = xv.w*scale*wv.w;
    long long i = row*DIMM + threadIdx.x*4;
    if (outf) *(float4*)(outf + i) = o;
    bf162 h01 = __floats2bfloat162_rn(o.x, o.y);
    bf162 h23 = __floats2bfloat162_rn(o.z, o.w);
    bf162 l01 = __floats2bfloat162_rn(o.x-__low2float(h01), o.y-__high2float(h01));
    bf162 l23 = __floats2bfloat162_rn(o.z-__low2float(h23), o.w-__high2float(h23));
    *(uint2*)(ohh + i) = make_uint2(*(uint32_t*)&h01, *(uint32_t*)&h23);
    *(uint2*)(oll + i) = make_uint2(*(uint32_t*)&l01, *(uint32_t*)&l23);
}

// RoPE: fp32 q,k -> bf16 hi/lo
__global__ void rope_hl(const float* __restrict__ q, const float* __restrict__ k,
                        bf16* __restrict__ qhh, bf16* __restrict__ qll,
                        bf16* __restrict__ khh, bf16* __restrict__ kll){
    int idx = blockIdx.x*blockDim.x + threadIdx.x;
    if (idx >= NTOK*NHEADS*(HD/2)) return;
    int j = idx & 31;
    int h = (idx >> 5) & 15;
    int t = idx >> 9;
    int l = t & (LL-1);
    long long base = (long long)t*DIMM + h*HD;
    float inv = powf(10000.f, -(float)j * (1.f/32.f));
    float ang = (float)l * inv;
    float sn, cs; sincosf(ang, &sn, &cs);
    float a = q[base+j], b = q[base+32+j];
    float r0 = a*cs - b*sn, r1 = a*sn + b*cs;
    bf16 h0 = __float2bfloat16(r0); qhh[base+j] = h0;    qll[base+j]    = __float2bfloat16(r0-__bfloat162float(h0));
    bf16 h1 = __float2bfloat16(r1); qhh[base+32+j] = h1; qll[base+32+j] = __float2bfloat16(r1-__bfloat162float(h1));
    a = k[base+j]; b = k[base+32+j];
    r0 = a*cs - b*sn; r1 = a*sn + b*cs;
    h0 = __float2bfloat16(r0); khh[base+j] = h0;    kll[base+j]    = __float2bfloat16(r0-__bfloat162float(h0));
    h1 = __float2bfloat16(r1); khh[base+32+j] = h1; kll[base+32+j] = __float2bfloat16(r1-__bfloat162float(h1));
}

// silu(a)*b -> bf16 hi/lo
__global__ void silumul_hl(const float* __restrict__ ta, const float* __restrict__ tbv,
                           bf16* __restrict__ ohh, bf16* __restrict__ oll, long long n){
    long long i = ((long long)blockIdx.x*256 + threadIdx.x)*4;
    if (i >= n) return;
    float4 a = *(const float4*)(ta + i);
    float4 b = *(const float4*)(tbv + i);
    float4 o;
    o.x = a.x/(1.f+expf(-a.x))*b.x;
    o.y = a.y/(1.f+expf(-a.y))*b.y;
    o.z = a.z/(1.f+expf(-a.z))*b.z;
    o.w = a.w/(1.f+expf(-a.w))*b.w;
    bf162 h01 = __floats2bfloat162_rn(o.x, o.y);
    bf162 h23 = __floats2bfloat162_rn(o.z, o.w);
    bf162 l01 = __floats2bfloat162_rn(o.x-__low2float(h01), o.y-__high2float(h01));
    bf162 l23 = __floats2bfloat162_rn(o.z-__low2float(h23), o.w-__high2float(h23));
    *(uint2*)(ohh + i) = make_uint2(*(uint32_t*)&h01, *(uint32_t*)&h23);
    *(uint2*)(oll + i) = make_uint2(*(uint32_t*)&l01, *(uint32_t*)&l23);
}

__global__ void __launch_bounds__(256) gate_topk(const float* __restrict__ xf,
                                                 const float* __restrict__ gw,
                                                 int* __restrict__ topi, float* __restrict__ topw,
                                                 int* __restrict__ counts){
    int t = blockIdx.x;
    int tid = threadIdx.x;
    float4 xv = ((const float4*)(xf + (long long)t*DIMM))[tid];
    float acc[16];
    #pragma unroll
    for (int e = 0; e < 16; e++){
        float4 g = ((const float4*)(gw + (long long)e*DIMM))[tid];
        acc[e] = xv.x*g.x + xv.y*g.y + xv.z*g.z + xv.w*g.w;
    }
    #pragma unroll
    for (int e = 0; e < 16; e++) acc[e] = warpReduceSum(acc[e]);
    __shared__ float wr[8][16];
    __shared__ float lg[16];
    int lane = tid & 31, wid = tid >> 5;
    if (lane == 0){
        #pragma unroll
        for (int e = 0; e < 16; e++) wr[wid][e] = acc[e];
    }
    __syncthreads();
    if (tid < 16){
        float s = 0.f;
        #pragma unroll
        for (int w = 0; w < 8; w++) s += wr[w][tid];
        lg[tid] = s;
    }
    __syncthreads();
    if (tid == 0){
        float l0 = -3.0e38f; int i0 = 0;
        for (int e = 0; e < 16; e++) if (lg[e] > l0){ l0 = lg[e]; i0 = e; }
        float l1 = -3.0e38f; int i1 = 0;
        for (int e = 0; e < 16; e++) if (e != i0 && lg[e] > l1){ l1 = lg[e]; i1 = e; }
        float w1 = expf(l1 - l0);
        float sden = 1.f + w1;
        topi[2*t] = i0; topi[2*t+1] = i1;
        topw[2*t] = 1.f / sden; topw[2*t+1] = w1 / sden;
        atomicAdd(&counts[i0], 1);
        atomicAdd(&counts[i1], 1);
    }
}

__global__ void zero_counts(int* counts){
    if (threadIdx.x < NE) counts[threadIdx.x] = 0;
}
__global__ void scan_kernel(const int* __restrict__ counts, int* __restrict__ offs,
                            int* __restrict__ cursor){
    if (threadIdx.x == 0){
        int s = 0;
        for (int e = 0; e < NE; e++){ offs[e] = s; s += counts[e]; cursor[e] = 0; }
    }
}
__global__ void scatter_kernel(const int* __restrict__ topi, int* __restrict__ cursor,
                               const int* __restrict__ offs, int* __restrict__ order,
                               int* __restrict__ tokslot){
    int t = blockIdx.x*blockDim.x + threadIdx.x;
    if (t >= NTOK) return;
    #pragma unroll
    for (int k2 = 0; k2 < 2; k2++){
        int e = topi[2*t+k2];
        int pos = atomicAdd(&cursor[e], 1);
        int slot = offs[e] + pos;
        order[slot] = t;
        tokslot[2*t+k2] = slot;
    }
}
__global__ void final_kernel(const float* __restrict__ h, const float* __restrict__ moe,
                             const float* __restrict__ y, const int* __restrict__ tokslot,
                             const float* __restrict__ topw, float* __restrict__ out){
    long long idx = (long long)blockIdx.x*blockDim.x + threadIdx.x;
    if (idx >= (long long)NTOK*DIMM) return;
    int t = (int)(idx >> 10);
    int i = (int)(idx & 1023);
    int s0 = tokslot[2*t], s1 = tokslot[2*t+1];
    float w0 = topw[2*t], w1 = topw[2*t+1];
    out[idx] = h[idx] + moe[idx] + w0*y[(long long)s0*DIMM + i] + w1*y[(long long)s1*DIMM + i];
}

// ---------------- host launcher ----------------
extern "C" void kernel_launch(void* const* d_in, const int* in_sizes, int n_in,
                              void* d_out, int out_size){
    const float* x    = (const float*)d_in[0];
    const float* mask = (const float*)d_in[1];
    const float* wq   = (const float*)d_in[2];
    const float* wk   = (const float*)d_in[3];
    const float* wv   = (const float*)d_in[4];
    const float* wo   = (const float*)d_in[5];
    const float* n1   = (const float*)d_in[6];
    const float* n2   = (const float*)d_in[7];
    const float* gw   = (const float*)d_in[8];
    const float* fc1  = (const float*)d_in[9];
    const float* fc2  = (const float*)d_in[10];
    const float* s1   = (const float*)d_in[11];
    const float* s2   = (const float*)d_in[12];
    const float* s3   = (const float*)d_in[13];
    float* out = (float*)d_out;

    void *p;
    cudaGetSymbolAddress(&p, g_q);      float* q      = (float*)p;
    cudaGetSymbolAddress(&p, g_k);      float* k      = (float*)p;
    cudaGetSymbolAddress(&p, g_v);      float* v      = (float*)p;
    cudaGetSymbolAddress(&p, g_h);      float* hbuf   = (float*)p;
    cudaGetSymbolAddress(&p, g_xf);     float* xf     = (float*)p;
    cudaGetSymbolAddress(&p, g_ta);     float* ta     = (float*)p;
    cudaGetSymbolAddress(&p, g_tb);     float* tb     = (float*)p;
    cudaGetSymbolAddress(&p, g_moe);    float* moe    = (float*)p;
    cudaGetSymbolAddress(&p, g_hexp);   float* hexp   = (float*)p;
    cudaGetSymbolAddress(&p, g_yexp);   float* yexp   = (float*)p;
    cudaGetSymbolAddress(&p, g_hnh);    bf16* hnh = (bf16*)p;
    cudaGetSymbolAddress(&p, g_hnl);    bf16* hnl = (bf16*)p;
    cudaGetSymbolAddress(&p, g_wh);     bf16* wh  = (bf16*)p;
    cudaGetSymbolAddress(&p, g_wl);     bf16* wl  = (bf16*)p;
    cudaGetSymbolAddress(&p, g_qh);     bf16* qhp = (bf16*)p;
    cudaGetSymbolAddress(&p, g_ql);     bf16* qlp = (bf16*)p;
    cudaGetSymbolAddress(&p, g_kh);     bf16* khp = (bf16*)p;
    cudaGetSymbolAddress(&p, g_kl);     bf16* klp = (bf16*)p;
    cudaGetSymbolAddress(&p, g_vh);     bf16* vhp = (bf16*)p;
    cudaGetSymbolAddress(&p, g_vl);     bf16* vlp = (bf16*)p;
    cudaGetSymbolAddress(&p, g_ah);     bf16* ahp = (bf16*)p;
    cudaGetSymbolAddress(&p, g_al);     bf16* alp = (bf16*)p;
    cudaGetSymbolAddress(&p, g_xh);     bf16* xhp = (bf16*)p;
    cudaGetSymbolAddress(&p, g_xl);     bf16* xlp = (bf16*)p;
    cudaGetSymbolAddress(&p, g_tah);    bf16* tahp= (bf16*)p;
    cudaGetSymbolAddress(&p, g_tal);    bf16* talp= (bf16*)p;
    cudaGetSymbolAddress(&p, g_eh);     bf16* ehp = (bf16*)p;
    cudaGetSymbolAddress(&p, g_el);     bf16* elp = (bf16*)p;
    cudaGetSymbolAddress(&p, g_topi);   int*   topi   = (int*)p;
    cudaGetSymbolAddress(&p, g_topw);   float* topw   = (float*)p;
    cudaGetSymbolAddress(&p, g_counts); int*   counts = (int*)p;
    cudaGetSymbolAddress(&p, g_cursor); int*   cursor = (int*)p;
    cudaGetSymbolAddress(&p, g_offs);   int*   offs   = (int*)p;
    cudaGetSymbolAddress(&p, g_order);  int*   order  = (int*)p;
    cudaGetSymbolAddress(&p, g_tokslot);int*   tokslot= (int*)p;

    cudaFuncSetAttribute(mm_bf, cudaFuncAttributeMaxDynamicSharedMemorySize, MMBF_SMEM);
    cudaFuncSetAttribute(flash_attn, cudaFuncAttributeMaxDynamicSharedMemorySize, FLASH_SMEM);

    #define CONV(src, dh, dl, n) conv_hl<<<(int)((n)/1024), 256>>>(src, dh, dl, (long long)(n))

    // 1. rmsnorm1 -> hn hi/lo (fp32 dumped to tb, unused)
    rmsnorm_hl<<<NTOK, 256>>>(x, n1, nullptr, hnh, hnl);
    // 2. QKV
    CONV(wq, wh, wl, DIMM*DIMM);
    mm_bf<<<dim3(8,32,1),256,MMBF_SMEM>>>(hnh, hnl, wh, wl, q, nullptr, NTOK, DIMM, DIMM, DIMM, DIMM, DIMM, 0, nullptr, nullptr, nullptr, 0);
    CONV(wk, wh, wl, DIMM*DIMM);
    mm_bf<<<dim3(8,32,1),256,MMBF_SMEM>>>(hnh, hnl, wh, wl, k, nullptr, NTOK, DIMM, DIMM, DIMM, DIMM, DIMM, 0, nullptr, nullptr, nullptr, 0);
    CONV(wv, wh, wl, DIMM*DIMM);
    mm_bf<<<dim3(8,32,1),256,MMBF_SMEM>>>(hnh, hnl, wh, wl, v, nullptr, NTOK, DIMM, DIMM, DIMM, DIMM, DIMM, 0, nullptr, nullptr, nullptr, 0);
    // 3. RoPE -> bf16 hi/lo ; V convert
    rope_hl<<<(NTOK*NHEADS*32)/256, 256>>>(q, k, qhp, qlp, khp, klp);
    CONV(v, vhp, vlp, (long long)NTOK*DIMM);
    // 4. flash attention -> attn bf16 hi/lo
    flash_attn<<<dim3(8,64),256,FLASH_SMEM>>>(qhp, qlp, khp, klp, vhp, vlp, mask, ahp, alp);
    // 5. h = x + attn @ wo^T
    CONV(wo, wh, wl, DIMM*DIMM);
    mm_bf<<<dim3(8,32,1),256,MMBF_SMEM>>>(ahp, alp, wh, wl, hbuf, x, NTOK, DIMM, DIMM, DIMM, DIMM, DIMM, 1, nullptr, nullptr, nullptr, 0);
    // 6. rmsnorm2 -> xf fp32 + hi/lo
    rmsnorm_hl<<<NTOK, 256>>>(hbuf, n2, xf, xhp, xlp);
    // 7. shared expert
    CONV(s1, wh, wl, NSHARED*DIMM);
    mm_bf<<<dim3(16,32,1),256,MMBF_SMEM>>>(xhp, xlp, wh, wl, ta, nullptr, NTOK, NSHARED, DIMM, DIMM, DIMM, NSHARED, 0, nullptr, nullptr, nullptr, 0);
    CONV(s2, wh, wl, NSHARED*DIMM);
    mm_bf<<<dim3(16,32,1),256,MMBF_SMEM>>>(xhp, xlp, wh, wl, tb, nullptr, NTOK, NSHARED, DIMM, DIMM, DIMM, NSHARED, 0, nullptr, nullptr, nullptr, 0);
    silumul_hl<<<(NTOK*NSHARED)/1024, 256>>>(ta, tb, tahp, talp, (long long)NTOK*NSHARED);
    CONV(s3, wh, wl, DIMM*NSHARED);
    mm_bf<<<dim3(8,32,1),256,MMBF_SMEM>>>(tahp, talp, wh, wl, moe, nullptr, NTOK, DIMM, NSHARED, NSHARED, NSHARED, DIMM, 0, nullptr, nullptr, nullptr, 0);
    // 8. routing
    zero_counts<<<1,32>>>(counts);
    gate_topk<<<NTOK,256>>>(xf, gw, topi, topw, counts);
    scan_kernel<<<1,1>>>(counts, offs, cursor);
    scatter_kernel<<<NTOK/256,256>>>(topi, cursor, offs, order, tokslot);
    // 9. expert fc1 (gathered rows, silu)
    CONV(fc1, wh, wl, (long long)NE*HID*DIMM);
    mm_bf<<<dim3(4,64,NE),256,MMBF_SMEM>>>(xhp, xlp, wh, wl, hexp, nullptr, 0, HID, DIMM, DIMM, DIMM, HID, 2, counts, offs, order, (long long)HID*DIMM);
    CONV(hexp, ehp, elp, (long long)NSLOTS*HID);
    // 10. expert fc2
    CONV(fc2, wh, wl, (long long)NE*DIMM*HID);
    mm_bf<<<dim3(8,64,NE),256,MMBF_SMEM>>>(ehp, elp, wh, wl, yexp, nullptr, 0, DIMM, HID, HID, HID, DIMM, 0, counts, offs, nullptr, (long long)DIMM*HID);
    // 11. final
    final_kernel<<<(NTOK*DIMM)/256, 256>>>(hbuf, moe, yexp, tokslot, topw, out);
}

// round 5
// speedup vs baseline: 3.3283x; 1.3590x over previous
#include <cuda_runtime.h>
#include <cuda_fp16.h>
#include <math.h>
#include <stdint.h>

#define BB 4
#define LL 1024
#define DIMM 1024
#define NHEADS 16
#define HD 64
#define NTOK (BB*LL)
#define HID 512
#define NE 16
#define NSHARED 2048
#define NSLOTS (NTOK*2)

// ---------------- scratch ----------------
__device__ float g_qkv[NTOK*3*DIMM];          // merged q|k|v fp32
__device__ float g_h[NTOK*DIMM];
__device__ float g_xf[NTOK*DIMM];
__device__ float g_tacat[(long long)NTOK*2*NSHARED]; // merged s1|s2 outputs
__device__ float g_moe[NTOK*DIMM];            // h + shared-moe
__device__ float g_yexp[NSLOTS*DIMM];
// fp16 buffers
__device__ __half g_hnh[NTOK*DIMM], g_hnl[NTOK*DIMM];
__device__ __half g_wh[NE*HID*DIMM];          // weight scratch (single fp16), 8M halves
__device__ __half g_qh[NTOK*DIMM], g_ql[NTOK*DIMM];
__device__ __half g_kh[NTOK*DIMM];
__device__ __half g_vh[NTOK*DIMM];
__device__ __half g_ah[NTOK*DIMM], g_al[NTOK*DIMM];
__device__ __half g_xh[NTOK*DIMM], g_xl[NTOK*DIMM];
__device__ __half g_tah[NTOK*NSHARED], g_tal[NTOK*NSHARED];
__device__ __half g_eh[NSLOTS*HID], g_el[NSLOTS*HID];
// routing
__device__ int   g_topi[NSLOTS];
__device__ float g_topw[NSLOTS];
__device__ int   g_counts[NE];
__device__ int   g_cursor[NE];
__device__ int   g_offs[NE];
__device__ int   g_order[NSLOTS];
__device__ int   g_tokslot[NSLOTS];

__device__ __forceinline__ uint32_t smem_u32(const void* p){
    uint32_t a;
    asm("{ .reg .u64 t; cvta.to.shared.u64 t, %1; cvt.u32.u64 %0, t; }" : "=r"(a) : "l"(p));
    return a;
}

#define LDMX4(r0,r1,r2,r3,addr) \
    asm volatile("ldmatrix.sync.aligned.m8n8.x4.shared.b16 {%0,%1,%2,%3}, [%4];" \
        : "=r"(r0),"=r"(r1),"=r"(r2),"=r"(r3) : "r"(addr))
#define LDMX4T(r0,r1,r2,r3,addr) \
    asm volatile("ldmatrix.sync.aligned.m8n8.x4.trans.shared.b16 {%0,%1,%2,%3}, [%4];" \
        : "=r"(r0),"=r"(r1),"=r"(r2),"=r"(r3) : "r"(addr))

#define MMAH(c0,c1,c2,c3,a0,a1,a2,a3,b0,b1) \
    asm volatile("mma.sync.aligned.m16n8k16.row.col.f32.f16.f16.f32 " \
        "{%0,%1,%2,%3}, {%4,%5,%6,%7}, {%8,%9}, {%0,%1,%2,%3};" \
        : "+f"(c0),"+f"(c1),"+f"(c2),"+f"(c3) \
        : "r"(a0),"r"(a1),"r"(a2),"r"(a3), "r"(b0),"r"(b1))

#define CPASYNC(dst,src,sz) \
    asm volatile("cp.async.cg.shared.global [%0], [%1], 16, %2;" :: "r"(dst), "l"(src), "r"(sz))
#define CPCOMMIT() asm volatile("cp.async.commit_group;")
#define CPWAIT(n)  asm volatile("cp.async.wait_group %0;" :: "n"(n))

// ========== fp16 GEMM: C = (Ah+Al) * Bh^T ; A exact fp16 pair, B single fp16 ==========
// mode: 0 fp32 out, 1 fp32 += res, 3 silu -> fp16 pair (Cph/Cpl)
#define SSTR 40
#define STGB 10240           // bytes per array per stage (128*40*2)
#define STAGE_BYTES 30720    // 3 arrays
#define MM16_SMEM 61440

__global__ void __launch_bounds__(256) mm16(
    const __half* __restrict__ Ah, const __half* __restrict__ Al,
    const __half* __restrict__ Bh,
    float* __restrict__ C, const float* __restrict__ res,
    __half* __restrict__ Cph, __half* __restrict__ Cpl,
    int M, int N, int K, int lda, int ldb, int ldc, int mode,
    const int* __restrict__ counts, const int* __restrict__ offs,
    const int* __restrict__ rows, long long bStrideE)
{
    extern __shared__ __align__(16) char dsm[];
    __shared__ int rsrc[128];
    uint32_t ub = smem_u32(dsm);
    int tid = threadIdx.x, wid = tid >> 5, lane = tid & 31;
    int e = blockIdx.z;

    int Mloc = M, rowOff = 0;
    const __half* Bp = Bh;
    if (counts){ Mloc = counts[e]; rowOff = offs[e]; Bp = Bh + (long long)e*bStrideE; }
    int m0 = blockIdx.y * 128;
    if (m0 >= Mloc) return;
    int n0 = blockIdx.x * 128;

    for (int i = tid; i < 128; i += 256){
        int gr = m0 + i;
        rsrc[i] = (gr < Mloc) ? (rows ? rows[rowOff + gr] : (counts ? rowOff + gr : gr)) : -1;
    }
    __syncthreads();

    int lrow2 = tid >> 1, lhalf = (tid & 1) * 16;
    int asrc = rsrc[lrow2];
    int szA = (asrc >= 0) ? 16 : 0;
    const __half* agh = Ah + (long long)asrc*lda + lhalf;
    const __half* agl = Al + (long long)asrc*lda + lhalf;
    const __half* bgh = Bp + (long long)(n0 + lrow2)*ldb + lhalf;
    uint32_t dstoff = (uint32_t)(lrow2*SSTR + lhalf)*2;

#define MM16_ISSUE(stg, kc) do { \
    uint32_t d = ub + (stg)*STAGE_BYTES + dstoff; \
    int ko = (kc)*32; \
    CPASYNC(d,           agh + ko,     szA); CPASYNC(d+16,          agh + ko + 8, szA); \
    CPASYNC(d+STGB,      agl + ko,     szA); CPASYNC(d+STGB+16,     agl + ko + 8, szA); \
    CPASYNC(d+2*STGB,    bgh + ko,     16 ); CPASYNC(d+2*STGB+16,   bgh + ko + 8, 16 ); \
    CPCOMMIT(); } while(0)

    float acc[4][4][4];
    #pragma unroll
    for (int i=0;i<4;i++) for (int j=0;j<4;j++) for (int f=0;f<4;f++) acc[i][j][f]=0.f;

    int wm = (wid >> 2) * 64, wn = (wid & 3) * 32;
    int lrow = lane & 15, lsel = (lane >> 4) * 8;
    int nk = K >> 5;

    MM16_ISSUE(0, 0);
    for (int kc = 0; kc < nk; kc++){
        int cur = kc & 1;
        if (kc + 1 < nk){ MM16_ISSUE((kc+1)&1, kc+1); CPWAIT(1); }
        else            { CPWAIT(0); }
        __syncthreads();
        uint32_t uAh = ub + cur*STAGE_BYTES, uAl = uAh + STGB, uBh = uAh + 2*STGB;
        #pragma unroll
        for (int ks = 0; ks < 2; ks++){
            int kofs = ks*16 + lsel;
            uint32_t ah[4][4], al[4][4], bh[2][4];
            #pragma unroll
            for (int mt = 0; mt < 4; mt++){
                uint32_t ad = 2u*((wm + mt*16 + lrow)*SSTR + kofs);
                LDMX4(ah[mt][0],ah[mt][1],ah[mt][2],ah[mt][3], uAh + ad);
                LDMX4(al[mt][0],al[mt][1],al[mt][2],al[mt][3], uAl + ad);
            }
            #pragma unroll
            for (int j = 0; j < 2; j++){
                uint32_t bd = 2u*((wn + j*16 + lrow)*SSTR + kofs);
                LDMX4(bh[j][0],bh[j][1],bh[j][2],bh[j][3], uBh + bd);
            }
            #pragma unroll
            for (int mt = 0; mt < 4; mt++){
                #pragma unroll
                for (int j = 0; j < 2; j++){
                    float* c0 = acc[mt][2*j];
                    float* c1 = acc[mt][2*j+1];
                    MMAH(c0[0],c0[1],c0[2],c0[3], ah[mt][0],ah[mt][1],ah[mt][2],ah[mt][3], bh[j][0],bh[j][2]);
                    MMAH(c1[0],c1[1],c1[2],c1[3], ah[mt][0],ah[mt][1],ah[mt][2],ah[mt][3], bh[j][1],bh[j][3]);
                    MMAH(c0[0],c0[1],c0[2],c0[3], al[mt][0],al[mt][1],al[mt][2],al[mt][3], bh[j][0],bh[j][2]);
                    MMAH(c1[0],c1[1],c1[2],c1[3], al[mt][0],al[mt][1],al[mt][2],al[mt][3], bh[j][1],bh[j][3]);
                }
            }
        }
        __syncthreads();
    }

    int rbase = lane >> 2, cbase = (lane & 3) * 2;
    #pragma unroll
    for (int mt = 0; mt < 4; mt++){
        #pragma unroll
        for (int nt = 0; nt < 4; nt++){
            int gn = n0 + wn + nt*8 + cbase;
            #pragma unroll
            for (int half = 0; half < 2; half++){
                int gm = m0 + wm + mt*16 + rbase + half*8;
                if (gm >= Mloc) continue;
                float v0 = acc[mt][nt][2*half];
                float v1 = acc[mt][nt][2*half+1];
                long long ci = (long long)(rowOff + gm)*ldc + gn;
                if (mode == 1){
                    v0 += res[ci]; v1 += res[ci+1];
                    *(float2*)(C + ci) = make_float2(v0, v1);
                } else if (mode == 3){
                    v0 = v0 / (1.f + expf(-v0));
                    v1 = v1 / (1.f + expf(-v1));
                    __half2 h = __floats2half2_rn(v0, v1);
                    __half2 l = __floats2half2_rn(v0-__low2float(h), v1-__high2float(h));
                    *(__half2*)(Cph + ci) = h;
                    *(__half2*)(Cpl + ci) = l;
                } else {
                    *(float2*)(C + ci) = make_float2(v0, v1);
                }
            }
        }
    }
}

// ===================== fused flash attention (fp16: Q pair, K/V single) =====================
#define FSTR 72
#define FLASH_SMEM (4*128*FSTR*2)

__global__ void __launch_bounds__(256,1) flash_attn(
    const __half* __restrict__ qh, const __half* __restrict__ ql,
    const __half* __restrict__ kh, const __half* __restrict__ vh,
    const float* __restrict__ mask,
    __half* __restrict__ oh, __half* __restrict__ ol)
{
    extern __shared__ __align__(16) char fsm[];
    __half* sQh = (__half*)fsm;
    __half* sQl = sQh + 128*FSTR;
    __half* sKh = sQl + 128*FSTR;
    __half* sVh = sKh + 128*FSTR;

    int tid = threadIdx.x, wid = tid >> 5, lane = tid & 31;
    int bh_ = blockIdx.y, b = bh_ >> 4, h = bh_ & 15;
    int q0 = blockIdx.x * 128;
    long long tb = (long long)b * LL;
    int crow = tid >> 1, chalf = (tid & 1) * 32;

    { // Q pair tile
        long long g = (tb + q0 + crow)*DIMM + h*HD + chalf;
        uint4* d0 = (uint4*)&sQh[crow*FSTR + chalf];
        uint4* d1 = (uint4*)&sQl[crow*FSTR + chalf];
        const uint4* s0 = (const uint4*)(qh + g);
        const uint4* s1 = (const uint4*)(ql + g);
        #pragma unroll
        for (int i = 0; i < 4; i++){ d0[i] = s0[i]; d1[i] = s1[i]; }
    }
    __syncthreads();

    uint32_t uQh = smem_u32(sQh), uQl = smem_u32(sQl);
    uint32_t uKh = smem_u32(sKh), uVh = smem_u32(sVh);
    int lr = lane & 15, ls = (lane >> 4) * 8;

    uint32_t aqh[4][4], aql[4][4];
    #pragma unroll
    for (int kc = 0; kc < 4; kc++){
        uint32_t ad = 2u*((wid*16 + lr)*FSTR + kc*16 + ls);
        LDMX4(aqh[kc][0],aqh[kc][1],aqh[kc][2],aqh[kc][3], uQh + ad);
        LDMX4(aql[kc][0],aql[kc][1],aql[kc][2],aql[kc][3], uQl + ad);
    }

    float oacc[8][4];
    #pragma unroll
    for (int i=0;i<8;i++) for (int j=0;j<4;j++) oacc[i][j]=0.f;
    float m0r = -1e30f, m1r = -1e30f, l0r = 0.f, l1r = 0.f;

    const float* mp0 = mask + (long long)(q0 + wid*16 + (lane>>2))*LL;
    const float* mp1 = mp0 + 8*LL;
    const float SC  = 0.125f * 1.44269504f;
    const float L2E = 1.44269504f;

    for (int jt = 0; jt < 8; jt++){
        __syncthreads();
        { // K,V single tiles
            long long g = (tb + jt*128 + crow)*DIMM + h*HD + chalf;
            int so = crow*FSTR + chalf;
            const uint4 *k0 = (const uint4*)(kh+g);
            const uint4 *v0 = (const uint4*)(vh+g);
            uint4 *dk0 = (uint4*)&sKh[so];
            uint4 *dv0 = (uint4*)&sVh[so];
            #pragma unroll
            for (int i = 0; i < 4; i++){ dk0[i]=k0[i]; dv0[i]=v0[i]; }
        }
        __syncthreads();

        float s[16][4];
        #pragma unroll
        for (int i=0;i<16;i++) for (int j=0;j<4;j++) s[i][j]=0.f;

        #pragma unroll
        for (int kc = 0; kc < 4; kc++){
            #pragma unroll
            for (int np = 0; np < 8; np++){
                uint32_t bk[4];
                uint32_t ad = 2u*((np*16 + lr)*FSTR + kc*16 + ls);
                LDMX4(bk[0],bk[1],bk[2],bk[3], uKh + ad);
                float* c0 = s[2*np]; float* c1 = s[2*np+1];
                MMAH(c0[0],c0[1],c0[2],c0[3], aqh[kc][0],aqh[kc][1],aqh[kc][2],aqh[kc][3], bk[0],bk[2]);
                MMAH(c1[0],c1[1],c1[2],c1[3], aqh[kc][0],aqh[kc][1],aqh[kc][2],aqh[kc][3], bk[1],bk[3]);
                MMAH(c0[0],c0[1],c0[2],c0[3], aql[kc][0],aql[kc][1],aql[kc][2],aql[kc][3], bk[0],bk[2]);
                MMAH(c1[0],c1[1],c1[2],c1[3], aql[kc][0],aql[kc][1],aql[kc][2],aql[kc][3], bk[1],bk[3]);
            }
        }

        float mx0 = -1e30f, mx1 = -1e30f;
        #pragma unroll
        for (int nt = 0; nt < 16; nt++){
            int colb = jt*128 + nt*8 + (lane&3)*2;
            float2 mm0 = *(const float2*)(mp0 + colb);
            float2 mm1 = *(const float2*)(mp1 + colb);
            s[nt][0] = fmaf(s[nt][0], SC, mm0.x*L2E);
            s[nt][1] = fmaf(s[nt][1], SC, mm0.y*L2E);
            s[nt][2] = fmaf(s[nt][2], SC, mm1.x*L2E);
            s[nt][3] = fmaf(s[nt][3], SC, mm1.y*L2E);
            mx0 = fmaxf(mx0, fmaxf(s[nt][0], s[nt][1]));
            mx1 = fmaxf(mx1, fmaxf(s[nt][2], s[nt][3]));
        }
        mx0 = fmaxf(mx0, __shfl_xor_sync(0xffffffffu, mx0, 1));
        mx0 = fmaxf(mx0, __shfl_xor_sync(0xffffffffu, mx0, 2));
        mx1 = fmaxf(mx1, __shfl_xor_sync(0xffffffffu, mx1, 1));
        mx1 = fmaxf(mx1, __shfl_xor_sync(0xffffffffu, mx1, 2));

        float nm0 = fmaxf(m0r, mx0), nm1 = fmaxf(m1r, mx1);
        float al0 = exp2f(m0r - nm0), al1 = exp2f(m1r - nm1);
        m0r = nm0; m1r = nm1;

        float rs0 = 0.f, rs1 = 0.f;
        #pragma unroll
        for (int nt = 0; nt < 16; nt++){
            s[nt][0] = exp2f(s[nt][0] - nm0);
            s[nt][1] = exp2f(s[nt][1] - nm0);
            s[nt][2] = exp2f(s[nt][2] - nm1);
            s[nt][3] = exp2f(s[nt][3] - nm1);
            rs0 += s[nt][0] + s[nt][1];
            rs1 += s[nt][2] + s[nt][3];
        }
        rs0 += __shfl_xor_sync(0xffffffffu, rs0, 1);
        rs0 += __shfl_xor_sync(0xffffffffu, rs0, 2);
        rs1 += __shfl_xor_sync(0xffffffffu, rs1, 1);
        rs1 += __shfl_xor_sync(0xffffffffu, rs1, 2);
        l0r = l0r*al0 + rs0;
        l1r = l1r*al1 + rs1;
        #pragma unroll
        for (int dt = 0; dt < 8; dt++){
            oacc[dt][0] *= al0; oacc[dt][1] *= al0;
            oacc[dt][2] *= al1; oacc[dt][3] *= al1;
        }

        // PV: P exact fp16 pair from regs, V single via ldmatrix.trans
        #pragma unroll
        for (int kc2 = 0; kc2 < 8; kc2++){
            uint32_t pah[4], pal[4];
            {
                float c0 = s[2*kc2][0],  c1 = s[2*kc2][1];
                float c2 = s[2*kc2][2],  c3 = s[2*kc2][3];
                float d0 = s[2*kc2+1][0],d1 = s[2*kc2+1][1];
                float d2 = s[2*kc2+1][2],d3 = s[2*kc2+1][3];
                __half2 h0 = __floats2half2_rn(c0, c1);
                __half2 h1 = __floats2half2_rn(c2, c3);
                __half2 h2 = __floats2half2_rn(d0, d1);
                __half2 h3 = __floats2half2_rn(d2, d3);
                __half2 e0 = __floats2half2_rn(c0-__low2float(h0), c1-__high2float(h0));
                __half2 e1 = __floats2half2_rn(c2-__low2float(h1), c3-__high2float(h1));
                __half2 e2 = __floats2half2_rn(d0-__low2float(h2), d1-__high2float(h2));
                __half2 e3 = __floats2half2_rn(d2-__low2float(h3), d3-__high2float(h3));
                pah[0]=*(uint32_t*)&h0; pah[1]=*(uint32_t*)&h1; pah[2]=*(uint32_t*)&h2; pah[3]=*(uint32_t*)&h3;
                pal[0]=*(uint32_t*)&e0; pal[1]=*(uint32_t*)&e1; pal[2]=*(uint32_t*)&e2; pal[3]=*(uint32_t*)&e3;
            }
            #pragma unroll
            for (int dt = 0; dt < 4; dt++){
                uint32_t bv[4];
                uint32_t ad = 2u*((kc2*16 + lr)*FSTR + dt*16 + ls);
                LDMX4T(bv[0],bv[1],bv[2],bv[3], uVh + ad);
                float* o0 = oacc[2*dt]; float* o1 = oacc[2*dt+1];
                MMAH(o0[0],o0[1],o0[2],o0[3], pah[0],pah[1],pah[2],pah[3], bv[0],bv[1]);
                MMAH(o0[0],o0[1],o0[2],o0[3], pal[0],pal[1],pal[2],pal[3], bv[0],bv[1]);
                MMAH(o1[0],o1[1],o1[2],o1[3], pah[0],pah[1],pah[2],pah[3], bv[2],bv[3]);
                MMAH(o1[0],o1[1],o1[2],o1[3], pal[0],pal[1],pal[2],pal[3], bv[2],bv[3]);
            }
        }
    }

    float i0 = 1.f / l0r, i1 = 1.f / l1r;
    long long r0 = tb + q0 + wid*16 + (lane>>2);
    #pragma unroll
    for (int dt = 0; dt < 8; dt++){
        long long g0 = r0*DIMM + h*HD + dt*8 + (lane&3)*2;
        long long g1 = g0 + 8*DIMM;
        float v0 = oacc[dt][0]*i0, v1 = oacc[dt][1]*i0;
        float v2 = oacc[dt][2]*i1, v3 = oacc[dt][3]*i1;
        __half2 h0 = __floats2half2_rn(v0, v1);
        __half2 h1 = __floats2half2_rn(v2, v3);
        __half2 e0 = __floats2half2_rn(v0-__low2float(h0), v1-__high2float(h0));
        __half2 e1 = __floats2half2_rn(v2-__low2float(h1), v3-__high2float(h1));
        *(__half2*)(oh + g0) = h0;  *(__half2*)(ol + g0) = e0;
        *(__half2*)(oh + g1) = h1;  *(__half2*)(ol + g1) = e1;
    }
}

// ---------------- misc kernels ----------------
__device__ __forceinline__ float warpReduceSum(float v){
    #pragma unroll
    for (int o=16;o;o>>=1) v += __shfl_xor_sync(0xffffffffu, v, o);
    return v;
}
__device__ float blockReduceSum(float v){
    __shared__ float sh[33];
    int lane = threadIdx.x & 31, wid = threadIdx.x >> 5;
    __syncthreads();
    v = warpReduceSum(v);
    if (lane==0) sh[wid] = v;
    __syncthreads();
    int nw = blockDim.x >> 5;
    float r = (threadIdx.x < nw) ? sh[threadIdx.x] : 0.f;
    if (wid==0){ r = warpReduceSum(r); if (lane==0) sh[32] = r; }
    __syncthreads();
    return sh[32];
}

// fp32 -> single fp16 (8 elems/thread)
__global__ void conv1(const float* __restrict__ in, __half* __restrict__ o, long long n){
    long long i = ((long long)blockIdx.x*256 + threadIdx.x)*8;
    if (i >= n) return;
    float4 a = *(const float4*)(in + i);
    float4 b = *(const float4*)(in + i + 4);
    __half2 h0 = __floats2half2_rn(a.x, a.y);
    __half2 h1 = __floats2half2_rn(a.z, a.w);
    __half2 h2 = __floats2half2_rn(b.x, b.y);
    __half2 h3 = __floats2half2_rn(b.z, b.w);
    uint4 pk;
    pk.x = *(uint32_t*)&h0; pk.y = *(uint32_t*)&h1;
    pk.z = *(uint32_t*)&h2; pk.w = *(uint32_t*)&h3;
    *(uint4*)(o + i) = pk;
}

// strided V extract: qkv[t*3072 + 2048 + c] -> fp16 v[t*1024 + c]
__global__ void convV(const float* __restrict__ qkv, __half* __restrict__ o){
    long long i = ((long long)blockIdx.x*256 + threadIdx.x)*8;
    if (i >= (long long)NTOK*DIMM) return;
    int t = (int)(i >> 10), c = (int)(i & 1023);
    const float* src = qkv + (long long)t*3072 + 2048 + c;
    float4 a = *(const float4*)src;
    float4 b = *(const float4*)(src + 4);
    __half2 h0 = __floats2half2_rn(a.x, a.y);
    __half2 h1 = __floats2half2_rn(a.z, a.w);
    __half2 h2 = __floats2half2_rn(b.x, b.y);
    __half2 h3 = __floats2half2_rn(b.z, b.w);
    uint4 pk;
    pk.x = *(uint32_t*)&h0; pk.y = *(uint32_t*)&h1;
    pk.z = *(uint32_t*)&h2; pk.w = *(uint32_t*)&h3;
    *(uint4*)(o + i) = pk;
}

// rmsnorm -> optional fp32 + fp16 pair
__global__ void __launch_bounds__(256) rmsnorm_pair(const float* __restrict__ x,
        const float* __restrict__ w, float* __restrict__ outf,
        __half* __restrict__ ohh, __half* __restrict__ oll){
    long long row = blockIdx.x;
    float4 xv = ((const float4*)(x + row*DIMM))[threadIdx.x];
    float ss = xv.x*xv.x + xv.y*xv.y + xv.z*xv.z + xv.w*xv.w;
    float tot = blockReduceSum(ss);
    float scale = rsqrtf(tot * (1.0f/DIMM) + 1e-5f);
    float4 wv = ((const float4*)w)[threadIdx.x];
    float4 o;
    o.x = xv.x*scale*wv.x; o.y = xv.y*scale*wv.y;
    o.z = xv.z*scale*wv.z; o.w = xv.w*scale*wv.w;
    long long i = row*DIMM + threadIdx.x*4;
    if (outf) *(float4*)(outf + i) = o;
    __half2 h01 = __floats2half2_rn(o.x, o.y);
    __half2 h23 = __floats2half2_rn(o.z, o.w);
    __half2 l01 = __floats2half2_rn(o.x-__low2float(h01), o.y-__high2float(h01));
    __half2 l23 = __floats2half2_rn(o.z-__low2float(h23), o.w-__high2float(h23));
    *(uint2*)(ohh + i) = make_uint2(*(uint32_t*)&h01, *(uint32_t*)&h23);
    *(uint2*)(oll + i) = make_uint2(*(uint32_t*)&l01, *(uint32_t*)&l23);
}

// RoPE from merged qkv fp32: Q -> fp16 pair, K -> fp16 single
__global__ void rope16(const float* __restrict__ qkv,
                       __half* __restrict__ qhh, __half* __restrict__ qll,
                       __half* __restrict__ khh){
    int idx = blockIdx.x*blockDim.x + threadIdx.x;
    if (idx >= NTOK*NHEADS*(HD/2)) return;
    int j = idx & 31;
    int h = (idx >> 5) & 15;
    int t = idx >> 9;
    int l = t & (LL-1);
    long long bsrc = (long long)t*3072 + h*HD;
    long long bdst = (long long)t*DIMM + h*HD;
    float inv = powf(10000.f, -(float)j * (1.f/32.f));
    float ang = (float)l * inv;
    float sn, cs; sincosf(ang, &sn, &cs);
    float a = qkv[bsrc+j], b = qkv[bsrc+32+j];
    float r0 = a*cs - b*sn, r1 = a*sn + b*cs;
    __half h0 = __float2half_rn(r0);
    __half h1 = __float2half_rn(r1);
    qhh[bdst+j]    = h0; qll[bdst+j]    = __float2half_rn(r0-__half2float(h0));
    qhh[bdst+32+j] = h1; qll[bdst+32+j] = __float2half_rn(r1-__half2float(h1));
    a = qkv[bsrc+1024+j]; b = qkv[bsrc+1024+32+j];
    khh[bdst+j]    = __float2half_rn(a*cs - b*sn);
    khh[bdst+32+j] = __float2half_rn(a*sn + b*cs);
}

// silu(a)*b from merged tacat -> fp16 pair
__global__ void silumul16(const float* __restrict__ tacat,
                          __half* __restrict__ ohh, __half* __restrict__ oll){
    long long i = ((long long)blockIdx.x*256 + threadIdx.x)*4;
    if (i >= (long long)NTOK*NSHARED) return;
    int t = (int)(i >> 11), c = (int)(i & 2047);
    const float* rowp = tacat + (long long)t*4096;
    float4 a = *(const float4*)(rowp + c);
    float4 b = *(const float4*)(rowp + 2048 + c);
    float4 o;
    o.x = a.x/(1.f+expf(-a.x))*b.x;
    o.y = a.y/(1.f+expf(-a.y))*b.y;
    o.z = a.z/(1.f+expf(-a.z))*b.z;
    o.w = a.w/(1.f+expf(-a.w))*b.w;
    __half2 h01 = __floats2half2_rn(o.x, o.y);
    __half2 h23 = __floats2half2_rn(o.z, o.w);
    __half2 l01 = __floats2half2_rn(o.x-__low2float(h01), o.y-__high2float(h01));
    __half2 l23 = __floats2half2_rn(o.z-__low2float(h23), o.w-__high2float(h23));
    *(uint2*)(ohh + i) = make_uint2(*(uint32_t*)&h01, *(uint32_t*)&h23);
    *(uint2*)(oll + i) = make_uint2(*(uint32_t*)&l01, *(uint32_t*)&l23);
}

__global__ void __launch_bounds__(256) gate_topk(const float* __restrict__ xf,
                                                 const float* __restrict__ gw,
                                                 int* __restrict__ topi, float* __restrict__ topw,
                                                 int* __restrict__ counts){
    int t = blockIdx.x;
    int tid = threadIdx.x;
    float4 xv = ((const float4*)(xf + (long long)t*DIMM))[tid];
    float acc[16];
    #pragma unroll
    for (int e = 0; e < 16; e++){
        float4 g = ((const float4*)(gw + (long long)e*DIMM))[tid];
        acc[e] = xv.x*g.x + xv.y*g.y + xv.z*g.z + xv.w*g.w;
    }
    #pragma unroll
    for (int e = 0; e < 16; e++) acc[e] = warpReduceSum(acc[e]);
    __shared__ float wr[8][16];
    __shared__ float lg[16];
    int lane = tid & 31, wid = tid >> 5;
    if (lane == 0){
        #pragma unroll
        for (int e = 0; e < 16; e++) wr[wid][e] = acc[e];
    }
    __syncthreads();
    if (tid < 16){
        float s = 0.f;
        #pragma unroll
        for (int w = 0; w < 8; w++) s += wr[w][tid];
        lg[tid] = s;
    }
    __syncthreads();
    if (tid == 0){
        float l0 = -3.0e38f; int i0 = 0;
        for (int e = 0; e < 16; e++) if (lg[e] > l0){ l0 = lg[e]; i0 = e; }
        float l1 = -3.0e38f; int i1 = 0;
        for (int e = 0; e < 16; e++) if (e != i0 && lg[e] > l1){ l1 = lg[e]; i1 = e; }
        float w1 = expf(l1 - l0);
        float sden = 1.f + w1;
        topi[2*t] = i0; topi[2*t+1] = i1;
        topw[2*t] = 1.f / sden; topw[2*t+1] = w1 / sden;
        atomicAdd(&counts[i0], 1);
        atomicAdd(&counts[i1], 1);
    }
}

__global__ void zero_counts(int* counts){
    if (threadIdx.x < NE) counts[threadIdx.x] = 0;
}
__global__ void scan_kernel(const int* __restrict__ counts, int* __restrict__ offs,
                            int* __restrict__ cursor){
    if (threadIdx.x == 0){
        int s = 0;
        for (int e = 0; e < NE; e++){ offs[e] = s; s += counts[e]; cursor[e] = 0; }
    }
}
__global__ void scatter_kernel(const int* __restrict__ topi, int* __restrict__ cursor,
                               const int* __restrict__ offs, int* __restrict__ order,
                               int* __restrict__ tokslot){
    int t = blockIdx.x*blockDim.x + threadIdx.x;
    if (t >= NTOK) return;
    #pragma unroll
    for (int k2 = 0; k2 < 2; k2++){
        int e = topi[2*t+k2];
        int pos = atomicAdd(&cursor[e], 1);
        int slot = offs[e] + pos;
        order[slot] = t;
        tokslot[2*t+k2] = slot;
    }
}
// out = (h+moe) + w0*y0 + w1*y1
__global__ void final_kernel(const float* __restrict__ hmoe,
                             const float* __restrict__ y, const int* __restrict__ tokslot,
                             const float* __restrict__ topw, float* __restrict__ out){
    long long idx = (long long)blockIdx.x*blockDim.x + threadIdx.x;
    if (idx >= (long long)NTOK*DIMM) return;
    int t = (int)(idx >> 10);
    int i = (int)(idx & 1023);
    int s0 = tokslot[2*t], s1 = tokslot[2*t+1];
    float w0 = topw[2*t], w1 = topw[2*t+1];
    out[idx] = hmoe[idx] + w0*y[(long long)s0*DIMM + i] + w1*y[(long long)s1*DIMM + i];
}

// ---------------- host launcher ----------------
extern "C" void kernel_launch(void* const* d_in, const int* in_sizes, int n_in,
                              void* d_out, int out_size){
    const float* x    = (const float*)d_in[0];
    const float* mask = (const float*)d_in[1];
    const float* wq   = (const float*)d_in[2];
    const float* wk   = (const float*)d_in[3];
    const float* wv   = (const float*)d_in[4];
    const float* wo   = (const float*)d_in[5];
    const float* n1   = (const float*)d_in[6];
    const float* n2   = (const float*)d_in[7];
    const float* gw   = (const float*)d_in[8];
    const float* fc1  = (const float*)d_in[9];
    const float* fc2  = (const float*)d_in[10];
    const float* s1   = (const float*)d_in[11];
    const float* s2   = (const float*)d_in[12];
    const float* s3   = (const float*)d_in[13];
    float* out = (float*)d_out;

    void *p;
    cudaGetSymbolAddress(&p, g_qkv);    float* qkv    = (float*)p;
    cudaGetSymbolAddress(&p, g_h);      float* hbuf   = (float*)p;
    cudaGetSymbolAddress(&p, g_xf);     float* xf     = (float*)p;
    cudaGetSymbolAddress(&p, g_tacat);  float* tacat  = (float*)p;
    cudaGetSymbolAddress(&p, g_moe);    float* moe    = (float*)p;
    cudaGetSymbolAddress(&p, g_yexp);   float* yexp   = (float*)p;
    cudaGetSymbolAddress(&p, g_hnh);    __half* hnh = (__half*)p;
    cudaGetSymbolAddress(&p, g_hnl);    __half* hnl = (__half*)p;
    cudaGetSymbolAddress(&p, g_wh);     __half* wh  = (__half*)p;
    cudaGetSymbolAddress(&p, g_qh);     __half* qhp = (__half*)p;
    cudaGetSymbolAddress(&p, g_ql);     __half* qlp = (__half*)p;
    cudaGetSymbolAddress(&p, g_kh);     __half* khp = (__half*)p;
    cudaGetSymbolAddress(&p, g_vh);     __half* vhp = (__half*)p;
    cudaGetSymbolAddress(&p, g_ah);     __half* ahp = (__half*)p;
    cudaGetSymbolAddress(&p, g_al);     __half* alp = (__half*)p;
    cudaGetSymbolAddress(&p, g_xh);     __half* xhp = (__half*)p;
    cudaGetSymbolAddress(&p, g_xl);     __half* xlp = (__half*)p;
    cudaGetSymbolAddress(&p, g_tah);    __half* tahp= (__half*)p;
    cudaGetSymbolAddress(&p, g_tal);    __half* talp= (__half*)p;
    cudaGetSymbolAddress(&p, g_eh);     __half* ehp = (__half*)p;
    cudaGetSymbolAddress(&p, g_el);     __half* elp = (__half*)p;
    cudaGetSymbolAddress(&p, g_topi);   int*   topi   = (int*)p;
    cudaGetSymbolAddress(&p, g_topw);   float* topw   = (float*)p;
    cudaGetSymbolAddress(&p, g_counts); int*   counts = (int*)p;
    cudaGetSymbolAddress(&p, g_cursor); int*   cursor = (int*)p;
    cudaGetSymbolAddress(&p, g_offs);   int*   offs   = (int*)p;
    cudaGetSymbolAddress(&p, g_order);  int*   order  = (int*)p;
    cudaGetSymbolAddress(&p, g_tokslot);int*   tokslot= (int*)p;

    cudaFuncSetAttribute(mm16, cudaFuncAttributeMaxDynamicSharedMemorySize, MM16_SMEM);
    cudaFuncSetAttribute(flash_attn, cudaFuncAttributeMaxDynamicSharedMemorySize, FLASH_SMEM);

    #define C1(src, dst, n) conv1<<<(int)((n)/2048), 256>>>(src, dst, (long long)(n))

    // 1. rmsnorm1 -> fp16 pair
    rmsnorm_pair<<<NTOK, 256>>>(x, n1, nullptr, hnh, hnl);
    // 2. merged QKV (weights stacked into wh)
    C1(wq, wh, DIMM*DIMM);
    C1(wk, wh + (long long)DIMM*DIMM, DIMM*DIMM);
    C1(wv, wh + 2ll*DIMM*DIMM, DIMM*DIMM);
    mm16<<<dim3(24,32,1),256,MM16_SMEM>>>(hnh, hnl, wh, qkv, nullptr, nullptr, nullptr,
        NTOK, 3*DIMM, DIMM, DIMM, DIMM, 3*DIMM, 0, nullptr, nullptr, nullptr, 0);
    // 3. RoPE (Q pair, K single) + V extract
    rope16<<<(NTOK*NHEADS*32)/256, 256>>>(qkv, qhp, qlp, khp);
    convV<<<(NTOK*DIMM)/2048, 256>>>(qkv, vhp);
    // 4. flash attention
    flash_attn<<<dim3(8,64),256,FLASH_SMEM>>>(qhp, qlp, khp, vhp, mask, ahp, alp);
    // 5. h = x + attn @ wo^T
    C1(wo, wh, DIMM*DIMM);
    mm16<<<dim3(8,32,1),256,MM16_SMEM>>>(ahp, alp, wh, hbuf, x, nullptr, nullptr,
        NTOK, DIMM, DIMM, DIMM, DIMM, DIMM, 1, nullptr, nullptr, nullptr, 0);
    // 6. rmsnorm2 -> xf fp32 + pair
    rmsnorm_pair<<<NTOK, 256>>>(hbuf, n2, xf, xhp, xlp);
    // 7. merged shared fc1|fc2 -> tacat
    C1(s1, wh, NSHARED*DIMM);
    C1(s2, wh + (long long)NSHARED*DIMM, NSHARED*DIMM);
    mm16<<<dim3(32,32,1),256,MM16_SMEM>>>(xhp, xlp, wh, tacat, nullptr, nullptr, nullptr,
        NTOK, 2*NSHARED, DIMM, DIMM, DIMM, 2*NSHARED, 0, nullptr, nullptr, nullptr, 0);
    silumul16<<<(NTOK*NSHARED)/1024, 256>>>(tacat, tahp, talp);
    // 8. moe = h + silu_out @ s3^T
    C1(s3, wh, (long long)DIMM*NSHARED);
    mm16<<<dim3(8,32,1),256,MM16_SMEM>>>(tahp, talp, wh, moe, hbuf, nullptr, nullptr,
        NTOK, DIMM, NSHARED, NSHARED, NSHARED, DIMM, 1, nullptr, nullptr, nullptr, 0);
    // 9. routing
    zero_counts<<<1,32>>>(counts);
    gate_topk<<<NTOK,256>>>(xf, gw, topi, topw, counts);
    scan_kernel<<<1,1>>>(counts, offs, cursor);
    scatter_kernel<<<NTOK/256,256>>>(topi, cursor, offs, order, tokslot);
    // 10. expert fc1 (gather + silu -> fp16 pair)
    C1(fc1, wh, (long long)NE*HID*DIMM);
    mm16<<<dim3(4,64,NE),256,MM16_SMEM>>>(xhp, xlp, wh, nullptr, nullptr, ehp, elp,
        0, HID, DIMM, DIMM, DIMM, HID, 3, counts, offs, order, (long long)HID*DIMM);
    // 11. expert fc2
    C1(fc2, wh, (long long)NE*DIMM*HID);
    mm16<<<dim3(8,64,NE),256,MM16_SMEM>>>(ehp, elp, wh, yexp, nullptr, nullptr, nullptr,
        0, DIMM, HID, HID, HID, DIMM, 0, counts, offs, nullptr, (long long)DIMM*HID);
    // 12. final
    final_kernel<<<(NTOK*DIMM)/256, 256>>>(moe, yexp, tokslot, topw, out);
}

// round 6
// speedup vs baseline: 4.9197x; 1.4782x over previous
#include <cuda_runtime.h>
#include <cuda_fp16.h>
#include <math.h>
#include <stdint.h>

#define BB 4
#define LL 1024
#define DIMM 1024
#define NHEADS 16
#define HD 64
#define NTOK (BB*LL)
#define HID 512
#define NE 16
#define NSHARED 2048
#define NSLOTS (NTOK*2)

// ---------------- scratch ----------------
__device__ float g_qkv[NTOK*3*DIMM];
__device__ float g_h[NTOK*DIMM];
__device__ float g_xf[NTOK*DIMM];
__device__ float g_tacat[(long long)NTOK*2*NSHARED];
__device__ float g_moe[NTOK*DIMM];
__device__ float g_yexp[NSLOTS*DIMM];
// fp16 buffers (single precision level now)
__device__ __half g_hn16[NTOK*DIMM];
__device__ __half g_wh[NE*HID*DIMM];
__device__ __half g_q16[NTOK*DIMM];
__device__ __half g_k16[NTOK*DIMM];
__device__ __half g_v16[NTOK*DIMM];
__device__ __half g_a16[NTOK*DIMM];
__device__ __half g_x16[NTOK*DIMM];
__device__ __half g_ta16[NTOK*NSHARED];
__device__ __half g_e16[NSLOTS*HID];
// routing
__device__ int   g_topi[NSLOTS];
__device__ float g_topw[NSLOTS];
__device__ int   g_counts[NE];
__device__ int   g_cursor[NE];
__device__ int   g_offs[NE];
__device__ int   g_order[NSLOTS];
__device__ int   g_tokslot[NSLOTS];

__device__ __forceinline__ uint32_t smem_u32(const void* p){
    uint32_t a;
    asm("{ .reg .u64 t; cvta.to.shared.u64 t, %1; cvt.u32.u64 %0, t; }" : "=r"(a) : "l"(p));
    return a;
}

#define LDMX4(r0,r1,r2,r3,addr) \
    asm volatile("ldmatrix.sync.aligned.m8n8.x4.shared.b16 {%0,%1,%2,%3}, [%4];" \
        : "=r"(r0),"=r"(r1),"=r"(r2),"=r"(r3) : "r"(addr))
#define LDMX4T(r0,r1,r2,r3,addr) \
    asm volatile("ldmatrix.sync.aligned.m8n8.x4.trans.shared.b16 {%0,%1,%2,%3}, [%4];" \
        : "=r"(r0),"=r"(r1),"=r"(r2),"=r"(r3) : "r"(addr))

#define MMAH(c0,c1,c2,c3,a0,a1,a2,a3,b0,b1) \
    asm volatile("mma.sync.aligned.m16n8k16.row.col.f32.f16.f16.f32 " \
        "{%0,%1,%2,%3}, {%4,%5,%6,%7}, {%8,%9}, {%0,%1,%2,%3};" \
        : "+f"(c0),"+f"(c1),"+f"(c2),"+f"(c3) \
        : "r"(a0),"r"(a1),"r"(a2),"r"(a3), "r"(b0),"r"(b1))

#define CPASYNC(dst,src,sz) \
    asm volatile("cp.async.cg.shared.global [%0], [%1], 16, %2;" :: "r"(dst), "l"(src), "r"(sz))
#define CPCOMMIT() asm volatile("cp.async.commit_group;")
#define CPWAIT(n)  asm volatile("cp.async.wait_group %0;" :: "n"(n))

// ========== fp16 GEMM: C = A * B^T ; single fp16 operands, fp32 accum ==========
// mode: 0 fp32 out, 1 fp32 += res, 3 silu -> fp16 out
#define SSTR 40
#define STGB 10240           // bytes per array per stage (128*40*2)
#define STAGE_BYTES 20480    // 2 arrays (A,B)
#define MM16_SMEM 40960

__global__ void __launch_bounds__(256) mm16(
    const __half* __restrict__ Ah, const __half* __restrict__ Bh,
    float* __restrict__ C, const float* __restrict__ res,
    __half* __restrict__ Cp16,
    int M, int N, int K, int lda, int ldb, int ldc, int mode,
    const int* __restrict__ counts, const int* __restrict__ offs,
    const int* __restrict__ rows, long long bStrideE)
{
    extern __shared__ __align__(16) char dsm[];
    __shared__ int rsrc[128];
    uint32_t ub = smem_u32(dsm);
    int tid = threadIdx.x, wid = tid >> 5, lane = tid & 31;
    int e = blockIdx.z;

    int Mloc = M, rowOff = 0;
    const __half* Bp = Bh;
    if (counts){ Mloc = counts[e]; rowOff = offs[e]; Bp = Bh + (long long)e*bStrideE; }
    int m0 = blockIdx.y * 128;
    if (m0 >= Mloc) return;
    int n0 = blockIdx.x * 128;

    for (int i = tid; i < 128; i += 256){
        int gr = m0 + i;
        rsrc[i] = (gr < Mloc) ? (rows ? rows[rowOff + gr] : (counts ? rowOff + gr : gr)) : -1;
    }
    __syncthreads();

    int lrow2 = tid >> 1, lhalf = (tid & 1) * 16;
    int asrc = rsrc[lrow2];
    int szA = (asrc >= 0) ? 16 : 0;
    const __half* agh = Ah + (long long)asrc*lda + lhalf;
    const __half* bgh = Bp + (long long)(n0 + lrow2)*ldb + lhalf;
    uint32_t dstoff = (uint32_t)(lrow2*SSTR + lhalf)*2;

#define MM16_ISSUE(stg, kc) do { \
    uint32_t d = ub + (stg)*STAGE_BYTES + dstoff; \
    int ko = (kc)*32; \
    CPASYNC(d,        agh + ko,     szA); CPASYNC(d+16,       agh + ko + 8, szA); \
    CPASYNC(d+STGB,   bgh + ko,     16 ); CPASYNC(d+STGB+16,  bgh + ko + 8, 16 ); \
    CPCOMMIT(); } while(0)

    float acc[4][4][4];
    #pragma unroll
    for (int i=0;i<4;i++) for (int j=0;j<4;j++) for (int f=0;f<4;f++) acc[i][j][f]=0.f;

    int wm = (wid >> 2) * 64, wn = (wid & 3) * 32;
    int lrow = lane & 15, lsel = (lane >> 4) * 8;
    int nk = K >> 5;

    MM16_ISSUE(0, 0);
    for (int kc = 0; kc < nk; kc++){
        int cur = kc & 1;
        if (kc + 1 < nk){ MM16_ISSUE((kc+1)&1, kc+1); CPWAIT(1); }
        else            { CPWAIT(0); }
        __syncthreads();
        uint32_t uAh = ub + cur*STAGE_BYTES, uBh = uAh + STGB;
        #pragma unroll
        for (int ks = 0; ks < 2; ks++){
            int kofs = ks*16 + lsel;
            uint32_t ah[4][4], bh[2][4];
            #pragma unroll
            for (int mt = 0; mt < 4; mt++){
                uint32_t ad = 2u*((wm + mt*16 + lrow)*SSTR + kofs);
                LDMX4(ah[mt][0],ah[mt][1],ah[mt][2],ah[mt][3], uAh + ad);
            }
            #pragma unroll
            for (int j = 0; j < 2; j++){
                uint32_t bd = 2u*((wn + j*16 + lrow)*SSTR + kofs);
                LDMX4(bh[j][0],bh[j][1],bh[j][2],bh[j][3], uBh + bd);
            }
            #pragma unroll
            for (int mt = 0; mt < 4; mt++){
                #pragma unroll
                for (int j = 0; j < 2; j++){
                    float* c0 = acc[mt][2*j];
                    float* c1 = acc[mt][2*j+1];
                    MMAH(c0[0],c0[1],c0[2],c0[3], ah[mt][0],ah[mt][1],ah[mt][2],ah[mt][3], bh[j][0],bh[j][2]);
                    MMAH(c1[0],c1[1],c1[2],c1[3], ah[mt][0],ah[mt][1],ah[mt][2],ah[mt][3], bh[j][1],bh[j][3]);
                }
            }
        }
        __syncthreads();
    }

    int rbase = lane >> 2, cbase = (lane & 3) * 2;
    #pragma unroll
    for (int mt = 0; mt < 4; mt++){
        #pragma unroll
        for (int nt = 0; nt < 4; nt++){
            int gn = n0 + wn + nt*8 + cbase;
            #pragma unroll
            for (int half = 0; half < 2; half++){
                int gm = m0 + wm + mt*16 + rbase + half*8;
                if (gm >= Mloc) continue;
                float v0 = acc[mt][nt][2*half];
                float v1 = acc[mt][nt][2*half+1];
                long long ci = (long long)(rowOff + gm)*ldc + gn;
                if (mode == 1){
                    v0 += res[ci]; v1 += res[ci+1];
                    *(float2*)(C + ci) = make_float2(v0, v1);
                } else if (mode == 3){
                    v0 = v0 / (1.f + expf(-v0));
                    v1 = v1 / (1.f + expf(-v1));
                    *(__half2*)(Cp16 + ci) = __floats2half2_rn(v0, v1);
                } else {
                    *(float2*)(C + ci) = make_float2(v0, v1);
                }
            }
        }
    }
}

// ===================== fused flash attention (single fp16) =====================
#define FSTR 72
#define FLASH_SMEM (3*128*FSTR*2)

__global__ void __launch_bounds__(256,1) flash_attn(
    const __half* __restrict__ qh, const __half* __restrict__ kh,
    const __half* __restrict__ vh, const float* __restrict__ mask,
    __half* __restrict__ oh)
{
    extern __shared__ __align__(16) char fsm[];
    __half* sQ = (__half*)fsm;
    __half* sK = sQ + 128*FSTR;
    __half* sV = sK + 128*FSTR;

    int tid = threadIdx.x, wid = tid >> 5, lane = tid & 31;
    int bh_ = blockIdx.y, b = bh_ >> 4, h = bh_ & 15;
    int q0 = blockIdx.x * 128;
    long long tb = (long long)b * LL;
    int crow = tid >> 1, chalf = (tid & 1) * 32;

    { // Q tile
        long long g = (tb + q0 + crow)*DIMM + h*HD + chalf;
        uint4* d0 = (uint4*)&sQ[crow*FSTR + chalf];
        const uint4* s0 = (const uint4*)(qh + g);
        #pragma unroll
        for (int i = 0; i < 4; i++) d0[i] = s0[i];
    }
    __syncthreads();

    uint32_t uQ = smem_u32(sQ), uK = smem_u32(sK), uV = smem_u32(sV);
    int lr = lane & 15, ls = (lane >> 4) * 8;

    uint32_t aq[4][4];
    #pragma unroll
    for (int kc = 0; kc < 4; kc++){
        uint32_t ad = 2u*((wid*16 + lr)*FSTR + kc*16 + ls);
        LDMX4(aq[kc][0],aq[kc][1],aq[kc][2],aq[kc][3], uQ + ad);
    }

    float oacc[8][4];
    #pragma unroll
    for (int i=0;i<8;i++) for (int j=0;j<4;j++) oacc[i][j]=0.f;
    float m0r = -1e30f, m1r = -1e30f, l0r = 0.f, l1r = 0.f;

    const float* mp0 = mask + (long long)(q0 + wid*16 + (lane>>2))*LL;
    const float* mp1 = mp0 + 8*LL;
    const float SC  = 0.125f * 1.44269504f;
    const float L2E = 1.44269504f;

    for (int jt = 0; jt < 8; jt++){
        __syncthreads();
        {
            long long g = (tb + jt*128 + crow)*DIMM + h*HD + chalf;
            int so = crow*FSTR + chalf;
            const uint4 *k0 = (const uint4*)(kh+g);
            const uint4 *v0 = (const uint4*)(vh+g);
            uint4 *dk0 = (uint4*)&sK[so];
            uint4 *dv0 = (uint4*)&sV[so];
            #pragma unroll
            for (int i = 0; i < 4; i++){ dk0[i]=k0[i]; dv0[i]=v0[i]; }
        }
        __syncthreads();

        float s[16][4];
        #pragma unroll
        for (int i=0;i<16;i++) for (int j=0;j<4;j++) s[i][j]=0.f;

        #pragma unroll
        for (int kc = 0; kc < 4; kc++){
            #pragma unroll
            for (int np = 0; np < 8; np++){
                uint32_t bk[4];
                uint32_t ad = 2u*((np*16 + lr)*FSTR + kc*16 + ls);
                LDMX4(bk[0],bk[1],bk[2],bk[3], uK + ad);
                float* c0 = s[2*np]; float* c1 = s[2*np+1];
                MMAH(c0[0],c0[1],c0[2],c0[3], aq[kc][0],aq[kc][1],aq[kc][2],aq[kc][3], bk[0],bk[2]);
                MMAH(c1[0],c1[1],c1[2],c1[3], aq[kc][0],aq[kc][1],aq[kc][2],aq[kc][3], bk[1],bk[3]);
            }
        }

        float mx0 = -1e30f, mx1 = -1e30f;
        #pragma unroll
        for (int nt = 0; nt < 16; nt++){
            int colb = jt*128 + nt*8 + (lane&3)*2;
            float2 mm0 = *(const float2*)(mp0 + colb);
            float2 mm1 = *(const float2*)(mp1 + colb);
            s[nt][0] = fmaf(s[nt][0], SC, mm0.x*L2E);
            s[nt][1] = fmaf(s[nt][1], SC, mm0.y*L2E);
            s[nt][2] = fmaf(s[nt][2], SC, mm1.x*L2E);
            s[nt][3] = fmaf(s[nt][3], SC, mm1.y*L2E);
            mx0 = fmaxf(mx0, fmaxf(s[nt][0], s[nt][1]));
            mx1 = fmaxf(mx1, fmaxf(s[nt][2], s[nt][3]));
        }
        mx0 = fmaxf(mx0, __shfl_xor_sync(0xffffffffu, mx0, 1));
        mx0 = fmaxf(mx0, __shfl_xor_sync(0xffffffffu, mx0, 2));
        mx1 = fmaxf(mx1, __shfl_xor_sync(0xffffffffu, mx1, 1));
        mx1 = fmaxf(mx1, __shfl_xor_sync(0xffffffffu, mx1, 2));

        float nm0 = fmaxf(m0r, mx0), nm1 = fmaxf(m1r, mx1);
        float al0 = exp2f(m0r - nm0), al1 = exp2f(m1r - nm1);
        m0r = nm0; m1r = nm1;

        float rs0 = 0.f, rs1 = 0.f;
        #pragma unroll
        for (int nt = 0; nt < 16; nt++){
            s[nt][0] = exp2f(s[nt][0] - nm0);
            s[nt][1] = exp2f(s[nt][1] - nm0);
            s[nt][2] = exp2f(s[nt][2] - nm1);
            s[nt][3] = exp2f(s[nt][3] - nm1);
            rs0 += s[nt][0] + s[nt][1];
            rs1 += s[nt][2] + s[nt][3];
        }
        rs0 += __shfl_xor_sync(0xffffffffu, rs0, 1);
        rs0 += __shfl_xor_sync(0xffffffffu, rs0, 2);
        rs1 += __shfl_xor_sync(0xffffffffu, rs1, 1);
        rs1 += __shfl_xor_sync(0xffffffffu, rs1, 2);
        l0r = l0r*al0 + rs0;
        l1r = l1r*al1 + rs1;
        #pragma unroll
        for (int dt = 0; dt < 8; dt++){
            oacc[dt][0] *= al0; oacc[dt][1] *= al0;
            oacc[dt][2] *= al1; oacc[dt][3] *= al1;
        }

        #pragma unroll
        for (int kc2 = 0; kc2 < 8; kc2++){
            uint32_t pa[4];
            {
                __half2 h0 = __floats2half2_rn(s[2*kc2][0],   s[2*kc2][1]);
                __half2 h1 = __floats2half2_rn(s[2*kc2][2],   s[2*kc2][3]);
                __half2 h2 = __floats2half2_rn(s[2*kc2+1][0], s[2*kc2+1][1]);
                __half2 h3 = __floats2half2_rn(s[2*kc2+1][2], s[2*kc2+1][3]);
                pa[0]=*(uint32_t*)&h0; pa[1]=*(uint32_t*)&h1; pa[2]=*(uint32_t*)&h2; pa[3]=*(uint32_t*)&h3;
            }
            #pragma unroll
            for (int dt = 0; dt < 4; dt++){
                uint32_t bv[4];
                uint32_t ad = 2u*((kc2*16 + lr)*FSTR + dt*16 + ls);
                LDMX4T(bv[0],bv[1],bv[2],bv[3], uV + ad);
                float* o0 = oacc[2*dt]; float* o1 = oacc[2*dt+1];
                MMAH(o0[0],o0[1],o0[2],o0[3], pa[0],pa[1],pa[2],pa[3], bv[0],bv[1]);
                MMAH(o1[0],o1[1],o1[2],o1[3], pa[0],pa[1],pa[2],pa[3], bv[2],bv[3]);
            }
        }
    }

    float i0 = 1.f / l0r, i1 = 1.f / l1r;
    long long r0 = tb + q0 + wid*16 + (lane>>2);
    #pragma unroll
    for (int dt = 0; dt < 8; dt++){
        long long g0 = r0*DIMM + h*HD + dt*8 + (lane&3)*2;
        long long g1 = g0 + 8*DIMM;
        *(__half2*)(oh + g0) = __floats2half2_rn(oacc[dt][0]*i0, oacc[dt][1]*i0);
        *(__half2*)(oh + g1) = __floats2half2_rn(oacc[dt][2]*i1, oacc[dt][3]*i1);
    }
}

// ---------------- misc kernels ----------------
__device__ __forceinline__ float warpReduceSum(float v){
    #pragma unroll
    for (int o=16;o;o>>=1) v += __shfl_xor_sync(0xffffffffu, v, o);
    return v;
}
__device__ float blockReduceSum(float v){
    __shared__ float sh[33];
    int lane = threadIdx.x & 31, wid = threadIdx.x >> 5;
    __syncthreads();
    v = warpReduceSum(v);
    if (lane==0) sh[wid] = v;
    __syncthreads();
    int nw = blockDim.x >> 5;
    float r = (threadIdx.x < nw) ? sh[threadIdx.x] : 0.f;
    if (wid==0){ r = warpReduceSum(r); if (lane==0) sh[32] = r; }
    __syncthreads();
    return sh[32];
}

// fp32 -> fp16 (8 elems/thread)
__global__ void conv1(const float* __restrict__ in, __half* __restrict__ o, long long n){
    long long i = ((long long)blockIdx.x*256 + threadIdx.x)*8;
    if (i >= n) return;
    float4 a = *(const float4*)(in + i);
    float4 b = *(const float4*)(in + i + 4);
    __half2 h0 = __floats2half2_rn(a.x, a.y);
    __half2 h1 = __floats2half2_rn(a.z, a.w);
    __half2 h2 = __floats2half2_rn(b.x, b.y);
    __half2 h3 = __floats2half2_rn(b.z, b.w);
    uint4 pk;
    pk.x = *(uint32_t*)&h0; pk.y = *(uint32_t*)&h1;
    pk.z = *(uint32_t*)&h2; pk.w = *(uint32_t*)&h3;
    *(uint4*)(o + i) = pk;
}

// strided V extract: qkv[t*3072 + 2048 + c] -> fp16 v[t*1024 + c]
__global__ void convV(const float* __restrict__ qkv, __half* __restrict__ o){
    long long i = ((long long)blockIdx.x*256 + threadIdx.x)*8;
    if (i >= (long long)NTOK*DIMM) return;
    int t = (int)(i >> 10), c = (int)(i & 1023);
    const float* src = qkv + (long long)t*3072 + 2048 + c;
    float4 a = *(const float4*)src;
    float4 b = *(const float4*)(src + 4);
    __half2 h0 = __floats2half2_rn(a.x, a.y);
    __half2 h1 = __floats2half2_rn(a.z, a.w);
    __half2 h2 = __floats2half2_rn(b.x, b.y);
    __half2 h3 = __floats2half2_rn(b.z, b.w);
    uint4 pk;
    pk.x = *(uint32_t*)&h0; pk.y = *(uint32_t*)&h1;
    pk.z = *(uint32_t*)&h2; pk.w = *(uint32_t*)&h3;
    *(uint4*)(o + i) = pk;
}

// rmsnorm -> optional fp32 + fp16
__global__ void __launch_bounds__(256) rmsnorm16(const float* __restrict__ x,
        const float* __restrict__ w, float* __restrict__ outf,
        __half* __restrict__ o16){
    long long row = blockIdx.x;
    float4 xv = ((const float4*)(x + row*DIMM))[threadIdx.x];
    float ss = xv.x*xv.x + xv.y*xv.y + xv.z*xv.z + xv.w*xv.w;
    float tot = blockReduceSum(ss);
    float scale = rsqrtf(tot * (1.0f/DIMM) + 1e-5f);
    float4 wv = ((const float4*)w)[threadIdx.x];
    float4 o;
    o.x = xv.x*scale*wv.x; o.y = xv.y*scale*wv.y;
    o.z = xv.z*scale*wv.z; o.w = xv.w*scale*wv.w;
    long long i = row*DIMM + threadIdx.x*4;
    if (outf) *(float4*)(outf + i) = o;
    __half2 h01 = __floats2half2_rn(o.x, o.y);
    __half2 h23 = __floats2half2_rn(o.z, o.w);
    *(uint2*)(o16 + i) = make_uint2(*(uint32_t*)&h01, *(uint32_t*)&h23);
}

// RoPE from merged qkv fp32: Q,K -> fp16
__global__ void rope16(const float* __restrict__ qkv,
                       __half* __restrict__ q16, __half* __restrict__ k16){
    int idx = blockIdx.x*blockDim.x + threadIdx.x;
    if (idx >= NTOK*NHEADS*(HD/2)) return;
    int j = idx & 31;
    int h = (idx >> 5) & 15;
    int t = idx >> 9;
    int l = t & (LL-1);
    long long bsrc = (long long)t*3072 + h*HD;
    long long bdst = (long long)t*DIMM + h*HD;
    float inv = powf(10000.f, -(float)j * (1.f/32.f));
    float ang = (float)l * inv;
    float sn, cs; sincosf(ang, &sn, &cs);
    float a = qkv[bsrc+j], b = qkv[bsrc+32+j];
    q16[bdst+j]    = __float2half_rn(a*cs - b*sn);
    q16[bdst+32+j] = __float2half_rn(a*sn + b*cs);
    a = qkv[bsrc+1024+j]; b = qkv[bsrc+1024+32+j];
    k16[bdst+j]    = __float2half_rn(a*cs - b*sn);
    k16[bdst+32+j] = __float2half_rn(a*sn + b*cs);
}

// silu(a)*b from merged tacat -> fp16
__global__ void silumul16(const float* __restrict__ tacat, __half* __restrict__ o16){
    long long i = ((long long)blockIdx.x*256 + threadIdx.x)*4;
    if (i >= (long long)NTOK*NSHARED) return;
    int t = (int)(i >> 11), c = (int)(i & 2047);
    const float* rowp = tacat + (long long)t*4096;
    float4 a = *(const float4*)(rowp + c);
    float4 b = *(const float4*)(rowp + 2048 + c);
    float4 o;
    o.x = a.x/(1.f+expf(-a.x))*b.x;
    o.y = a.y/(1.f+expf(-a.y))*b.y;
    o.z = a.z/(1.f+expf(-a.z))*b.z;
    o.w = a.w/(1.f+expf(-a.w))*b.w;
    __half2 h01 = __floats2half2_rn(o.x, o.y);
    __half2 h23 = __floats2half2_rn(o.z, o.w);
    *(uint2*)(o16 + i) = make_uint2(*(uint32_t*)&h01, *(uint32_t*)&h23);
}

__global__ void __launch_bounds__(256) gate_topk(const float* __restrict__ xf,
                                                 const float* __restrict__ gw,
                                                 int* __restrict__ topi, float* __restrict__ topw,
                                                 int* __restrict__ counts){
    int t = blockIdx.x;
    int tid = threadIdx.x;
    float4 xv = ((const float4*)(xf + (long long)t*DIMM))[tid];
    float acc[16];
    #pragma unroll
    for (int e = 0; e < 16; e++){
        float4 g = ((const float4*)(gw + (long long)e*DIMM))[tid];
        acc[e] = xv.x*g.x + xv.y*g.y + xv.z*g.z + xv.w*g.w;
    }
    #pragma unroll
    for (int e = 0; e < 16; e++) acc[e] = warpReduceSum(acc[e]);
    __shared__ float wr[8][16];
    __shared__ float lg[16];
    int lane = tid & 31, wid = tid >> 5;
    if (lane == 0){
        #pragma unroll
        for (int e = 0; e < 16; e++) wr[wid][e] = acc[e];
    }
    __syncthreads();
    if (tid < 16){
        float s = 0.f;
        #pragma unroll
        for (int w = 0; w < 8; w++) s += wr[w][tid];
        lg[tid] = s;
    }
    __syncthreads();
    if (tid == 0){
        float l0 = -3.0e38f; int i0 = 0;
        for (int e = 0; e < 16; e++) if (lg[e] > l0){ l0 = lg[e]; i0 = e; }
        float l1 = -3.0e38f; int i1 = 0;
        for (int e = 0; e < 16; e++) if (e != i0 && lg[e] > l1){ l1 = lg[e]; i1 = e; }
        float w1 = expf(l1 - l0);
        float sden = 1.f + w1;
        topi[2*t] = i0; topi[2*t+1] = i1;
        topw[2*t] = 1.f / sden; topw[2*t+1] = w1 / sden;
        atomicAdd(&counts[i0], 1);
        atomicAdd(&counts[i1], 1);
    }
}

__global__ void zero_counts(int* counts){
    if (threadIdx.x < NE) counts[threadIdx.x] = 0;
}
__global__ void scan_kernel(const int* __restrict__ counts, int* __restrict__ offs,
                            int* __restrict__ cursor){
    if (threadIdx.x == 0){
        int s = 0;
        for (int e = 0; e < NE; e++){ offs[e] = s; s += counts[e]; cursor[e] = 0; }
    }
}
__global__ void scatter_kernel(const int* __restrict__ topi, int* __restrict__ cursor,
                               const int* __restrict__ offs, int* __restrict__ order,
                               int* __restrict__ tokslot){
    int t = blockIdx.x*blockDim.x + threadIdx.x;
    if (t >= NTOK) return;
    #pragma unroll
    for (int k2 = 0; k2 < 2; k2++){
        int e = topi[2*t+k2];
        int pos = atomicAdd(&cursor[e], 1);
        int slot = offs[e] + pos;
        order[slot] = t;
        tokslot[2*t+k2] = slot;
    }
}
__global__ void final_kernel(const float* __restrict__ hmoe,
                             const float* __restrict__ y, const int* __restrict__ tokslot,
                             const float* __restrict__ topw, float* __restrict__ out){
    long long idx = (long long)blockIdx.x*blockDim.x + threadIdx.x;
    if (idx >= (long long)NTOK*DIMM) return;
    int t = (int)(idx >> 10);
    int i = (int)(idx & 1023);
    int s0 = tokslot[2*t], s1 = tokslot[2*t+1];
    float w0 = topw[2*t], w1 = topw[2*t+1];
    out[idx] = hmoe[idx] + w0*y[(long long)s0*DIMM + i] + w1*y[(long long)s1*DIMM + i];
}

// ---------------- host launcher ----------------
extern "C" void kernel_launch(void* const* d_in, const int* in_sizes, int n_in,
                              void* d_out, int out_size){
    const float* x    = (const float*)d_in[0];
    const float* mask = (const float*)d_in[1];
    const float* wq   = (const float*)d_in[2];
    const float* wk   = (const float*)d_in[3];
    const float* wv   = (const float*)d_in[4];
    const float* wo   = (const float*)d_in[5];
    const float* n1   = (const float*)d_in[6];
    const float* n2   = (const float*)d_in[7];
    const float* gw   = (const float*)d_in[8];
    const float* fc1  = (const float*)d_in[9];
    const float* fc2  = (const float*)d_in[10];
    const float* s1   = (const float*)d_in[11];
    const float* s2   = (const float*)d_in[12];
    const float* s3   = (const float*)d_in[13];
    float* out = (float*)d_out;

    void *p;
    cudaGetSymbolAddress(&p, g_qkv);    float* qkv    = (float*)p;
    cudaGetSymbolAddress(&p, g_h);      float* hbuf   = (float*)p;
    cudaGetSymbolAddress(&p, g_xf);     float* xf     = (float*)p;
    cudaGetSymbolAddress(&p, g_tacat);  float* tacat  = (float*)p;
    cudaGetSymbolAddress(&p, g_moe);    float* moe    = (float*)p;
    cudaGetSymbolAddress(&p, g_yexp);   float* yexp   = (float*)p;
    cudaGetSymbolAddress(&p, g_hn16);   __half* hn16 = (__half*)p;
    cudaGetSymbolAddress(&p, g_wh);     __half* wh   = (__half*)p;
    cudaGetSymbolAddress(&p, g_q16);    __half* q16  = (__half*)p;
    cudaGetSymbolAddress(&p, g_k16);    __half* k16  = (__half*)p;
    cudaGetSymbolAddress(&p, g_v16);    __half* v16  = (__half*)p;
    cudaGetSymbolAddress(&p, g_a16);    __half* a16  = (__half*)p;
    cudaGetSymbolAddress(&p, g_x16);    __half* x16  = (__half*)p;
    cudaGetSymbolAddress(&p, g_ta16);   __half* ta16 = (__half*)p;
    cudaGetSymbolAddress(&p, g_e16);    __half* e16  = (__half*)p;
    cudaGetSymbolAddress(&p, g_topi);   int*   topi   = (int*)p;
    cudaGetSymbolAddress(&p, g_topw);   float* topw   = (float*)p;
    cudaGetSymbolAddress(&p, g_counts); int*   counts = (int*)p;
    cudaGetSymbolAddress(&p, g_cursor); int*   cursor = (int*)p;
    cudaGetSymbolAddress(&p, g_offs);   int*   offs   = (int*)p;
    cudaGetSymbolAddress(&p, g_order);  int*   order  = (int*)p;
    cudaGetSymbolAddress(&p, g_tokslot);int*   tokslot= (int*)p;

    cudaFuncSetAttribute(mm16, cudaFuncAttributeMaxDynamicSharedMemorySize, MM16_SMEM);
    cudaFuncSetAttribute(flash_attn, cudaFuncAttributeMaxDynamicSharedMemorySize, FLASH_SMEM);

    #define C1(src, dst, n) conv1<<<(int)((n)/2048), 256>>>(src, dst, (long long)(n))

    // 1. rmsnorm1 -> fp16
    rmsnorm16<<<NTOK, 256>>>(x, n1, nullptr, hn16);
    // 2. merged QKV
    C1(wq, wh, DIMM*DIMM);
    C1(wk, wh + (long long)DIMM*DIMM, DIMM*DIMM);
    C1(wv, wh + 2ll*DIMM*DIMM, DIMM*DIMM);
    mm16<<<dim3(24,32,1),256,MM16_SMEM>>>(hn16, wh, qkv, nullptr, nullptr,
        NTOK, 3*DIMM, DIMM, DIMM, DIMM, 3*DIMM, 0, nullptr, nullptr, nullptr, 0);
    // 3. RoPE + V extract
    rope16<<<(NTOK*NHEADS*32)/256, 256>>>(qkv, q16, k16);
    convV<<<(NTOK*DIMM)/2048, 256>>>(qkv, v16);
    // 4. flash attention
    flash_attn<<<dim3(8,64),256,FLASH_SMEM>>>(q16, k16, v16, mask, a16);
    // 5. h = x + attn @ wo^T
    C1(wo, wh, DIMM*DIMM);
    mm16<<<dim3(8,32,1),256,MM16_SMEM>>>(a16, wh, hbuf, x, nullptr,
        NTOK, DIMM, DIMM, DIMM, DIMM, DIMM, 1, nullptr, nullptr, nullptr, 0);
    // 6. rmsnorm2
    rmsnorm16<<<NTOK, 256>>>(hbuf, n2, xf, x16);
    // 7. merged shared fc1|fc2
    C1(s1, wh, NSHARED*DIMM);
    C1(s2, wh + (long long)NSHARED*DIMM, NSHARED*DIMM);
    mm16<<<dim3(32,32,1),256,MM16_SMEM>>>(x16, wh, tacat, nullptr, nullptr,
        NTOK, 2*NSHARED, DIMM, DIMM, DIMM, 2*NSHARED, 0, nullptr, nullptr, nullptr, 0);
    silumul16<<<(NTOK*NSHARED)/1024, 256>>>(tacat, ta16);
    // 8. moe = h + silu_out @ s3^T
    C1(s3, wh, (long long)DIMM*NSHARED);
    mm16<<<dim3(8,32,1),256,MM16_SMEM>>>(ta16, wh, moe, hbuf, nullptr,
        NTOK, DIMM, NSHARED, NSHARED, NSHARED, DIMM, 1, nullptr, nullptr, nullptr, 0);
    // 9. routing
    zero_counts<<<1,32>>>(counts);
    gate_topk<<<NTOK,256>>>(xf, gw, topi, topw, counts);
    scan_kernel<<<1,1>>>(counts, offs, cursor);
    scatter_kernel<<<NTOK/256,256>>>(topi, cursor, offs, order, tokslot);
    // 10. expert fc1 (gather + silu -> fp16)
    C1(fc1, wh, (long long)NE*HID*DIMM);
    mm16<<<dim3(4,64,NE),256,MM16_SMEM>>>(x16, wh, nullptr, nullptr, e16,
        0, HID, DIMM, DIMM, DIMM, HID, 3, counts, offs, order, (long long)HID*DIMM);
    // 11. expert fc2
    C1(fc2, wh, (long long)NE*DIMM*HID);
    mm16<<<dim3(8,64,NE),256,MM16_SMEM>>>(e16, wh, yexp, nullptr, nullptr,
        0, DIMM, HID, HID, HID, DIMM, 0, counts, offs, nullptr, (long long)DIMM*HID);
    // 12. final
    final_kernel<<<(NTOK*DIMM)/256, 256>>>(moe, yexp, tokslot, topw, out);
}

// round 7
// speedup vs baseline: 5.3858x; 1.0947x over previous
#include <cuda_runtime.h>
#include <cuda_fp16.h>
#include <math.h>
#include <stdint.h>

#define BB 4
#define LL 1024
#define DIMM 1024
#define NHEADS 16
#define HD 64
#define NTOK (BB*LL)
#define HID 512
#define NE 16
#define NSHARED 2048
#define NSLOTS (NTOK*2)

// ---------------- scratch ----------------
__device__ float g_qkv[NTOK*3*DIMM];
__device__ float g_h[NTOK*DIMM];
__device__ float g_xf[NTOK*DIMM];
__device__ float g_tacat[(long long)NTOK*2*NSHARED];
// fp16 buffers
#define WSEG 1048576ll
__device__ __half g_wh[26*WSEG];      // all weights fp16: qkv|wo|s1|s2|s3|fc1|fc2
__device__ __half g_hn16[NTOK*DIMM];
__device__ __half g_q16[NTOK*DIMM];
__device__ __half g_k16[NTOK*DIMM];
__device__ __half g_v16[NTOK*DIMM];
__device__ __half g_a16[NTOK*DIMM];
__device__ __half g_x16[NTOK*DIMM];
__device__ __half g_ta16[NTOK*NSHARED];
__device__ __half g_e16[NSLOTS*HID];
// routing
__device__ int   g_topi[NSLOTS];
__device__ float g_topw[NSLOTS];
__device__ int   g_counts[NE];
__device__ int   g_cursor[NE];
__device__ int   g_offs[NE];
__device__ int   g_order[NSLOTS];
__device__ float g_wslot[NSLOTS];

__device__ __forceinline__ uint32_t smem_u32(const void* p){
    uint32_t a;
    asm("{ .reg .u64 t; cvta.to.shared.u64 t, %1; cvt.u32.u64 %0, t; }" : "=r"(a) : "l"(p));
    return a;
}

#define LDMX4(r0,r1,r2,r3,addr) \
    asm volatile("ldmatrix.sync.aligned.m8n8.x4.shared.b16 {%0,%1,%2,%3}, [%4];" \
        : "=r"(r0),"=r"(r1),"=r"(r2),"=r"(r3) : "r"(addr))
#define LDMX4T(r0,r1,r2,r3,addr) \
    asm volatile("ldmatrix.sync.aligned.m8n8.x4.trans.shared.b16 {%0,%1,%2,%3}, [%4];" \
        : "=r"(r0),"=r"(r1),"=r"(r2),"=r"(r3) : "r"(addr))

#define MMAH(c0,c1,c2,c3,a0,a1,a2,a3,b0,b1) \
    asm volatile("mma.sync.aligned.m16n8k16.row.col.f32.f16.f16.f32 " \
        "{%0,%1,%2,%3}, {%4,%5,%6,%7}, {%8,%9}, {%0,%1,%2,%3};" \
        : "+f"(c0),"+f"(c1),"+f"(c2),"+f"(c3) \
        : "r"(a0),"r"(a1),"r"(a2),"r"(a3), "r"(b0),"r"(b1))

#define CPASYNC(dst,src,sz) \
    asm volatile("cp.async.cg.shared.global [%0], [%1], 16, %2;" :: "r"(dst), "l"(src), "r"(sz))
#define CPCOMMIT() asm volatile("cp.async.commit_group;")
#define CPWAIT(n)  asm volatile("cp.async.wait_group %0;" :: "n"(n))

// ========== fp16 GEMM: C = A * B^T ; 3-stage cp.async, single sync/iter ==========
// mode: 0 fp32 out, 1 fp32 += res, 3 silu -> fp16 out, 4 atomic MoE combine
#define SSTR 40
#define STGB 10240
#define STAGE_BYTES 20480
#define NSTAGE 3
#define MM16_SMEM (NSTAGE*STAGE_BYTES)

__global__ void __launch_bounds__(256) mm16(
    const __half* __restrict__ Ah, const __half* __restrict__ Bh,
    float* __restrict__ C, const float* __restrict__ res,
    __half* __restrict__ Cp16,
    int M, int N, int K, int lda, int ldb, int ldc, int mode,
    const int* __restrict__ counts, const int* __restrict__ offs,
    const int* __restrict__ rows,
    const int* __restrict__ omap, const float* __restrict__ wsl,
    long long bStrideE)
{
    extern __shared__ __align__(16) char dsm[];
    __shared__ int rsrc[128];
    uint32_t ub = smem_u32(dsm);
    int tid = threadIdx.x, wid = tid >> 5, lane = tid & 31;
    int e = blockIdx.z;

    int Mloc = M, rowOff = 0;
    const __half* Bp = Bh;
    if (counts){ Mloc = counts[e]; rowOff = offs[e]; Bp = Bh + (long long)e*bStrideE; }
    int m0 = blockIdx.y * 128;
    if (m0 >= Mloc) return;
    int n0 = blockIdx.x * 128;

    for (int i = tid; i < 128; i += 256){
        int gr = m0 + i;
        rsrc[i] = (gr < Mloc) ? (rows ? rows[rowOff + gr] : (counts ? rowOff + gr : gr)) : -1;
    }
    __syncthreads();

    int lrow2 = tid >> 1, lhalf = (tid & 1) * 16;
    int asrc = rsrc[lrow2];
    int szA = (asrc >= 0) ? 16 : 0;
    const __half* agh = Ah + (long long)asrc*lda + lhalf;
    const __half* bgh = Bp + (long long)(n0 + lrow2)*ldb + lhalf;
    uint32_t dstoff = (uint32_t)(lrow2*SSTR + lhalf)*2;

#define MM16_ISSUE(stg, kc) do { \
    uint32_t d = ub + (stg)*STAGE_BYTES + dstoff; \
    int ko = (kc)*32; \
    CPASYNC(d,        agh + ko,     szA); CPASYNC(d+16,       agh + ko + 8, szA); \
    CPASYNC(d+STGB,   bgh + ko,     16 ); CPASYNC(d+STGB+16,  bgh + ko + 8, 16 ); \
    CPCOMMIT(); } while(0)

    float acc[4][4][4];
    #pragma unroll
    for (int i=0;i<4;i++) for (int j=0;j<4;j++) for (int f=0;f<4;f++) acc[i][j][f]=0.f;

    int wm = (wid >> 2) * 64, wn = (wid & 3) * 32;
    int lrow = lane & 15, lsel = (lane >> 4) * 8;
    int nk = K >> 5;

    MM16_ISSUE(0, 0);
    if (nk > 1) MM16_ISSUE(1, 1);
    for (int kc = 0; kc < nk; kc++){
        if (kc + 1 < nk) CPWAIT(1); else CPWAIT(0);
        __syncthreads();
        int cur = kc % NSTAGE;
        uint32_t uAh = ub + cur*STAGE_BYTES, uBh = uAh + STGB;
        #pragma unroll
        for (int ks = 0; ks < 2; ks++){
            int kofs = ks*16 + lsel;
            uint32_t ah[4][4], bh[2][4];
            #pragma unroll
            for (int mt = 0; mt < 4; mt++){
                uint32_t ad = 2u*((wm + mt*16 + lrow)*SSTR + kofs);
                LDMX4(ah[mt][0],ah[mt][1],ah[mt][2],ah[mt][3], uAh + ad);
            }
            #pragma unroll
            for (int j = 0; j < 2; j++){
                uint32_t bd = 2u*((wn + j*16 + lrow)*SSTR + kofs);
                LDMX4(bh[j][0],bh[j][1],bh[j][2],bh[j][3], uBh + bd);
            }
            #pragma unroll
            for (int mt = 0; mt < 4; mt++){
                #pragma unroll
                for (int j = 0; j < 2; j++){
                    float* c0 = acc[mt][2*j];
                    float* c1 = acc[mt][2*j+1];
                    MMAH(c0[0],c0[1],c0[2],c0[3], ah[mt][0],ah[mt][1],ah[mt][2],ah[mt][3], bh[j][0],bh[j][2]);
                    MMAH(c1[0],c1[1],c1[2],c1[3], ah[mt][0],ah[mt][1],ah[mt][2],ah[mt][3], bh[j][1],bh[j][3]);
                }
            }
        }
        int nxt = kc + 2;
        if (nxt < nk) MM16_ISSUE(nxt % NSTAGE, nxt);
    }

    int rbase = lane >> 2, cbase = (lane & 3) * 2;
    #pragma unroll
    for (int mt = 0; mt < 4; mt++){
        #pragma unroll
        for (int nt = 0; nt < 4; nt++){
            int gn = n0 + wn + nt*8 + cbase;
            #pragma unroll
            for (int half = 0; half < 2; half++){
                int gm = m0 + wm + mt*16 + rbase + half*8;
                if (gm >= Mloc) continue;
                float v0 = acc[mt][nt][2*half];
                float v1 = acc[mt][nt][2*half+1];
                long long ci = (long long)(rowOff + gm)*ldc + gn;
                if (mode == 1){
                    v0 += res[ci]; v1 += res[ci+1];
                    *(float2*)(C + ci) = make_float2(v0, v1);
                } else if (mode == 3){
                    v0 = v0 / (1.f + expf(-v0));
                    v1 = v1 / (1.f + expf(-v1));
                    *(__half2*)(Cp16 + ci) = __floats2half2_rn(v0, v1);
                } else if (mode == 4){
                    int slot = rowOff + gm;
                    int t = omap[slot];
                    float w = wsl[slot];
                    long long co = (long long)t*ldc + gn;
                    atomicAdd(&C[co],   w*v0);
                    atomicAdd(&C[co+1], w*v1);
                } else {
                    *(float2*)(C + ci) = make_float2(v0, v1);
                }
            }
        }
    }
}

// ===================== fused flash attention (fp16) =====================
#define FSTR 72
#define FLASH_SMEM (3*128*FSTR*2)

__global__ void __launch_bounds__(256,1) flash_attn(
    const __half* __restrict__ qh, const __half* __restrict__ kh,
    const __half* __restrict__ vh, const float* __restrict__ mask,
    __half* __restrict__ oh)
{
    extern __shared__ __align__(16) char fsm[];
    __half* sQ = (__half*)fsm;
    __half* sK = sQ + 128*FSTR;
    __half* sV = sK + 128*FSTR;

    int tid = threadIdx.x, wid = tid >> 5, lane = tid & 31;
    int bh_ = blockIdx.y, b = bh_ >> 4, h = bh_ & 15;
    int q0 = blockIdx.x * 128;
    long long tb = (long long)b * LL;
    int crow = tid >> 1, chalf = (tid & 1) * 32;

    {
        long long g = (tb + q0 + crow)*DIMM + h*HD + chalf;
        uint4* d0 = (uint4*)&sQ[crow*FSTR + chalf];
        const uint4* s0 = (const uint4*)(qh + g);
        #pragma unroll
        for (int i = 0; i < 4; i++) d0[i] = s0[i];
    }
    __syncthreads();

    uint32_t uQ = smem_u32(sQ), uK = smem_u32(sK), uV = smem_u32(sV);
    int lr = lane & 15, ls = (lane >> 4) * 8;

    uint32_t aq[4][4];
    #pragma unroll
    for (int kc = 0; kc < 4; kc++){
        uint32_t ad = 2u*((wid*16 + lr)*FSTR + kc*16 + ls);
        LDMX4(aq[kc][0],aq[kc][1],aq[kc][2],aq[kc][3], uQ + ad);
    }

    float oacc[8][4];
    #pragma unroll
    for (int i=0;i<8;i++) for (int j=0;j<4;j++) oacc[i][j]=0.f;
    float m0r = -1e30f, m1r = -1e30f, l0r = 0.f, l1r = 0.f;

    const float* mp0 = mask + (long long)(q0 + wid*16 + (lane>>2))*LL;
    const float* mp1 = mp0 + 8*LL;
    const float SC  = 0.125f * 1.44269504f;
    const float L2E = 1.44269504f;

    for (int jt = 0; jt < 8; jt++){
        __syncthreads();
        {
            long long g = (tb + jt*128 + crow)*DIMM + h*HD + chalf;
            int so = crow*FSTR + chalf;
            const uint4 *k0 = (const uint4*)(kh+g);
            const uint4 *v0 = (const uint4*)(vh+g);
            uint4 *dk0 = (uint4*)&sK[so];
            uint4 *dv0 = (uint4*)&sV[so];
            #pragma unroll
            for (int i = 0; i < 4; i++){ dk0[i]=k0[i]; dv0[i]=v0[i]; }
        }
        __syncthreads();

        float s[16][4];
        #pragma unroll
        for (int i=0;i<16;i++) for (int j=0;j<4;j++) s[i][j]=0.f;

        #pragma unroll
        for (int kc = 0; kc < 4; kc++){
            #pragma unroll
            for (int np = 0; np < 8; np++){
                uint32_t bk[4];
                uint32_t ad = 2u*((np*16 + lr)*FSTR + kc*16 + ls);
                LDMX4(bk[0],bk[1],bk[2],bk[3], uK + ad);
                float* c0 = s[2*np]; float* c1 = s[2*np+1];
                MMAH(c0[0],c0[1],c0[2],c0[3], aq[kc][0],aq[kc][1],aq[kc][2],aq[kc][3], bk[0],bk[2]);
                MMAH(c1[0],c1[1],c1[2],c1[3], aq[kc][0],aq[kc][1],aq[kc][2],aq[kc][3], bk[1],bk[3]);
            }
        }

        float mx0 = -1e30f, mx1 = -1e30f;
        #pragma unroll
        for (int nt = 0; nt < 16; nt++){
            int colb = jt*128 + nt*8 + (lane&3)*2;
            float2 mm0 = *(const float2*)(mp0 + colb);
            float2 mm1 = *(const float2*)(mp1 + colb);
            s[nt][0] = fmaf(s[nt][0], SC, mm0.x*L2E);
            s[nt][1] = fmaf(s[nt][1], SC, mm0.y*L2E);
            s[nt][2] = fmaf(s[nt][2], SC, mm1.x*L2E);
            s[nt][3] = fmaf(s[nt][3], SC, mm1.y*L2E);
            mx0 = fmaxf(mx0, fmaxf(s[nt][0], s[nt][1]));
            mx1 = fmaxf(mx1, fmaxf(s[nt][2], s[nt][3]));
        }
        mx0 = fmaxf(mx0, __shfl_xor_sync(0xffffffffu, mx0, 1));
        mx0 = fmaxf(mx0, __shfl_xor_sync(0xffffffffu, mx0, 2));
        mx1 = fmaxf(mx1, __shfl_xor_sync(0xffffffffu, mx1, 1));
        mx1 = fmaxf(mx1, __shfl_xor_sync(0xffffffffu, mx1, 2));

        float nm0 = fmaxf(m0r, mx0), nm1 = fmaxf(m1r, mx1);
        float al0 = exp2f(m0r - nm0), al1 = exp2f(m1r - nm1);
        m0r = nm0; m1r = nm1;

        float rs0 = 0.f, rs1 = 0.f;
        #pragma unroll
        for (int nt = 0; nt < 16; nt++){
            s[nt][0] = exp2f(s[nt][0] - nm0);
            s[nt][1] = exp2f(s[nt][1] - nm0);
            s[nt][2] = exp2f(s[nt][2] - nm1);
            s[nt][3] = exp2f(s[nt][3] - nm1);
            rs0 += s[nt][0] + s[nt][1];
            rs1 += s[nt][2] + s[nt][3];
        }
        rs0 += __shfl_xor_sync(0xffffffffu, rs0, 1);
        rs0 += __shfl_xor_sync(0xffffffffu, rs0, 2);
        rs1 += __shfl_xor_sync(0xffffffffu, rs1, 1);
        rs1 += __shfl_xor_sync(0xffffffffu, rs1, 2);
        l0r = l0r*al0 + rs0;
        l1r = l1r*al1 + rs1;
        #pragma unroll
        for (int dt = 0; dt < 8; dt++){
            oacc[dt][0] *= al0; oacc[dt][1] *= al0;
            oacc[dt][2] *= al1; oacc[dt][3] *= al1;
        }

        #pragma unroll
        for (int kc2 = 0; kc2 < 8; kc2++){
            uint32_t pa[4];
            {
                __half2 h0 = __floats2half2_rn(s[2*kc2][0],   s[2*kc2][1]);
                __half2 h1 = __floats2half2_rn(s[2*kc2][2],   s[2*kc2][3]);
                __half2 h2 = __floats2half2_rn(s[2*kc2+1][0], s[2*kc2+1][1]);
                __half2 h3 = __floats2half2_rn(s[2*kc2+1][2], s[2*kc2+1][3]);
                pa[0]=*(uint32_t*)&h0; pa[1]=*(uint32_t*)&h1; pa[2]=*(uint32_t*)&h2; pa[3]=*(uint32_t*)&h3;
            }
            #pragma unroll
            for (int dt = 0; dt < 4; dt++){
                uint32_t bv[4];
                uint32_t ad = 2u*((kc2*16 + lr)*FSTR + dt*16 + ls);
                LDMX4T(bv[0],bv[1],bv[2],bv[3], uV + ad);
                float* o0 = oacc[2*dt]; float* o1 = oacc[2*dt+1];
                MMAH(o0[0],o0[1],o0[2],o0[3], pa[0],pa[1],pa[2],pa[3], bv[0],bv[1]);
                MMAH(o1[0],o1[1],o1[2],o1[3], pa[0],pa[1],pa[2],pa[3], bv[2],bv[3]);
            }
        }
    }

    float i0 = 1.f / l0r, i1 = 1.f / l1r;
    long long r0 = tb + q0 + wid*16 + (lane>>2);
    #pragma unroll
    for (int dt = 0; dt < 8; dt++){
        long long g0 = r0*DIMM + h*HD + dt*8 + (lane&3)*2;
        long long g1 = g0 + 8*DIMM;
        *(__half2*)(oh + g0) = __floats2half2_rn(oacc[dt][0]*i0, oacc[dt][1]*i0);
        *(__half2*)(oh + g1) = __floats2half2_rn(oacc[dt][2]*i1, oacc[dt][3]*i1);
    }
}

// ---------------- misc kernels ----------------
__device__ __forceinline__ float warpReduceSum(float v){
    #pragma unroll
    for (int o=16;o;o>>=1) v += __shfl_xor_sync(0xffffffffu, v, o);
    return v;
}
__device__ float blockReduceSum(float v){
    __shared__ float sh[33];
    int lane = threadIdx.x & 31, wid = threadIdx.x >> 5;
    __syncthreads();
    v = warpReduceSum(v);
    if (lane==0) sh[wid] = v;
    __syncthreads();
    int nw = blockDim.x >> 5;
    float r = (threadIdx.x < nw) ? sh[threadIdx.x] : 0.f;
    if (wid==0){ r = warpReduceSum(r); if (lane==0) sh[32] = r; }
    __syncthreads();
    return sh[32];
}

// all weights -> fp16 in one pass
__global__ void convAll(const float* __restrict__ wq, const float* __restrict__ wk,
                        const float* __restrict__ wv, const float* __restrict__ wo,
                        const float* __restrict__ s1, const float* __restrict__ s2,
                        const float* __restrict__ s3, const float* __restrict__ fc1,
                        const float* __restrict__ fc2, __half* __restrict__ o){
    long long i = ((long long)blockIdx.x*256 + threadIdx.x)*8;
    if (i >= 26*WSEG) return;
    const float* src; long long off;
    if      (i <  1*WSEG){ src = wq;  off = i; }
    else if (i <  2*WSEG){ src = wk;  off = i -  1*WSEG; }
    else if (i <  3*WSEG){ src = wv;  off = i -  2*WSEG; }
    else if (i <  4*WSEG){ src = wo;  off = i -  3*WSEG; }
    else if (i <  6*WSEG){ src = s1;  off = i -  4*WSEG; }
    else if (i <  8*WSEG){ src = s2;  off = i -  6*WSEG; }
    else if (i < 10*WSEG){ src = s3;  off = i -  8*WSEG; }
    else if (i < 18*WSEG){ src = fc1; off = i - 10*WSEG; }
    else                 { src = fc2; off = i - 18*WSEG; }
    float4 a = *(const float4*)(src + off);
    float4 b = *(const float4*)(src + off + 4);
    __half2 h0 = __floats2half2_rn(a.x, a.y);
    __half2 h1 = __floats2half2_rn(a.z, a.w);
    __half2 h2 = __floats2half2_rn(b.x, b.y);
    __half2 h3 = __floats2half2_rn(b.z, b.w);
    uint4 pk;
    pk.x = *(uint32_t*)&h0; pk.y = *(uint32_t*)&h1;
    pk.z = *(uint32_t*)&h2; pk.w = *(uint32_t*)&h3;
    *(uint4*)(o + i) = pk;
}

// rmsnorm -> optional fp32 + fp16
__global__ void __launch_bounds__(256) rmsnorm16(const float* __restrict__ x,
        const float* __restrict__ w, float* __restrict__ outf,
        __half* __restrict__ o16){
    long long row = blockIdx.x;
    float4 xv = ((const float4*)(x + row*DIMM))[threadIdx.x];
    float ss = xv.x*xv.x + xv.y*xv.y + xv.z*xv.z + xv.w*xv.w;
    float tot = blockReduceSum(ss);
    float scale = rsqrtf(tot * (1.0f/DIMM) + 1e-5f);
    float4 wv = ((const float4*)w)[threadIdx.x];
    float4 o;
    o.x = xv.x*scale*wv.x; o.y = xv.y*scale*wv.y;
    o.z = xv.z*scale*wv.z; o.w = xv.w*scale*wv.w;
    long long i = row*DIMM + threadIdx.x*4;
    if (outf) *(float4*)(outf + i) = o;
    __half2 h01 = __floats2half2_rn(o.x, o.y);
    __half2 h23 = __floats2half2_rn(o.z, o.w);
    *(uint2*)(o16 + i) = make_uint2(*(uint32_t*)&h01, *(uint32_t*)&h23);
}

// RoPE (Q,K) + V extract, all from merged qkv fp32 -> fp16
__global__ void ropeConv(const float* __restrict__ qkv,
                         __half* __restrict__ q16, __half* __restrict__ k16,
                         __half* __restrict__ v16){
    int idx = blockIdx.x*blockDim.x + threadIdx.x;
    if (idx >= NTOK*NHEADS*(HD/2)) return;
    int j = idx & 31;
    int h = (idx >> 5) & 15;
    int t = idx >> 9;
    int l = t & (LL-1);
    long long bsrc = (long long)t*3072 + h*HD;
    long long bdst = (long long)t*DIMM + h*HD;
    float inv = powf(10000.f, -(float)j * (1.f/32.f));
    float ang = (float)l * inv;
    float sn, cs; sincosf(ang, &sn, &cs);
    float a = qkv[bsrc+j], b = qkv[bsrc+32+j];
    q16[bdst+j]    = __float2half_rn(a*cs - b*sn);
    q16[bdst+32+j] = __float2half_rn(a*sn + b*cs);
    a = qkv[bsrc+1024+j]; b = qkv[bsrc+1024+32+j];
    k16[bdst+j]    = __float2half_rn(a*cs - b*sn);
    k16[bdst+32+j] = __float2half_rn(a*sn + b*cs);
    v16[bdst+j]    = __float2half_rn(qkv[bsrc+2048+j]);
    v16[bdst+32+j] = __float2half_rn(qkv[bsrc+2048+32+j]);
}

// silu(a)*b from merged tacat -> fp16
__global__ void silumul16(const float* __restrict__ tacat, __half* __restrict__ o16){
    long long i = ((long long)blockIdx.x*256 + threadIdx.x)*4;
    if (i >= (long long)NTOK*NSHARED) return;
    int t = (int)(i >> 11), c = (int)(i & 2047);
    const float* rowp = tacat + (long long)t*4096;
    float4 a = *(const float4*)(rowp + c);
    float4 b = *(const float4*)(rowp + 2048 + c);
    float4 o;
    o.x = a.x/(1.f+expf(-a.x))*b.x;
    o.y = a.y/(1.f+expf(-a.y))*b.y;
    o.z = a.z/(1.f+expf(-a.z))*b.z;
    o.w = a.w/(1.f+expf(-a.w))*b.w;
    __half2 h01 = __floats2half2_rn(o.x, o.y);
    __half2 h23 = __floats2half2_rn(o.z, o.w);
    *(uint2*)(o16 + i) = make_uint2(*(uint32_t*)&h01, *(uint32_t*)&h23);
}

__global__ void __launch_bounds__(256) gate_topk(const float* __restrict__ xf,
                                                 const float* __restrict__ gw,
                                                 int* __restrict__ topi, float* __restrict__ topw,
                                                 int* __restrict__ counts){
    int t = blockIdx.x;
    int tid = threadIdx.x;
    float4 xv = ((const float4*)(xf + (long long)t*DIMM))[tid];
    float acc[16];
    #pragma unroll
    for (int e = 0; e < 16; e++){
        float4 g = ((const float4*)(gw + (long long)e*DIMM))[tid];
        acc[e] = xv.x*g.x + xv.y*g.y + xv.z*g.z + xv.w*g.w;
    }
    #pragma unroll
    for (int e = 0; e < 16; e++) acc[e] = warpReduceSum(acc[e]);
    __shared__ float wr[8][16];
    __shared__ float lg[16];
    int lane = tid & 31, wid = tid >> 5;
    if (lane == 0){
        #pragma unroll
        for (int e = 0; e < 16; e++) wr[wid][e] = acc[e];
    }
    __syncthreads();
    if (tid < 16){
        float s = 0.f;
        #pragma unroll
        for (int w = 0; w < 8; w++) s += wr[w][tid];
        lg[tid] = s;
    }
    __syncthreads();
    if (tid == 0){
        float l0 = -3.0e38f; int i0 = 0;
        for (int e = 0; e < 16; e++) if (lg[e] > l0){ l0 = lg[e]; i0 = e; }
        float l1 = -3.0e38f; int i1 = 0;
        for (int e = 0; e < 16; e++) if (e != i0 && lg[e] > l1){ l1 = lg[e]; i1 = e; }
        float w1 = expf(l1 - l0);
        float sden = 1.f + w1;
        topi[2*t] = i0; topi[2*t+1] = i1;
        topw[2*t] = 1.f / sden; topw[2*t+1] = w1 / sden;
        atomicAdd(&counts[i0], 1);
        atomicAdd(&counts[i1], 1);
    }
}

__global__ void zero_counts(int* counts){
    if (threadIdx.x < NE) counts[threadIdx.x] = 0;
}
__global__ void scan_kernel(const int* __restrict__ counts, int* __restrict__ offs,
                            int* __restrict__ cursor){
    if (threadIdx.x == 0){
        int s = 0;
        for (int e = 0; e < NE; e++){ offs[e] = s; s += counts[e]; cursor[e] = 0; }
    }
}
__global__ void scatter_kernel(const int* __restrict__ topi, int* __restrict__ cursor,
                               const int* __restrict__ offs, const float* __restrict__ topw,
                               int* __restrict__ order, float* __restrict__ wslot){
    int t = blockIdx.x*blockDim.x + threadIdx.x;
    if (t >= NTOK) return;
    #pragma unroll
    for (int k2 = 0; k2 < 2; k2++){
        int e = topi[2*t+k2];
        int pos = atomicAdd(&cursor[e], 1);
        int slot = offs[e] + pos;
        order[slot] = t;
        wslot[slot] = topw[2*t+k2];
    }
}

// ---------------- host launcher ----------------
extern "C" void kernel_launch(void* const* d_in, const int* in_sizes, int n_in,
                              void* d_out, int out_size){
    const float* x    = (const float*)d_in[0];
    const float* mask = (const float*)d_in[1];
    const float* wq   = (const float*)d_in[2];
    const float* wk   = (const float*)d_in[3];
    const float* wv   = (const float*)d_in[4];
    const float* wo   = (const float*)d_in[5];
    const float* n1   = (const float*)d_in[6];
    const float* n2   = (const float*)d_in[7];
    const float* gw   = (const float*)d_in[8];
    const float* fc1  = (const float*)d_in[9];
    const float* fc2  = (const float*)d_in[10];
    const float* s1   = (const float*)d_in[11];
    const float* s2   = (const float*)d_in[12];
    const float* s3   = (const float*)d_in[13];
    float* out = (float*)d_out;

    void *p;
    cudaGetSymbolAddress(&p, g_qkv);    float* qkv    = (float*)p;
    cudaGetSymbolAddress(&p, g_h);      float* hbuf   = (float*)p;
    cudaGetSymbolAddress(&p, g_xf);     float* xf     = (float*)p;
    cudaGetSymbolAddress(&p, g_tacat);  float* tacat  = (float*)p;
    cudaGetSymbolAddress(&p, g_wh);     __half* wh   = (__half*)p;
    cudaGetSymbolAddress(&p, g_hn16);   __half* hn16 = (__half*)p;
    cudaGetSymbolAddress(&p, g_q16);    __half* q16  = (__half*)p;
    cudaGetSymbolAddress(&p, g_k16);    __half* k16  = (__half*)p;
    cudaGetSymbolAddress(&p, g_v16);    __half* v16  = (__half*)p;
    cudaGetSymbolAddress(&p, g_a16);    __half* a16  = (__half*)p;
    cudaGetSymbolAddress(&p, g_x16);    __half* x16  = (__half*)p;
    cudaGetSymbolAddress(&p, g_ta16);   __half* ta16 = (__half*)p;
    cudaGetSymbolAddress(&p, g_e16);    __half* e16  = (__half*)p;
    cudaGetSymbolAddress(&p, g_topi);   int*   topi   = (int*)p;
    cudaGetSymbolAddress(&p, g_topw);   float* topw   = (float*)p;
    cudaGetSymbolAddress(&p, g_counts); int*   counts = (int*)p;
    cudaGetSymbolAddress(&p, g_cursor); int*   cursor = (int*)p;
    cudaGetSymbolAddress(&p, g_offs);   int*   offs   = (int*)p;
    cudaGetSymbolAddress(&p, g_order);  int*   order  = (int*)p;
    cudaGetSymbolAddress(&p, g_wslot);  float* wslot  = (float*)p;

    cudaFuncSetAttribute(mm16, cudaFuncAttributeMaxDynamicSharedMemorySize, MM16_SMEM);
    cudaFuncSetAttribute(flash_attn, cudaFuncAttributeMaxDynamicSharedMemorySize, FLASH_SMEM);

    // weight segment offsets (halves)
    __half* W_QKV = wh;
    __half* W_O   = wh +  3*WSEG;
    __half* W_S12 = wh +  4*WSEG;
    __half* W_S3  = wh +  8*WSEG;
    __half* W_FC1 = wh + 10*WSEG;
    __half* W_FC2 = wh + 18*WSEG;

    // 0. all weights -> fp16, one launch
    convAll<<<(int)(26*WSEG/2048), 256>>>(wq, wk, wv, wo, s1, s2, s3, fc1, fc2, wh);
    // 1. rmsnorm1 -> fp16
    rmsnorm16<<<NTOK, 256>>>(x, n1, nullptr, hn16);
    // 2. merged QKV
    mm16<<<dim3(24,32,1),256,MM16_SMEM>>>(hn16, W_QKV, qkv, nullptr, nullptr,
        NTOK, 3*DIMM, DIMM, DIMM, DIMM, 3*DIMM, 0, nullptr, nullptr, nullptr, nullptr, nullptr, 0);
    // 3. RoPE + V extract (fused)
    ropeConv<<<(NTOK*NHEADS*32)/256, 256>>>(qkv, q16, k16, v16);
    // 4. flash attention
    flash_attn<<<dim3(8,64),256,FLASH_SMEM>>>(q16, k16, v16, mask, a16);
    // 5. h = x + attn @ wo^T
    mm16<<<dim3(8,32,1),256,MM16_SMEM>>>(a16, W_O, hbuf, x, nullptr,
        NTOK, DIMM, DIMM, DIMM, DIMM, DIMM, 1, nullptr, nullptr, nullptr, nullptr, nullptr, 0);
    // 6. rmsnorm2
    rmsnorm16<<<NTOK, 256>>>(hbuf, n2, xf, x16);
    // 7. merged shared fc1|fc2
    mm16<<<dim3(32,32,1),256,MM16_SMEM>>>(x16, W_S12, tacat, nullptr, nullptr,
        NTOK, 2*NSHARED, DIMM, DIMM, DIMM, 2*NSHARED, 0, nullptr, nullptr, nullptr, nullptr, nullptr, 0);
    silumul16<<<(NTOK*NSHARED)/1024, 256>>>(tacat, ta16);
    // 8. out = h + silu_out @ s3^T   (writes d_out directly)
    mm16<<<dim3(8,32,1),256,MM16_SMEM>>>(ta16, W_S3, out, hbuf, nullptr,
        NTOK, DIMM, NSHARED, NSHARED, NSHARED, DIMM, 1, nullptr, nullptr, nullptr, nullptr, nullptr, 0);
    // 9. routing
    zero_counts<<<1,32>>>(counts);
    gate_topk<<<NTOK,256>>>(xf, gw, topi, topw, counts);
    scan_kernel<<<1,1>>>(counts, offs, cursor);
    scatter_kernel<<<NTOK/256,256>>>(topi, cursor, offs, topw, order, wslot);
    // 10. expert fc1 (gather + silu -> fp16)
    mm16<<<dim3(4,64,NE),256,MM16_SMEM>>>(x16, W_FC1, nullptr, nullptr, e16,
        0, HID, DIMM, DIMM, DIMM, HID, 3, counts, offs, order, nullptr, nullptr, (long long)HID*DIMM);
    // 11. expert fc2: atomic combine into out
    mm16<<<dim3(8,64,NE),256,MM16_SMEM>>>(e16, W_FC2, out, nullptr, nullptr,
        0, DIMM, HID, HID, HID, DIMM, 4, counts, offs, nullptr, order, wslot, (long long)DIMM*HID);
}

// round 8
// speedup vs baseline: 5.5677x; 1.0338x over previous
#include <cuda_runtime.h>
#include <cuda_fp16.h>
#include <math.h>
#include <stdint.h>

#define BB 4
#define LL 1024
#define DIMM 1024
#define NHEADS 16
#define HD 64
#define NTOK (BB*LL)
#define HID 512
#define NE 16
#define NSHARED 2048
#define NSLOTS (NTOK*2)

// ---------------- scratch ----------------
__device__ float g_qkv[NTOK*3*DIMM];
__device__ float g_h[NTOK*DIMM];
__device__ float g_xf[NTOK*DIMM];
__device__ float g_tacat[(long long)NTOK*2*NSHARED];
// fp16 buffers
#define WSEG 1048576ll
__device__ __half g_wh[26*WSEG];
__device__ __half g_hn16[NTOK*DIMM];
__device__ __half g_q16[NTOK*DIMM];
__device__ __half g_k16[NTOK*DIMM];
__device__ __half g_v16[NTOK*DIMM];
__device__ __half g_a16[NTOK*DIMM];
__device__ __half g_x16[NTOK*DIMM];
__device__ __half g_ta16[NTOK*NSHARED];
__device__ __half g_e16[NSLOTS*HID];
// routing
__device__ int   g_topi[NSLOTS];
__device__ float g_topw[NSLOTS];
__device__ int   g_counts[NE];
__device__ int   g_cursor[NE];
__device__ int   g_offs[NE];
__device__ int   g_order[NSLOTS];
__device__ float g_wslot[NSLOTS];

__device__ __forceinline__ uint32_t smem_u32(const void* p){
    uint32_t a;
    asm("{ .reg .u64 t; cvta.to.shared.u64 t, %1; cvt.u32.u64 %0, t; }" : "=r"(a) : "l"(p));
    return a;
}

#define LDMX4(r0,r1,r2,r3,addr) \
    asm volatile("ldmatrix.sync.aligned.m8n8.x4.shared.b16 {%0,%1,%2,%3}, [%4];" \
        : "=r"(r0),"=r"(r1),"=r"(r2),"=r"(r3) : "r"(addr))
#define LDMX4T(r0,r1,r2,r3,addr) \
    asm volatile("ldmatrix.sync.aligned.m8n8.x4.trans.shared.b16 {%0,%1,%2,%3}, [%4];" \
        : "=r"(r0),"=r"(r1),"=r"(r2),"=r"(r3) : "r"(addr))

#define MMAH(c0,c1,c2,c3,a0,a1,a2,a3,b0,b1) \
    asm volatile("mma.sync.aligned.m16n8k16.row.col.f32.f16.f16.f32 " \
        "{%0,%1,%2,%3}, {%4,%5,%6,%7}, {%8,%9}, {%0,%1,%2,%3};" \
        : "+f"(c0),"+f"(c1),"+f"(c2),"+f"(c3) \
        : "r"(a0),"r"(a1),"r"(a2),"r"(a3), "r"(b0),"r"(b1))

#define CPASYNC(dst,src,sz) \
    asm volatile("cp.async.cg.shared.global [%0], [%1], 16, %2;" :: "r"(dst), "l"(src), "r"(sz))
#define CPCOMMIT() asm volatile("cp.async.commit_group;")
#define CPWAIT(n)  asm volatile("cp.async.wait_group %0;" :: "n"(n))

// ========== fp16 GEMM: C = A * B^T ; 128x256 tile, 64x64 warp tile ==========
// mode: 0 fp32 out, 1 fp32 += res, 3 silu -> fp16 out, 4 atomic MoE combine
#define ROWB 80                    // bytes per smem row (32 halves + 8 pad)
#define STAGE_BYTES (384*ROWB)     // A 128 rows + B 256 rows
#define NSTAGE 3
#define MM16_SMEM (NSTAGE*STAGE_BYTES)

__global__ void __launch_bounds__(256,1) mm16(
    const __half* __restrict__ Ah, const __half* __restrict__ Bh,
    float* __restrict__ C, const float* __restrict__ res,
    __half* __restrict__ Cp16,
    int M, int N, int K, int lda, int ldb, int ldc, int mode,
    const int* __restrict__ counts, const int* __restrict__ offs,
    const int* __restrict__ rows,
    const int* __restrict__ omap, const float* __restrict__ wsl,
    long long bStrideE)
{
    extern __shared__ __align__(16) char dsm[];
    __shared__ int rsrc[128];
    uint32_t ub = smem_u32(dsm);
    int tid = threadIdx.x, wid = tid >> 5, lane = tid & 31;
    int e = blockIdx.z;

    int Mloc = M, rowOff = 0;
    const __half* Bp = Bh;
    if (counts){ Mloc = counts[e]; rowOff = offs[e]; Bp = Bh + (long long)e*bStrideE; }
    int m0 = blockIdx.y * 128;
    if (m0 >= Mloc) return;
    int n0 = blockIdx.x * 256;

    for (int i = tid; i < 128; i += 256){
        int gr = m0 + i;
        rsrc[i] = (gr < Mloc) ? (rows ? rows[rowOff + gr] : (counts ? rowOff + gr : gr)) : -1;
    }
    __syncthreads();

    // copy plan: 1536 chunks of 16B (384 rows x 4 parts), 6 per thread
    const __half* srcp[6];
    uint32_t dsto[6];
    int szs[6];
    #pragma unroll
    for (int i = 0; i < 6; i++){
        int c = tid + i*256;
        int row = c >> 2, part = c & 3;
        dsto[i] = (uint32_t)(row*ROWB + part*16);
        if (row < 128){
            int s = rsrc[row];
            szs[i] = (s >= 0) ? 16 : 0;
            srcp[i] = Ah + (long long)((s >= 0) ? s : 0)*lda + part*8;
        } else {
            szs[i] = 16;
            srcp[i] = Bp + (long long)(n0 + row - 128)*ldb + part*8;
        }
    }

#define MM16_ISSUE(stg, kc) do { \
    uint32_t dd = ub + (stg)*STAGE_BYTES; int ko = (kc)*32; \
    _Pragma("unroll") \
    for (int i = 0; i < 6; i++) CPASYNC(dd + dsto[i], srcp[i] + ko, szs[i]); \
    CPCOMMIT(); } while(0)

    float acc[4][8][4];
    #pragma unroll
    for (int i=0;i<4;i++) for (int j=0;j<8;j++) for (int f=0;f<4;f++) acc[i][j][f]=0.f;

    int wm = (wid >> 2) * 64, wn = (wid & 3) * 64;
    int lrow = lane & 15, lsel = (lane >> 4) * 8;
    int nk = K >> 5;

    MM16_ISSUE(0, 0);
    if (nk > 1) MM16_ISSUE(1, 1);
    for (int kc = 0; kc < nk; kc++){
        if (kc + 1 < nk) CPWAIT(1); else CPWAIT(0);
        __syncthreads();
        int nxt = kc + 2;
        if (nxt < nk) MM16_ISSUE(nxt % NSTAGE, nxt);
        uint32_t us = ub + (kc % NSTAGE)*STAGE_BYTES;
        #pragma unroll
        for (int ks = 0; ks < 2; ks++){
            int kofs2 = (ks*16 + lsel)*2;
            uint32_t ah[4][4], bh[4][4];
            #pragma unroll
            for (int mt = 0; mt < 4; mt++){
                uint32_t ad = us + (uint32_t)((wm + mt*16 + lrow)*ROWB) + kofs2;
                LDMX4(ah[mt][0],ah[mt][1],ah[mt][2],ah[mt][3], ad);
            }
            #pragma unroll
            for (int j = 0; j < 4; j++){
                uint32_t bd = us + (uint32_t)((128 + wn + j*16 + lrow)*ROWB) + kofs2;
                LDMX4(bh[j][0],bh[j][1],bh[j][2],bh[j][3], bd);
            }
            #pragma unroll
            for (int mt = 0; mt < 4; mt++){
                #pragma unroll
                for (int j = 0; j < 4; j++){
                    float* c0 = acc[mt][2*j];
                    float* c1 = acc[mt][2*j+1];
                    MMAH(c0[0],c0[1],c0[2],c0[3], ah[mt][0],ah[mt][1],ah[mt][2],ah[mt][3], bh[j][0],bh[j][2]);
                    MMAH(c1[0],c1[1],c1[2],c1[3], ah[mt][0],ah[mt][1],ah[mt][2],ah[mt][3], bh[j][1],bh[j][3]);
                }
            }
        }
    }

    int rbase = lane >> 2, cbase = (lane & 3) * 2;
    #pragma unroll
    for (int mt = 0; mt < 4; mt++){
        #pragma unroll
        for (int nt = 0; nt < 8; nt++){
            int gn = n0 + wn + nt*8 + cbase;
            #pragma unroll
            for (int half = 0; half < 2; half++){
                int gm = m0 + wm + mt*16 + rbase + half*8;
                if (gm >= Mloc) continue;
                float v0 = acc[mt][nt][2*half];
                float v1 = acc[mt][nt][2*half+1];
                long long ci = (long long)(rowOff + gm)*ldc + gn;
                if (mode == 1){
                    v0 += res[ci]; v1 += res[ci+1];
                    *(float2*)(C + ci) = make_float2(v0, v1);
                } else if (mode == 3){
                    v0 = v0 / (1.f + expf(-v0));
                    v1 = v1 / (1.f + expf(-v1));
                    *(__half2*)(Cp16 + ci) = __floats2half2_rn(v0, v1);
                } else if (mode == 4){
                    int slot = rowOff + gm;
                    int t = omap[slot];
                    float w = wsl[slot];
                    long long co = (long long)t*ldc + gn;
                    atomicAdd(&C[co],   w*v0);
                    atomicAdd(&C[co+1], w*v1);
                } else {
                    *(float2*)(C + ci) = make_float2(v0, v1);
                }
            }
        }
    }
}

// ===================== fused flash attention, 3-stage cp.async K/V =====================
#define FSTR 72
#define KVHALF (128*FSTR*2)        // 18432
#define KVSTG  (2*KVHALF)          // K+V per stage
#define FLASH_SMEM (KVHALF + 3*KVSTG)

__global__ void __launch_bounds__(256,1) flash_attn(
    const __half* __restrict__ qh, const __half* __restrict__ kh,
    const __half* __restrict__ vh, const float* __restrict__ mask,
    __half* __restrict__ oh)
{
    extern __shared__ __align__(16) char fsm[];
    __half* sQ = (__half*)fsm;
    uint32_t uQ = smem_u32(fsm);
    uint32_t ukv0 = uQ + KVHALF;

    int tid = threadIdx.x, wid = tid >> 5, lane = tid & 31;
    int bh_ = blockIdx.y, b = bh_ >> 4, h = bh_ & 15;
    int q0 = blockIdx.x * 128;
    long long tb = (long long)b * LL;
    int crow = tid >> 1, chalf = (tid & 1) * 32;

#define FLASH_ISSUE(jt) do { \
    int st_ = (jt) % 3; \
    long long g_ = (tb + (jt)*128 + crow)*DIMM + h*HD + chalf; \
    uint32_t dk_ = ukv0 + st_*KVSTG + (uint32_t)(crow*144 + chalf*2); \
    const __half* ks_ = kh + g_; const __half* vs_ = vh + g_; \
    CPASYNC(dk_,    ks_,    16); CPASYNC(dk_+16, ks_+8,  16); \
    CPASYNC(dk_+32, ks_+16, 16); CPASYNC(dk_+48, ks_+24, 16); \
    uint32_t dv_ = dk_ + KVHALF; \
    CPASYNC(dv_,    vs_,    16); CPASYNC(dv_+16, vs_+8,  16); \
    CPASYNC(dv_+32, vs_+16, 16); CPASYNC(dv_+48, vs_+24, 16); \
    CPCOMMIT(); } while(0)

    { // Q tile (plain loads, once)
        long long g = (tb + q0 + crow)*DIMM + h*HD + chalf;
        uint4* d0 = (uint4*)&sQ[crow*FSTR + chalf];
        const uint4* s0 = (const uint4*)(qh + g);
        #pragma unroll
        for (int i = 0; i < 4; i++) d0[i] = s0[i];
    }
    FLASH_ISSUE(0);
    FLASH_ISSUE(1);
    __syncthreads();

    int lr = lane & 15, ls = (lane >> 4) * 8;
    uint32_t aq[4][4];
    #pragma unroll
    for (int kc = 0; kc < 4; kc++){
        uint32_t ad = uQ + 2u*((wid*16 + lr)*FSTR + kc*16 + ls);
        LDMX4(aq[kc][0],aq[kc][1],aq[kc][2],aq[kc][3], ad);
    }

    float oacc[8][4];
    #pragma unroll
    for (int i=0;i<8;i++) for (int j=0;j<4;j++) oacc[i][j]=0.f;
    float m0r = -1e30f, m1r = -1e30f, l0r = 0.f, l1r = 0.f;

    const float* mp0 = mask + (long long)(q0 + wid*16 + (lane>>2))*LL;
    const float* mp1 = mp0 + 8*LL;
    const float SC  = 0.125f * 1.44269504f;
    const float L2E = 1.44269504f;

    for (int jt = 0; jt < 8; jt++){
        if (jt < 7) CPWAIT(1); else CPWAIT(0);
        __syncthreads();
        if (jt + 2 < 8) FLASH_ISSUE(jt + 2);
        uint32_t uK = ukv0 + (jt % 3)*KVSTG, uV = uK + KVHALF;

        float s[16][4];
        #pragma unroll
        for (int i=0;i<16;i++) for (int j=0;j<4;j++) s[i][j]=0.f;

        #pragma unroll
        for (int kc = 0; kc < 4; kc++){
            #pragma unroll
            for (int np = 0; np < 8; np++){
                uint32_t bk[4];
                uint32_t ad = uK + 2u*((np*16 + lr)*FSTR + kc*16 + ls);
                LDMX4(bk[0],bk[1],bk[2],bk[3], ad);
                float* c0 = s[2*np]; float* c1 = s[2*np+1];
                MMAH(c0[0],c0[1],c0[2],c0[3], aq[kc][0],aq[kc][1],aq[kc][2],aq[kc][3], bk[0],bk[2]);
                MMAH(c1[0],c1[1],c1[2],c1[3], aq[kc][0],aq[kc][1],aq[kc][2],aq[kc][3], bk[1],bk[3]);
            }
        }

        float mx0 = -1e30f, mx1 = -1e30f;
        #pragma unroll
        for (int nt = 0; nt < 16; nt++){
            int colb = jt*128 + nt*8 + (lane&3)*2;
            float2 mm0 = *(const float2*)(mp0 + colb);
            float2 mm1 = *(const float2*)(mp1 + colb);
            s[nt][0] = fmaf(s[nt][0], SC, mm0.x*L2E);
            s[nt][1] = fmaf(s[nt][1], SC, mm0.y*L2E);
            s[nt][2] = fmaf(s[nt][2], SC, mm1.x*L2E);
            s[nt][3] = fmaf(s[nt][3], SC, mm1.y*L2E);
            mx0 = fmaxf(mx0, fmaxf(s[nt][0], s[nt][1]));
            mx1 = fmaxf(mx1, fmaxf(s[nt][2], s[nt][3]));
        }
        mx0 = fmaxf(mx0, __shfl_xor_sync(0xffffffffu, mx0, 1));
        mx0 = fmaxf(mx0, __shfl_xor_sync(0xffffffffu, mx0, 2));
        mx1 = fmaxf(mx1, __shfl_xor_sync(0xffffffffu, mx1, 1));
        mx1 = fmaxf(mx1, __shfl_xor_sync(0xffffffffu, mx1, 2));

        float nm0 = fmaxf(m0r, mx0), nm1 = fmaxf(m1r, mx1);
        float al0 = exp2f(m0r - nm0), al1 = exp2f(m1r - nm1);
        m0r = nm0; m1r = nm1;

        float rs0 = 0.f, rs1 = 0.f;
        #pragma unroll
        for (int nt = 0; nt < 16; nt++){
            s[nt][0] = exp2f(s[nt][0] - nm0);
            s[nt][1] = exp2f(s[nt][1] - nm0);
            s[nt][2] = exp2f(s[nt][2] - nm1);
            s[nt][3] = exp2f(s[nt][3] - nm1);
            rs0 += s[nt][0] + s[nt][1];
            rs1 += s[nt][2] + s[nt][3];
        }
        rs0 += __shfl_xor_sync(0xffffffffu, rs0, 1);
        rs0 += __shfl_xor_sync(0xffffffffu, rs0, 2);
        rs1 += __shfl_xor_sync(0xffffffffu, rs1, 1);
        rs1 += __shfl_xor_sync(0xffffffffu, rs1, 2);
        l0r = l0r*al0 + rs0;
        l1r = l1r*al1 + rs1;
        #pragma unroll
        for (int dt = 0; dt < 8; dt++){
            oacc[dt][0] *= al0; oacc[dt][1] *= al0;
            oacc[dt][2] *= al1; oacc[dt][3] *= al1;
        }

        #pragma unroll
        for (int kc2 = 0; kc2 < 8; kc2++){
            uint32_t pa[4];
            {
                __half2 h0 = __floats2half2_rn(s[2*kc2][0],   s[2*kc2][1]);
                __half2 h1 = __floats2half2_rn(s[2*kc2][2],   s[2*kc2][3]);
                __half2 h2 = __floats2half2_rn(s[2*kc2+1][0], s[2*kc2+1][1]);
                __half2 h3 = __floats2half2_rn(s[2*kc2+1][2], s[2*kc2+1][3]);
                pa[0]=*(uint32_t*)&h0; pa[1]=*(uint32_t*)&h1; pa[2]=*(uint32_t*)&h2; pa[3]=*(uint32_t*)&h3;
            }
            #pragma unroll
            for (int dt = 0; dt < 4; dt++){
                uint32_t bv[4];
                uint32_t ad = uV + 2u*((kc2*16 + lr)*FSTR + dt*16 + ls);
                LDMX4T(bv[0],bv[1],bv[2],bv[3], ad);
                float* o0 = oacc[2*dt]; float* o1 = oacc[2*dt+1];
                MMAH(o0[0],o0[1],o0[2],o0[3], pa[0],pa[1],pa[2],pa[3], bv[0],bv[1]);
                MMAH(o1[0],o1[1],o1[2],o1[3], pa[0],pa[1],pa[2],pa[3], bv[2],bv[3]);
            }
        }
    }

    float i0 = 1.f / l0r, i1 = 1.f / l1r;
    long long r0 = tb + q0 + wid*16 + (lane>>2);
    #pragma unroll
    for (int dt = 0; dt < 8; dt++){
        long long g0 = r0*DIMM + h*HD + dt*8 + (lane&3)*2;
        long long g1 = g0 + 8*DIMM;
        *(__half2*)(oh + g0) = __floats2half2_rn(oacc[dt][0]*i0, oacc[dt][1]*i0);
        *(__half2*)(oh + g1) = __floats2half2_rn(oacc[dt][2]*i1, oacc[dt][3]*i1);
    }
}

// ---------------- misc kernels ----------------
__device__ __forceinline__ float warpReduceSum(float v){
    #pragma unroll
    for (int o=16;o;o>>=1) v += __shfl_xor_sync(0xffffffffu, v, o);
    return v;
}
__device__ float blockReduceSum(float v){
    __shared__ float sh[33];
    int lane = threadIdx.x & 31, wid = threadIdx.x >> 5;
    __syncthreads();
    v = warpReduceSum(v);
    if (lane==0) sh[wid] = v;
    __syncthreads();
    int nw = blockDim.x >> 5;
    float r = (threadIdx.x < nw) ? sh[threadIdx.x] : 0.f;
    if (wid==0){ r = warpReduceSum(r); if (lane==0) sh[32] = r; }
    __syncthreads();
    return sh[32];
}

__global__ void convAll(const float* __restrict__ wq, const float* __restrict__ wk,
                        const float* __restrict__ wv, const float* __restrict__ wo,
                        const float* __restrict__ s1, const float* __restrict__ s2,
                        const float* __restrict__ s3, const float* __restrict__ fc1,
                        const float* __restrict__ fc2, __half* __restrict__ o){
    long long i = ((long long)blockIdx.x*256 + threadIdx.x)*8;
    if (i >= 26*WSEG) return;
    const float* src; long long off;
    if      (i <  1*WSEG){ src = wq;  off = i; }
    else if (i <  2*WSEG){ src = wk;  off = i -  1*WSEG; }
    else if (i <  3*WSEG){ src = wv;  off = i -  2*WSEG; }
    else if (i <  4*WSEG){ src = wo;  off = i -  3*WSEG; }
    else if (i <  6*WSEG){ src = s1;  off = i -  4*WSEG; }
    else if (i <  8*WSEG){ src = s2;  off = i -  6*WSEG; }
    else if (i < 10*WSEG){ src = s3;  off = i -  8*WSEG; }
    else if (i < 18*WSEG){ src = fc1; off = i - 10*WSEG; }
    else                 { src = fc2; off = i - 18*WSEG; }
    float4 a = *(const float4*)(src + off);
    float4 b = *(const float4*)(src + off + 4);
    __half2 h0 = __floats2half2_rn(a.x, a.y);
    __half2 h1 = __floats2half2_rn(a.z, a.w);
    __half2 h2 = __floats2half2_rn(b.x, b.y);
    __half2 h3 = __floats2half2_rn(b.z, b.w);
    uint4 pk;
    pk.x = *(uint32_t*)&h0; pk.y = *(uint32_t*)&h1;
    pk.z = *(uint32_t*)&h2; pk.w = *(uint32_t*)&h3;
    *(uint4*)(o + i) = pk;
}

__global__ void __launch_bounds__(256) rmsnorm16(const float* __restrict__ x,
        const float* __restrict__ w, float* __restrict__ outf,
        __half* __restrict__ o16){
    long long row = blockIdx.x;
    float4 xv = ((const float4*)(x + row*DIMM))[threadIdx.x];
    float ss = xv.x*xv.x + xv.y*xv.y + xv.z*xv.z + xv.w*xv.w;
    float tot = blockReduceSum(ss);
    float scale = rsqrtf(tot * (1.0f/DIMM) + 1e-5f);
    float4 wv = ((const float4*)w)[threadIdx.x];
    float4 o;
    o.x = xv.x*scale*wv.x; o.y = xv.y*scale*wv.y;
    o.z = xv.z*scale*wv.z; o.w = xv.w*scale*wv.w;
    long long i = row*DIMM + threadIdx.x*4;
    if (outf) *(float4*)(outf + i) = o;
    __half2 h01 = __floats2half2_rn(o.x, o.y);
    __half2 h23 = __floats2half2_rn(o.z, o.w);
    *(uint2*)(o16 + i) = make_uint2(*(uint32_t*)&h01, *(uint32_t*)&h23);
}

__global__ void ropeConv(const float* __restrict__ qkv,
                         __half* __restrict__ q16, __half* __restrict__ k16,
                         __half* __restrict__ v16){
    int idx = blockIdx.x*blockDim.x + threadIdx.x;
    if (idx >= NTOK*NHEADS*(HD/2)) return;
    int j = idx & 31;
    int h = (idx >> 5) & 15;
    int t = idx >> 9;
    int l = t & (LL-1);
    long long bsrc = (long long)t*3072 + h*HD;
    long long bdst = (long long)t*DIMM + h*HD;
    float inv = powf(10000.f, -(float)j * (1.f/32.f));
    float ang = (float)l * inv;
    float sn, cs; sincosf(ang, &sn, &cs);
    float a = qkv[bsrc+j], b = qkv[bsrc+32+j];
    q16[bdst+j]    = __float2half_rn(a*cs - b*sn);
    q16[bdst+32+j] = __float2half_rn(a*sn + b*cs);
    a = qkv[bsrc+1024+j]; b = qkv[bsrc+1024+32+j];
    k16[bdst+j]    = __float2half_rn(a*cs - b*sn);
    k16[bdst+32+j] = __float2half_rn(a*sn + b*cs);
    v16[bdst+j]    = __float2half_rn(qkv[bsrc+2048+j]);
    v16[bdst+32+j] = __float2half_rn(qkv[bsrc+2048+32+j]);
}

__global__ void silumul16(const float* __restrict__ tacat, __half* __restrict__ o16){
    long long i = ((long long)blockIdx.x*256 + threadIdx.x)*4;
    if (i >= (long long)NTOK*NSHARED) return;
    int t = (int)(i >> 11), c = (int)(i & 2047);
    const float* rowp = tacat + (long long)t*4096;
    float4 a = *(const float4*)(rowp + c);
    float4 b = *(const float4*)(rowp + 2048 + c);
    float4 o;
    o.x = a.x/(1.f+expf(-a.x))*b.x;
    o.y = a.y/(1.f+expf(-a.y))*b.y;
    o.z = a.z/(1.f+expf(-a.z))*b.z;
    o.w = a.w/(1.f+expf(-a.w))*b.w;
    __half2 h01 = __floats2half2_rn(o.x, o.y);
    __half2 h23 = __floats2half2_rn(o.z, o.w);
    *(uint2*)(o16 + i) = make_uint2(*(uint32_t*)&h01, *(uint32_t*)&h23);
}

__global__ void __launch_bounds__(256) gate_topk(const float* __restrict__ xf,
                                                 const float* __restrict__ gw,
                                                 int* __restrict__ topi, float* __restrict__ topw,
                                                 int* __restrict__ counts){
    int t = blockIdx.x;
    int tid = threadIdx.x;
    float4 xv = ((const float4*)(xf + (long long)t*DIMM))[tid];
    float acc[16];
    #pragma unroll
    for (int e = 0; e < 16; e++){
        float4 g = ((const float4*)(gw + (long long)e*DIMM))[tid];
        acc[e] = xv.x*g.x + xv.y*g.y + xv.z*g.z + xv.w*g.w;
    }
    #pragma unroll
    for (int e = 0; e < 16; e++) acc[e] = warpReduceSum(acc[e]);
    __shared__ float wr[8][16];
    __shared__ float lg[16];
    int lane = tid & 31, wid = tid >> 5;
    if (lane == 0){
        #pragma unroll
        for (int e = 0; e < 16; e++) wr[wid][e] = acc[e];
    }
    __syncthreads();
    if (tid < 16){
        float s = 0.f;
        #pragma unroll
        for (int w = 0; w < 8; w++) s += wr[w][tid];
        lg[tid] = s;
    }
    __syncthreads();
    if (tid == 0){
        float l0 = -3.0e38f; int i0 = 0;
        for (int e = 0; e < 16; e++) if (lg[e] > l0){ l0 = lg[e]; i0 = e; }
        float l1 = -3.0e38f; int i1 = 0;
        for (int e = 0; e < 16; e++) if (e != i0 && lg[e] > l1){ l1 = lg[e]; i1 = e; }
        float w1 = expf(l1 - l0);
        float sden = 1.f + w1;
        topi[2*t] = i0; topi[2*t+1] = i1;
        topw[2*t] = 1.f / sden; topw[2*t+1] = w1 / sden;
        atomicAdd(&counts[i0], 1);
        atomicAdd(&counts[i1], 1);
    }
}

__global__ void zero_counts(int* counts){
    if (threadIdx.x < NE) counts[threadIdx.x] = 0;
}
__global__ void scan_kernel(const int* __restrict__ counts, int* __restrict__ offs,
                            int* __restrict__ cursor){
    if (threadIdx.x == 0){
        int s = 0;
        for (int e = 0; e < NE; e++){ offs[e] = s; s += counts[e]; cursor[e] = 0; }
    }
}
__global__ void scatter_kernel(const int* __restrict__ topi, int* __restrict__ cursor,
                               const int* __restrict__ offs, const float* __restrict__ topw,
                               int* __restrict__ order, float* __restrict__ wslot){
    int t = blockIdx.x*blockDim.x + threadIdx.x;
    if (t >= NTOK) return;
    #pragma unroll
    for (int k2 = 0; k2 < 2; k2++){
        int e = topi[2*t+k2];
        int pos = atomicAdd(&cursor[e], 1);
        int slot = offs[e] + pos;
        order[slot] = t;
        wslot[slot] = topw[2*t+k2];
    }
}

// ---------------- host launcher ----------------
extern "C" void kernel_launch(void* const* d_in, const int* in_sizes, int n_in,
                              void* d_out, int out_size){
    const float* x    = (const float*)d_in[0];
    const float* mask = (const float*)d_in[1];
    const float* wq   = (const float*)d_in[2];
    const float* wk   = (const float*)d_in[3];
    const float* wv   = (const float*)d_in[4];
    const float* wo   = (const float*)d_in[5];
    const float* n1   = (const float*)d_in[6];
    const float* n2   = (const float*)d_in[7];
    const float* gw   = (const float*)d_in[8];
    const float* fc1  = (const float*)d_in[9];
    const float* fc2  = (const float*)d_in[10];
    const float* s1   = (const float*)d_in[11];
    const float* s2   = (const float*)d_in[12];
    const float* s3   = (const float*)d_in[13];
    float* out = (float*)d_out;

    void *p;
    cudaGetSymbolAddress(&p, g_qkv);    float* qkv    = (float*)p;
    cudaGetSymbolAddress(&p, g_h);      float* hbuf   = (float*)p;
    cudaGetSymbolAddress(&p, g_xf);     float* xf     = (float*)p;
    cudaGetSymbolAddress(&p, g_tacat);  float* tacat  = (float*)p;
    cudaGetSymbolAddress(&p, g_wh);     __half* wh   = (__half*)p;
    cudaGetSymbolAddress(&p, g_hn16);   __half* hn16 = (__half*)p;
    cudaGetSymbolAddress(&p, g_q16);    __half* q16  = (__half*)p;
    cudaGetSymbolAddress(&p, g_k16);    __half* k16  = (__half*)p;
    cudaGetSymbolAddress(&p, g_v16);    __half* v16  = (__half*)p;
    cudaGetSymbolAddress(&p, g_a16);    __half* a16  = (__half*)p;
    cudaGetSymbolAddress(&p, g_x16);    __half* x16  = (__half*)p;
    cudaGetSymbolAddress(&p, g_ta16);   __half* ta16 = (__half*)p;
    cudaGetSymbolAddress(&p, g_e16);    __half* e16  = (__half*)p;
    cudaGetSymbolAddress(&p, g_topi);   int*   topi   = (int*)p;
    cudaGetSymbolAddress(&p, g_topw);   float* topw   = (float*)p;
    cudaGetSymbolAddress(&p, g_counts); int*   counts = (int*)p;
    cudaGetSymbolAddress(&p, g_cursor); int*   cursor = (int*)p;
    cudaGetSymbolAddress(&p, g_offs);   int*   offs   = (int*)p;
    cudaGetSymbolAddress(&p, g_order);  int*   order  = (int*)p;
    cudaGetSymbolAddress(&p, g_wslot);  float* wslot  = (float*)p;

    cudaFuncSetAttribute(mm16, cudaFuncAttributeMaxDynamicSharedMemorySize, MM16_SMEM);
    cudaFuncSetAttribute(flash_attn, cudaFuncAttributeMaxDynamicSharedMemorySize, FLASH_SMEM);

    __half* W_QKV = wh;
    __half* W_O   = wh +  3*WSEG;
    __half* W_S12 = wh +  4*WSEG;
    __half* W_S3  = wh +  8*WSEG;
    __half* W_FC1 = wh + 10*WSEG;
    __half* W_FC2 = wh + 18*WSEG;

    // 0. all weights -> fp16, one launch
    convAll<<<(int)(26*WSEG/2048), 256>>>(wq, wk, wv, wo, s1, s2, s3, fc1, fc2, wh);
    // 1. rmsnorm1 -> fp16
    rmsnorm16<<<NTOK, 256>>>(x, n1, nullptr, hn16);
    // 2. merged QKV (N=3072 -> 12 x-blocks)
    mm16<<<dim3(12,32,1),256,MM16_SMEM>>>(hn16, W_QKV, qkv, nullptr, nullptr,
        NTOK, 3*DIMM, DIMM, DIMM, DIMM, 3*DIMM, 0, nullptr, nullptr, nullptr, nullptr, nullptr, 0);
    // 3. RoPE + V extract
    ropeConv<<<(NTOK*NHEADS*32)/256, 256>>>(qkv, q16, k16, v16);
    // 4. flash attention
    flash_attn<<<dim3(8,64),256,FLASH_SMEM>>>(q16, k16, v16, mask, a16);
    // 5. h = x + attn @ wo^T (N=1024 -> 4)
    mm16<<<dim3(4,32,1),256,MM16_SMEM>>>(a16, W_O, hbuf, x, nullptr,
        NTOK, DIMM, DIMM, DIMM, DIMM, DIMM, 1, nullptr, nullptr, nullptr, nullptr, nullptr, 0);
    // 6. rmsnorm2
    rmsnorm16<<<NTOK, 256>>>(hbuf, n2, xf, x16);
    // 7. merged shared fc1|fc2 (N=4096 -> 16)
    mm16<<<dim3(16,32,1),256,MM16_SMEM>>>(x16, W_S12, tacat, nullptr, nullptr,
        NTOK, 2*NSHARED, DIMM, DIMM, DIMM, 2*NSHARED, 0, nullptr, nullptr, nullptr, nullptr, nullptr, 0);
    silumul16<<<(NTOK*NSHARED)/1024, 256>>>(tacat, ta16);
    // 8. out = h + silu_out @ s3^T (N=1024 -> 4, K=2048)
    mm16<<<dim3(4,32,1),256,MM16_SMEM>>>(ta16, W_S3, out, hbuf, nullptr,
        NTOK, DIMM, NSHARED, NSHARED, NSHARED, DIMM, 1, nullptr, nullptr, nullptr, nullptr, nullptr, 0);
    // 9. routing
    zero_counts<<<1,32>>>(counts);
    gate_topk<<<NTOK,256>>>(xf, gw, topi, topw, counts);
    scan_kernel<<<1,1>>>(counts, offs, cursor);
    scatter_kernel<<<NTOK/256,256>>>(topi, cursor, offs, topw, order, wslot);
    // 10. expert fc1 (N=512 -> 2)
    mm16<<<dim3(2,64,NE),256,MM16_SMEM>>>(x16, W_FC1, nullptr, nullptr, e16,
        0, HID, DIMM, DIMM, DIMM, HID, 3, counts, offs, order, nullptr, nullptr, (long long)HID*DIMM);
    // 11. expert fc2: atomic combine into out (N=1024 -> 4)
    mm16<<<dim3(4,64,NE),256,MM16_SMEM>>>(e16, W_FC2, out, nullptr, nullptr,
        0, DIMM, HID, HID, HID, DIMM, 4, counts, offs, nullptr, order, wslot, (long long)DIMM*HID);
}

// round 9
// speedup vs baseline: 5.6358x; 1.0122x over previous
#include <cuda_runtime.h>
#include <cuda_fp16.h>
#include <math.h>
#include <stdint.h>

#define BB 4
#define LL 1024
#define DIMM 1024
#define NHEADS 16
#define HD 64
#define NTOK (BB*LL)
#define HID 512
#define NE 16
#define NSHARED 2048
#define NSLOTS (NTOK*2)

// ---------------- scratch ----------------
__device__ float g_qkv[NTOK*3*DIMM];
__device__ float g_h[NTOK*DIMM];
__device__ float g_xf[NTOK*DIMM];
// fp16 buffers
#define WSEG 1048576ll
__device__ __half g_wh[26*WSEG];
__device__ __half g_hn16[NTOK*DIMM];
__device__ __half g_q16[NTOK*DIMM];
__device__ __half g_k16[NTOK*DIMM];
__device__ __half g_v16[NTOK*DIMM];
__device__ __half g_a16[NTOK*DIMM];
__device__ __half g_x16[NTOK*DIMM];
__device__ __half g_ta16[NTOK*NSHARED];
__device__ __half g_e16[NSLOTS*HID];
// routing
__device__ int   g_topi[NSLOTS];
__device__ float g_topw[NSLOTS];
__device__ int   g_counts[NE];
__device__ int   g_cursor[NE];
__device__ int   g_offs[NE];
__device__ int   g_order[NSLOTS];
__device__ float g_wslot[NSLOTS];

__device__ __forceinline__ uint32_t smem_u32(const void* p){
    uint32_t a;
    asm("{ .reg .u64 t; cvta.to.shared.u64 t, %1; cvt.u32.u64 %0, t; }" : "=r"(a) : "l"(p));
    return a;
}

#define LDMX4(r0,r1,r2,r3,addr) \
    asm volatile("ldmatrix.sync.aligned.m8n8.x4.shared.b16 {%0,%1,%2,%3}, [%4];" \
        : "=r"(r0),"=r"(r1),"=r"(r2),"=r"(r3) : "r"(addr))
#define LDMX4T(r0,r1,r2,r3,addr) \
    asm volatile("ldmatrix.sync.aligned.m8n8.x4.trans.shared.b16 {%0,%1,%2,%3}, [%4];" \
        : "=r"(r0),"=r"(r1),"=r"(r2),"=r"(r3) : "r"(addr))

#define MMAH(c0,c1,c2,c3,a0,a1,a2,a3,b0,b1) \
    asm volatile("mma.sync.aligned.m16n8k16.row.col.f32.f16.f16.f32 " \
        "{%0,%1,%2,%3}, {%4,%5,%6,%7}, {%8,%9}, {%0,%1,%2,%3};" \
        : "+f"(c0),"+f"(c1),"+f"(c2),"+f"(c3) \
        : "r"(a0),"r"(a1),"r"(a2),"r"(a3), "r"(b0),"r"(b1))

#define CPASYNC(dst,src,sz) \
    asm volatile("cp.async.cg.shared.global [%0], [%1], 16, %2;" :: "r"(dst), "l"(src), "r"(sz))
#define CPCOMMIT() asm volatile("cp.async.commit_group;")
#define CPWAIT(n)  asm volatile("cp.async.wait_group %0;" :: "n"(n))

// ========== fp16 GEMM: C = A * B^T ; 128x256 tile, 64x64 warp tile ==========
// mode: 0 fp32 out, 1 fp32 += res, 3 silu->fp16, 4 atomic MoE combine,
//       5 paired silu: cols 0-127 = a1, 128-255 = a2; out fp16 silu(a1)*a2
#define ROWB 80
#define STAGE_BYTES (384*ROWB)
#define NSTAGE 3
#define MM16_SMEM (NSTAGE*STAGE_BYTES)

__global__ void __launch_bounds__(256,1) mm16(
    const __half* __restrict__ Ah, const __half* __restrict__ Bh,
    float* __restrict__ C, const float* __restrict__ res,
    __half* __restrict__ Cp16,
    int M, int N, int K, int lda, int ldb, int ldc, int mode,
    const int* __restrict__ counts, const int* __restrict__ offs,
    const int* __restrict__ rows,
    const int* __restrict__ omap, const float* __restrict__ wsl,
    long long bStrideE)
{
    extern __shared__ __align__(16) char dsm[];
    __shared__ int rsrc[128];
    uint32_t ub = smem_u32(dsm);
    int tid = threadIdx.x, wid = tid >> 5, lane = tid & 31;
    int e = blockIdx.z;

    int Mloc = M, rowOff = 0;
    const __half* Bp = Bh;
    if (counts){ Mloc = counts[e]; rowOff = offs[e]; Bp = Bh + (long long)e*bStrideE; }
    int m0 = blockIdx.y * 128;
    if (m0 >= Mloc) return;
    int n0 = blockIdx.x * 256;

    for (int i = tid; i < 128; i += 256){
        int gr = m0 + i;
        rsrc[i] = (gr < Mloc) ? (rows ? rows[rowOff + gr] : (counts ? rowOff + gr : gr)) : -1;
    }
    __syncthreads();

    const __half* srcp[6];
    uint32_t dsto[6];
    int szs[6];
    #pragma unroll
    for (int i = 0; i < 6; i++){
        int c = tid + i*256;
        int row = c >> 2, part = c & 3;
        dsto[i] = (uint32_t)(row*ROWB + part*16);
        if (row < 128){
            int s = rsrc[row];
            szs[i] = (s >= 0) ? 16 : 0;
            srcp[i] = Ah + (long long)((s >= 0) ? s : 0)*lda + part*8;
        } else {
            szs[i] = 16;
            srcp[i] = Bp + (long long)(n0 + row - 128)*ldb + part*8;
        }
    }

#define MM16_ISSUE(stg, kc) do { \
    uint32_t dd = ub + (stg)*STAGE_BYTES; int ko = (kc)*32; \
    _Pragma("unroll") \
    for (int i = 0; i < 6; i++) CPASYNC(dd + dsto[i], srcp[i] + ko, szs[i]); \
    CPCOMMIT(); } while(0)

    float acc[4][8][4];
    #pragma unroll
    for (int i=0;i<4;i++) for (int j=0;j<8;j++) for (int f=0;f<4;f++) acc[i][j][f]=0.f;

    int wm = (wid >> 2) * 64, wn = (wid & 3) * 64;
    int lrow = lane & 15, lsel = (lane >> 4) * 8;
    int nk = K >> 5;

    MM16_ISSUE(0, 0);
    if (nk > 1) MM16_ISSUE(1, 1);
    for (int kc = 0; kc < nk; kc++){
        if (kc + 1 < nk) CPWAIT(1); else CPWAIT(0);
        __syncthreads();
        int nxt = kc + 2;
        if (nxt < nk) MM16_ISSUE(nxt % NSTAGE, nxt);
        uint32_t us = ub + (kc % NSTAGE)*STAGE_BYTES;
        #pragma unroll
        for (int ks = 0; ks < 2; ks++){
            int kofs2 = (ks*16 + lsel)*2;
            uint32_t ah[4][4], bh[4][4];
            #pragma unroll
            for (int mt = 0; mt < 4; mt++){
                uint32_t ad = us + (uint32_t)((wm + mt*16 + lrow)*ROWB) + kofs2;
                LDMX4(ah[mt][0],ah[mt][1],ah[mt][2],ah[mt][3], ad);
            }
            #pragma unroll
            for (int j = 0; j < 4; j++){
                uint32_t bd = us + (uint32_t)((128 + wn + j*16 + lrow)*ROWB) + kofs2;
                LDMX4(bh[j][0],bh[j][1],bh[j][2],bh[j][3], bd);
            }
            #pragma unroll
            for (int mt = 0; mt < 4; mt++){
                #pragma unroll
                for (int j = 0; j < 4; j++){
                    float* c0 = acc[mt][2*j];
                    float* c1 = acc[mt][2*j+1];
                    MMAH(c0[0],c0[1],c0[2],c0[3], ah[mt][0],ah[mt][1],ah[mt][2],ah[mt][3], bh[j][0],bh[j][2]);
                    MMAH(c1[0],c1[1],c1[2],c1[3], ah[mt][0],ah[mt][1],ah[mt][2],ah[mt][3], bh[j][1],bh[j][3]);
                }
            }
        }
    }

    int rbase = lane >> 2, cbase = (lane & 3) * 2;

    if (mode == 5){
        // paired silu epilogue: a1 = cols 0..127, a2 = cols 128..255 (same out cols)
        float* stage = (float*)dsm;    // 128 x 132 fp32
        __syncthreads();               // pipeline smem dead, reuse
        if ((wid & 3) >= 2){
            int cb = wn - 128;
            #pragma unroll
            for (int mt = 0; mt < 4; mt++)
                #pragma unroll
                for (int nt = 0; nt < 8; nt++)
                    #pragma unroll
                    for (int half = 0; half < 2; half++){
                        int lm = wm + mt*16 + rbase + half*8;
                        int c = cb + nt*8 + cbase;
                        stage[lm*132 + c]   = acc[mt][nt][2*half];
                        stage[lm*132 + c+1] = acc[mt][nt][2*half+1];
                    }
        }
        __syncthreads();
        if ((wid & 3) < 2){
            int n0h = blockIdx.x * 128;
            #pragma unroll
            for (int mt = 0; mt < 4; mt++)
                #pragma unroll
                for (int nt = 0; nt < 8; nt++)
                    #pragma unroll
                    for (int half = 0; half < 2; half++){
                        int lm = wm + mt*16 + rbase + half*8;
                        int c = wn + nt*8 + cbase;
                        float a1x = acc[mt][nt][2*half];
                        float a1y = acc[mt][nt][2*half+1];
                        float a2x = stage[lm*132 + c];
                        float a2y = stage[lm*132 + c+1];
                        float ox = a1x/(1.f+expf(-a1x))*a2x;
                        float oy = a1y/(1.f+expf(-a1y))*a2y;
                        long long ci = (long long)(m0 + lm)*ldc + n0h + c;
                        *(__half2*)(Cp16 + ci) = __floats2half2_rn(ox, oy);
                    }
        }
        return;
    }

    #pragma unroll
    for (int mt = 0; mt < 4; mt++){
        #pragma unroll
        for (int nt = 0; nt < 8; nt++){
            int gn = n0 + wn + nt*8 + cbase;
            #pragma unroll
            for (int half = 0; half < 2; half++){
                int gm = m0 + wm + mt*16 + rbase + half*8;
                if (gm >= Mloc) continue;
                float v0 = acc[mt][nt][2*half];
                float v1 = acc[mt][nt][2*half+1];
                long long ci = (long long)(rowOff + gm)*ldc + gn;
                if (mode == 1){
                    v0 += res[ci]; v1 += res[ci+1];
                    *(float2*)(C + ci) = make_float2(v0, v1);
                } else if (mode == 3){
                    v0 = v0 / (1.f + expf(-v0));
                    v1 = v1 / (1.f + expf(-v1));
                    *(__half2*)(Cp16 + ci) = __floats2half2_rn(v0, v1);
                } else if (mode == 4){
                    int slot = rowOff + gm;
                    int t = omap[slot];
                    float w = wsl[slot];
                    long long co = (long long)t*ldc + gn;
                    atomicAdd(&C[co],   w*v0);
                    atomicAdd(&C[co+1], w*v1);
                } else {
                    *(float2*)(C + ci) = make_float2(v0, v1);
                }
            }
        }
    }
}

// ===================== fused flash attention, 3-stage cp.async K/V =====================
#define FSTR 72
#define KVHALF (128*FSTR*2)
#define KVSTG  (2*KVHALF)
#define FLASH_SMEM (KVHALF + 3*KVSTG)

__global__ void __launch_bounds__(256,1) flash_attn(
    const __half* __restrict__ qh, const __half* __restrict__ kh,
    const __half* __restrict__ vh, const float* __restrict__ mask,
    __half* __restrict__ oh)
{
    extern __shared__ __align__(16) char fsm[];
    __half* sQ = (__half*)fsm;
    uint32_t uQ = smem_u32(fsm);
    uint32_t ukv0 = uQ + KVHALF;

    int tid = threadIdx.x, wid = tid >> 5, lane = tid & 31;
    int bh_ = blockIdx.y, b = bh_ >> 4, h = bh_ & 15;
    int q0 = blockIdx.x * 128;
    long long tb = (long long)b * LL;
    int crow = tid >> 1, chalf = (tid & 1) * 32;

#define FLASH_ISSUE(jt) do { \
    int st_ = (jt) % 3; \
    long long g_ = (tb + (jt)*128 + crow)*DIMM + h*HD + chalf; \
    uint32_t dk_ = ukv0 + st_*KVSTG + (uint32_t)(crow*144 + chalf*2); \
    const __half* ks_ = kh + g_; const __half* vs_ = vh + g_; \
    CPASYNC(dk_,    ks_,    16); CPASYNC(dk_+16, ks_+8,  16); \
    CPASYNC(dk_+32, ks_+16, 16); CPASYNC(dk_+48, ks_+24, 16); \
    uint32_t dv_ = dk_ + KVHALF; \
    CPASYNC(dv_,    vs_,    16); CPASYNC(dv_+16, vs_+8,  16); \
    CPASYNC(dv_+32, vs_+16, 16); CPASYNC(dv_+48, vs_+24, 16); \
    CPCOMMIT(); } while(0)

    {
        long long g = (tb + q0 + crow)*DIMM + h*HD + chalf;
        uint4* d0 = (uint4*)&sQ[crow*FSTR + chalf];
        const uint4* s0 = (const uint4*)(qh + g);
        #pragma unroll
        for (int i = 0; i < 4; i++) d0[i] = s0[i];
    }
    FLASH_ISSUE(0);
    FLASH_ISSUE(1);
    __syncthreads();

    int lr = lane & 15, ls = (lane >> 4) * 8;
    uint32_t aq[4][4];
    #pragma unroll
    for (int kc = 0; kc < 4; kc++){
        uint32_t ad = uQ + 2u*((wid*16 + lr)*FSTR + kc*16 + ls);
        LDMX4(aq[kc][0],aq[kc][1],aq[kc][2],aq[kc][3], ad);
    }

    float oacc[8][4];
    #pragma unroll
    for (int i=0;i<8;i++) for (int j=0;j<4;j++) oacc[i][j]=0.f;
    float m0r = -1e30f, m1r = -1e30f, l0r = 0.f, l1r = 0.f;

    const float* mp0 = mask + (long long)(q0 + wid*16 + (lane>>2))*LL;
    const float* mp1 = mp0 + 8*LL;
    const float SC  = 0.125f * 1.44269504f;
    const float L2E = 1.44269504f;

    for (int jt = 0; jt < 8; jt++){
        if (jt < 7) CPWAIT(1); else CPWAIT(0);
        __syncthreads();
        if (jt + 2 < 8) FLASH_ISSUE(jt + 2);
        uint32_t uK = ukv0 + (jt % 3)*KVSTG, uV = uK + KVHALF;

        float s[16][4];
        #pragma unroll
        for (int i=0;i<16;i++) for (int j=0;j<4;j++) s[i][j]=0.f;

        #pragma unroll
        for (int kc = 0; kc < 4; kc++){
            #pragma unroll
            for (int np = 0; np < 8; np++){
                uint32_t bk[4];
                uint32_t ad = uK + 2u*((np*16 + lr)*FSTR + kc*16 + ls);
                LDMX4(bk[0],bk[1],bk[2],bk[3], ad);
                float* c0 = s[2*np]; float* c1 = s[2*np+1];
                MMAH(c0[0],c0[1],c0[2],c0[3], aq[kc][0],aq[kc][1],aq[kc][2],aq[kc][3], bk[0],bk[2]);
                MMAH(c1[0],c1[1],c1[2],c1[3], aq[kc][0],aq[kc][1],aq[kc][2],aq[kc][3], bk[1],bk[3]);
            }
        }

        float mx0 = -1e30f, mx1 = -1e30f;
        #pragma unroll
        for (int nt = 0; nt < 16; nt++){
            int colb = jt*128 + nt*8 + (lane&3)*2;
            float2 mm0 = *(const float2*)(mp0 + colb);
            float2 mm1 = *(const float2*)(mp1 + colb);
            s[nt][0] = fmaf(s[nt][0], SC, mm0.x*L2E);
            s[nt][1] = fmaf(s[nt][1], SC, mm0.y*L2E);
            s[nt][2] = fmaf(s[nt][2], SC, mm1.x*L2E);
            s[nt][3] = fmaf(s[nt][3], SC, mm1.y*L2E);
            mx0 = fmaxf(mx0, fmaxf(s[nt][0], s[nt][1]));
            mx1 = fmaxf(mx1, fmaxf(s[nt][2], s[nt][3]));
        }
        mx0 = fmaxf(mx0, __shfl_xor_sync(0xffffffffu, mx0, 1));
        mx0 = fmaxf(mx0, __shfl_xor_sync(0xffffffffu, mx0, 2));
        mx1 = fmaxf(mx1, __shfl_xor_sync(0xffffffffu, mx1, 1));
        mx1 = fmaxf(mx1, __shfl_xor_sync(0xffffffffu, mx1, 2));

        float nm0 = fmaxf(m0r, mx0), nm1 = fmaxf(m1r, mx1);
        float al0 = exp2f(m0r - nm0), al1 = exp2f(m1r - nm1);
        m0r = nm0; m1r = nm1;

        float rs0 = 0.f, rs1 = 0.f;
        #pragma unroll
        for (int nt = 0; nt < 16; nt++){
            s[nt][0] = exp2f(s[nt][0] - nm0);
            s[nt][1] = exp2f(s[nt][1] - nm0);
            s[nt][2] = exp2f(s[nt][2] - nm1);
            s[nt][3] = exp2f(s[nt][3] - nm1);
            rs0 += s[nt][0] + s[nt][1];
            rs1 += s[nt][2] + s[nt][3];
        }
        rs0 += __shfl_xor_sync(0xffffffffu, rs0, 1);
        rs0 += __shfl_xor_sync(0xffffffffu, rs0, 2);
        rs1 += __shfl_xor_sync(0xffffffffu, rs1, 1);
        rs1 += __shfl_xor_sync(0xffffffffu, rs1, 2);
        l0r = l0r*al0 + rs0;
        l1r = l1r*al1 + rs1;
        #pragma unroll
        for (int dt = 0; dt < 8; dt++){
            oacc[dt][0] *= al0; oacc[dt][1] *= al0;
            oacc[dt][2] *= al1; oacc[dt][3] *= al1;
        }

        #pragma unroll
        for (int kc2 = 0; kc2 < 8; kc2++){
            uint32_t pa[4];
            {
                __half2 h0 = __floats2half2_rn(s[2*kc2][0],   s[2*kc2][1]);
                __half2 h1 = __floats2half2_rn(s[2*kc2][2],   s[2*kc2][3]);
                __half2 h2 = __floats2half2_rn(s[2*kc2+1][0], s[2*kc2+1][1]);
                __half2 h3 = __floats2half2_rn(s[2*kc2+1][2], s[2*kc2+1][3]);
                pa[0]=*(uint32_t*)&h0; pa[1]=*(uint32_t*)&h1; pa[2]=*(uint32_t*)&h2; pa[3]=*(uint32_t*)&h3;
            }
            #pragma unroll
            for (int dt = 0; dt < 4; dt++){
                uint32_t bv[4];
                uint32_t ad = uV + 2u*((kc2*16 + lr)*FSTR + dt*16 + ls);
                LDMX4T(bv[0],bv[1],bv[2],bv[3], ad);
                float* o0 = oacc[2*dt]; float* o1 = oacc[2*dt+1];
                MMAH(o0[0],o0[1],o0[2],o0[3], pa[0],pa[1],pa[2],pa[3], bv[0],bv[1]);
                MMAH(o1[0],o1[1],o1[2],o1[3], pa[0],pa[1],pa[2],pa[3], bv[2],bv[3]);
            }
        }
    }

    float i0 = 1.f / l0r, i1 = 1.f / l1r;
    long long r0 = tb + q0 + wid*16 + (lane>>2);
    #pragma unroll
    for (int dt = 0; dt < 8; dt++){
        long long g0 = r0*DIMM + h*HD + dt*8 + (lane&3)*2;
        long long g1 = g0 + 8*DIMM;
        *(__half2*)(oh + g0) = __floats2half2_rn(oacc[dt][0]*i0, oacc[dt][1]*i0);
        *(__half2*)(oh + g1) = __floats2half2_rn(oacc[dt][2]*i1, oacc[dt][3]*i1);
    }
}

// ---------------- misc kernels ----------------
__device__ __forceinline__ float warpReduceSum(float v){
    #pragma unroll
    for (int o=16;o;o>>=1) v += __shfl_xor_sync(0xffffffffu, v, o);
    return v;
}
__device__ float blockReduceSum(float v){
    __shared__ float sh[33];
    int lane = threadIdx.x & 31, wid = threadIdx.x >> 5;
    __syncthreads();
    v = warpReduceSum(v);
    if (lane==0) sh[wid] = v;
    __syncthreads();
    int nw = blockDim.x >> 5;
    float r = (threadIdx.x < nw) ? sh[threadIdx.x] : 0.f;
    if (wid==0){ r = warpReduceSum(r); if (lane==0) sh[32] = r; }
    __syncthreads();
    return sh[32];
}

// all weights -> fp16 in one pass; s1/s2 interleaved in 128-row blocks
__global__ void convAll(const float* __restrict__ wq, const float* __restrict__ wk,
                        const float* __restrict__ wv, const float* __restrict__ wo,
                        const float* __restrict__ s1, const float* __restrict__ s2,
                        const float* __restrict__ s3, const float* __restrict__ fc1,
                        const float* __restrict__ fc2, __half* __restrict__ o){
    long long i = ((long long)blockIdx.x*256 + threadIdx.x)*8;
    if (i >= 26*WSEG) return;
    const float* src; long long off; long long dst = i;
    if      (i <  1*WSEG){ src = wq;  off = i; }
    else if (i <  2*WSEG){ src = wk;  off = i -  1*WSEG; }
    else if (i <  3*WSEG){ src = wv;  off = i -  2*WSEG; }
    else if (i <  4*WSEG){ src = wo;  off = i -  3*WSEG; }
    else if (i <  8*WSEG){
        long long o12 = i - 4*WSEG;
        int is2 = (o12 >= 2*WSEG);
        long long o2 = is2 ? o12 - 2*WSEG : o12;
        src = is2 ? s2 : s1; off = o2;
        int r = (int)(o2 >> 10), c = (int)(o2 & 1023);
        int j = r >> 7, rl = r & 127;
        dst = 4*WSEG + (((long long)(j*256 + is2*128 + rl)) << 10) + c;
    }
    else if (i < 10*WSEG){ src = s3;  off = i -  8*WSEG; }
    else if (i < 18*WSEG){ src = fc1; off = i - 10*WSEG; }
    else                 { src = fc2; off = i - 18*WSEG; }
    float4 a = *(const float4*)(src + off);
    float4 b = *(const float4*)(src + off + 4);
    __half2 h0 = __floats2half2_rn(a.x, a.y);
    __half2 h1 = __floats2half2_rn(a.z, a.w);
    __half2 h2 = __floats2half2_rn(b.x, b.y);
    __half2 h3 = __floats2half2_rn(b.z, b.w);
    uint4 pk;
    pk.x = *(uint32_t*)&h0; pk.y = *(uint32_t*)&h1;
    pk.z = *(uint32_t*)&h2; pk.w = *(uint32_t*)&h3;
    *(uint4*)(o + dst) = pk;
}

__global__ void __launch_bounds__(256) rmsnorm16(const float* __restrict__ x,
        const float* __restrict__ w, float* __restrict__ outf,
        __half* __restrict__ o16){
    long long row = blockIdx.x;
    float4 xv = ((const float4*)(x + row*DIMM))[threadIdx.x];
    float ss = xv.x*xv.x + xv.y*xv.y + xv.z*xv.z + xv.w*xv.w;
    float tot = blockReduceSum(ss);
    float scale = rsqrtf(tot * (1.0f/DIMM) + 1e-5f);
    float4 wv = ((const float4*)w)[threadIdx.x];
    float4 o;
    o.x = xv.x*scale*wv.x; o.y = xv.y*scale*wv.y;
    o.z = xv.z*scale*wv.z; o.w = xv.w*scale*wv.w;
    long long i = row*DIMM + threadIdx.x*4;
    if (outf) *(float4*)(outf + i) = o;
    __half2 h01 = __floats2half2_rn(o.x, o.y);
    __half2 h23 = __floats2half2_rn(o.z, o.w);
    *(uint2*)(o16 + i) = make_uint2(*(uint32_t*)&h01, *(uint32_t*)&h23);
}

__global__ void ropeConv(const float* __restrict__ qkv,
                         __half* __restrict__ q16, __half* __restrict__ k16,
                         __half* __restrict__ v16){
    int idx = blockIdx.x*blockDim.x + threadIdx.x;
    if (idx >= NTOK*NHEADS*(HD/2)) return;
    int j = idx & 31;
    int h = (idx >> 5) & 15;
    int t = idx >> 9;
    int l = t & (LL-1);
    long long bsrc = (long long)t*3072 + h*HD;
    long long bdst = (long long)t*DIMM + h*HD;
    float inv = powf(10000.f, -(float)j * (1.f/32.f));
    float ang = (float)l * inv;
    float sn, cs; sincosf(ang, &sn, &cs);
    float a = qkv[bsrc+j], b = qkv[bsrc+32+j];
    q16[bdst+j]    = __float2half_rn(a*cs - b*sn);
    q16[bdst+32+j] = __float2half_rn(a*sn + b*cs);
    a = qkv[bsrc+1024+j]; b = qkv[bsrc+1024+32+j];
    k16[bdst+j]    = __float2half_rn(a*cs - b*sn);
    k16[bdst+32+j] = __float2half_rn(a*sn + b*cs);
    v16[bdst+j]    = __float2half_rn(qkv[bsrc+2048+j]);
    v16[bdst+32+j] = __float2half_rn(qkv[bsrc+2048+32+j]);
}

__global__ void __launch_bounds__(256) gate_topk(const float* __restrict__ xf,
                                                 const float* __restrict__ gw,
                                                 int* __restrict__ topi, float* __restrict__ topw,
                                                 int* __restrict__ counts){
    int t = blockIdx.x;
    int tid = threadIdx.x;
    float4 xv = ((const float4*)(xf + (long long)t*DIMM))[tid];
    float acc[16];
    #pragma unroll
    for (int e = 0; e < 16; e++){
        float4 g = ((const float4*)(gw + (long long)e*DIMM))[tid];
        acc[e] = xv.x*g.x + xv.y*g.y + xv.z*g.z + xv.w*g.w;
    }
    #pragma unroll
    for (int e = 0; e < 16; e++) acc[e] = warpReduceSum(acc[e]);
    __shared__ float wr[8][16];
    __shared__ float lg[16];
    int lane = tid & 31, wid = tid >> 5;
    if (lane == 0){
        #pragma unroll
        for (int e = 0; e < 16; e++) wr[wid][e] = acc[e];
    }
    __syncthreads();
    if (tid < 16){
        float s = 0.f;
        #pragma unroll
        for (int w = 0; w < 8; w++) s += wr[w][tid];
        lg[tid] = s;
    }
    __syncthreads();
    if (tid == 0){
        float l0 = -3.0e38f; int i0 = 0;
        for (int e = 0; e < 16; e++) if (lg[e] > l0){ l0 = lg[e]; i0 = e; }
        float l1 = -3.0e38f; int i1 = 0;
        for (int e = 0; e < 16; e++) if (e != i0 && lg[e] > l1){ l1 = lg[e]; i1 = e; }
        float w1 = expf(l1 - l0);
        float sden = 1.f + w1;
        topi[2*t] = i0; topi[2*t+1] = i1;
        topw[2*t] = 1.f / sden; topw[2*t+1] = w1 / sden;
        atomicAdd(&counts[i0], 1);
        atomicAdd(&counts[i1], 1);
    }
}

__global__ void zero_counts(int* counts){
    if (threadIdx.x < NE) counts[threadIdx.x] = 0;
}
__global__ void scan_kernel(const int* __restrict__ counts, int* __restrict__ offs,
                            int* __restrict__ cursor){
    if (threadIdx.x == 0){
        int s = 0;
        for (int e = 0; e < NE; e++){ offs[e] = s; s += counts[e]; cursor[e] = 0; }
    }
}
__global__ void scatter_kernel(const int* __restrict__ topi, int* __restrict__ cursor,
                               const int* __restrict__ offs, const float* __restrict__ topw,
                               int* __restrict__ order, float* __restrict__ wslot){
    int t = blockIdx.x*blockDim.x + threadIdx.x;
    if (t >= NTOK) return;
    #pragma unroll
    for (int k2 = 0; k2 < 2; k2++){
        int e = topi[2*t+k2];
        int pos = atomicAdd(&cursor[e], 1);
        int slot = offs[e] + pos;
        order[slot] = t;
        wslot[slot] = topw[2*t+k2];
    }
}

// ---------------- host launcher ----------------
extern "C" void kernel_launch(void* const* d_in, const int* in_sizes, int n_in,
                              void* d_out, int out_size){
    const float* x    = (const float*)d_in[0];
    const float* mask = (const float*)d_in[1];
    const float* wq   = (const float*)d_in[2];
    const float* wk   = (const float*)d_in[3];
    const float* wv   = (const float*)d_in[4];
    const float* wo   = (const float*)d_in[5];
    const float* n1   = (const float*)d_in[6];
    const float* n2   = (const float*)d_in[7];
    const float* gw   = (const float*)d_in[8];
    const float* fc1  = (const float*)d_in[9];
    const float* fc2  = (const float*)d_in[10];
    const float* s1   = (const float*)d_in[11];
    const float* s2   = (const float*)d_in[12];
    const float* s3   = (const float*)d_in[13];
    float* out = (float*)d_out;

    void *p;
    cudaGetSymbolAddress(&p, g_qkv);    float* qkv    = (float*)p;
    cudaGetSymbolAddress(&p, g_h);      float* hbuf   = (float*)p;
    cudaGetSymbolAddress(&p, g_xf);     float* xf     = (float*)p;
    cudaGetSymbolAddress(&p, g_wh);     __half* wh   = (__half*)p;
    cudaGetSymbolAddress(&p, g_hn16);   __half* hn16 = (__half*)p;
    cudaGetSymbolAddress(&p, g_q16);    __half* q16  = (__half*)p;
    cudaGetSymbolAddress(&p, g_k16);    __half* k16  = (__half*)p;
    cudaGetSymbolAddress(&p, g_v16);    __half* v16  = (__half*)p;
    cudaGetSymbolAddress(&p, g_a16);    __half* a16  = (__half*)p;
    cudaGetSymbolAddress(&p, g_x16);    __half* x16  = (__half*)p;
    cudaGetSymbolAddress(&p, g_ta16);   __half* ta16 = (__half*)p;
    cudaGetSymbolAddress(&p, g_e16);    __half* e16  = (__half*)p;
    cudaGetSymbolAddress(&p, g_topi);   int*   topi   = (int*)p;
    cudaGetSymbolAddress(&p, g_topw);   float* topw   = (float*)p;
    cudaGetSymbolAddress(&p, g_counts); int*   counts = (int*)p;
    cudaGetSymbolAddress(&p, g_cursor); int*   cursor = (int*)p;
    cudaGetSymbolAddress(&p, g_offs);   int*   offs   = (int*)p;
    cudaGetSymbolAddress(&p, g_order);  int*   order  = (int*)p;
    cudaGetSymbolAddress(&p, g_wslot);  float* wslot  = (float*)p;

    cudaFuncSetAttribute(mm16, cudaFuncAttributeMaxDynamicSharedMemorySize, MM16_SMEM);
    cudaFuncSetAttribute(flash_attn, cudaFuncAttributeMaxDynamicSharedMemorySize, FLASH_SMEM);

    __half* W_QKV = wh;
    __half* W_O   = wh +  3*WSEG;
    __half* W_S12 = wh +  4*WSEG;
    __half* W_S3  = wh +  8*WSEG;
    __half* W_FC1 = wh + 10*WSEG;
    __half* W_FC2 = wh + 18*WSEG;

    // second stream + events for overlap (host objects; capture-legal fork/join)
    cudaStream_t sB;
    cudaStreamCreateWithFlags(&sB, cudaStreamNonBlocking);
    cudaEvent_t eFork, eW, eX, eF1;
    cudaEventCreateWithFlags(&eFork, cudaEventDisableTiming);
    cudaEventCreateWithFlags(&eW,    cudaEventDisableTiming);
    cudaEventCreateWithFlags(&eX,    cudaEventDisableTiming);
    cudaEventCreateWithFlags(&eF1,   cudaEventDisableTiming);

    // fork: convAll on sB, rmsnorm1 on main
    cudaEventRecord(eFork, 0);
    cudaStreamWaitEvent(sB, eFork, 0);
    convAll<<<(int)(26*WSEG/2048), 256, 0, sB>>>(wq, wk, wv, wo, s1, s2, s3, fc1, fc2, wh);
    cudaEventRecord(eW, sB);
    rmsnorm16<<<NTOK, 256>>>(x, n1, nullptr, hn16);
    cudaStreamWaitEvent(0, eW, 0);       // weights ready for all GEMMs on main stream

    // QKV
    mm16<<<dim3(12,32,1),256,MM16_SMEM>>>(hn16, W_QKV, qkv, nullptr, nullptr,
        NTOK, 3*DIMM, DIMM, DIMM, DIMM, 3*DIMM, 0, nullptr, nullptr, nullptr, nullptr, nullptr, 0);
    ropeConv<<<(NTOK*NHEADS*32)/256, 256>>>(qkv, q16, k16, v16);
    flash_attn<<<dim3(8,64),256,FLASH_SMEM>>>(q16, k16, v16, mask, a16);
    mm16<<<dim3(4,32,1),256,MM16_SMEM>>>(a16, W_O, hbuf, x, nullptr,
        NTOK, DIMM, DIMM, DIMM, DIMM, DIMM, 1, nullptr, nullptr, nullptr, nullptr, nullptr, 0);
    rmsnorm16<<<NTOK, 256>>>(hbuf, n2, xf, x16);
    cudaEventRecord(eX, 0);

    // branch B: routing + expert fc1 (needs xf/x16 + weights)
    cudaStreamWaitEvent(sB, eX, 0);
    zero_counts<<<1,32,0,sB>>>(counts);
    gate_topk<<<NTOK,256,0,sB>>>(xf, gw, topi, topw, counts);
    scan_kernel<<<1,1,0,sB>>>(counts, offs, cursor);
    scatter_kernel<<<NTOK/256,256,0,sB>>>(topi, cursor, offs, topw, order, wslot);
    mm16<<<dim3(2,64,NE),256,MM16_SMEM,sB>>>(x16, W_FC1, nullptr, nullptr, e16,
        0, HID, DIMM, DIMM, DIMM, HID, 3, counts, offs, order, nullptr, nullptr, (long long)HID*DIMM);
    cudaEventRecord(eF1, sB);

    // main: shared expert with fused silu, then residual GEMM into out
    mm16<<<dim3(16,32,1),256,MM16_SMEM>>>(x16, W_S12, nullptr, nullptr, ta16,
        NTOK, 2*NSHARED, DIMM, DIMM, DIMM, NSHARED, 5, nullptr, nullptr, nullptr, nullptr, nullptr, 0);
    mm16<<<dim3(4,32,1),256,MM16_SMEM>>>(ta16, W_S3, out, hbuf, nullptr,
        NTOK, DIMM, NSHARED, NSHARED, NSHARED, DIMM, 1, nullptr, nullptr, nullptr, nullptr, nullptr, 0);

    // join: expert fc2 atomically combines into out
    cudaStreamWaitEvent(0, eF1, 0);
    mm16<<<dim3(4,64,NE),256,MM16_SMEM>>>(e16, W_FC2, out, nullptr, nullptr,
        0, DIMM, HID, HID, HID, DIMM, 4, counts, offs, nullptr, order, wslot, (long long)DIMM*HID);
}